// round 1
// baseline (speedup 1.0000x reference)
#include <cuda_runtime.h>
#include <cuda_bf16.h>
#include <cstdio>

#define D128 128
#define WS 132          // smem weight stride (floats): 528B, 16B-aligned, 4-way max conflict
#define FULLMASK 0xffffffffu

// ---------------- scratch (device globals; no allocation allowed) ----------------
#define NG_CAP 50000
#define NI_CAP 100000
__device__ float g_tmp2 [NI_CAP * D128]; // i2 then g2 (reused)
__device__ float g_fi   [NI_CAP * D128]; // final_item
__device__ float g_fg   [NG_CAP * D128]; // fus_group
__device__ float g_gfi  [NG_CAP * D128]; // sigmoid(spmm(gi, final_item))
__device__ float g_first[NG_CAP * D128];
__device__ float g_sec  [NG_CAP * D128];
__device__ float g_fgrp [NG_CAP * D128]; // final_group
__device__ float g_an   [NG_CAP * D128]; // all_neighbors
__device__ int   g_rp_gi[NG_CAP + 1];
__device__ int   g_rp_gg[NG_CAP + 1];

// ---------------- helpers ----------------
__device__ __forceinline__ float wredsum(float v) {
    #pragma unroll
    for (int o = 16; o; o >>= 1) v += __shfl_xor_sync(FULLMASK, v, o);
    return v;
}
__device__ __forceinline__ float sigf(float x) { return 1.0f / (1.0f + __expf(-x)); }
__device__ __forceinline__ void fma4(float4& a, const float4 w, const float x) {
    a.x = fmaf(w.x, x, a.x); a.y = fmaf(w.y, x, a.y);
    a.z = fmaf(w.z, x, a.z); a.w = fmaf(w.w, x, a.w);
}
// per-row instance-norm of the 128 values distributed as float4/lane across one warp
__device__ __forceinline__ float4 inorm4(float4 v) {
    float m = wredsum(v.x + v.y + v.z + v.w) * (1.0f / 128.0f);
    float dx = v.x - m, dy = v.y - m, dz = v.z - m, dw = v.w - m;
    float q = wredsum(dx*dx + dy*dy + dz*dz + dw*dw) * (1.0f / 128.0f);
    float inv = rsqrtf(q + 1e-5f);
    return make_float4(dx*inv, dy*inv, dz*inv, dw*inv);
}

// ---------------- row_ptr from sorted COO rows ----------------
__global__ void k_rowptr(const int* __restrict__ rows, int E, int N, int* __restrict__ rp) {
    for (int e = blockIdx.x * blockDim.x + threadIdx.x; e < E; e += gridDim.x * blockDim.x) {
        int r = rows[e];
        int prev = (e == 0) ? -1 : rows[e - 1];
        for (int rr = prev + 1; rr <= r; rr++) rp[rr] = e;
        if (e == E - 1) for (int rr = r + 1; rr <= N; rr++) rp[rr] = E;
    }
}

// ---------------- out = inorm( inorm(X) @ W^T + b ), W: 128x128 ----------------
__global__ void __launch_bounds__(512, 2)
k_nln(const float* __restrict__ X, const float* __restrict__ W,
      const float* __restrict__ Bv, float* __restrict__ out, int N)
{
    extern __shared__ float sm[];
    float* Wt   = sm;               // [128][WS] : Wt[k*WS+j] = W[j*128+k]
    float* bias = Wt + 128 * WS;
    float* rb   = bias + 128;       // 32 rows * 128
    const int tid = threadIdx.x, lane = tid & 31, w = tid >> 5;
    for (int i = tid; i < 128 * 128; i += 512) {
        int j = i >> 7, k = i & 127;
        Wt[k * WS + j] = W[i];
    }
    if (tid < 128) bias[tid] = Bv[tid];
    __syncthreads();
    const int c = lane * 4;
    const float4 z = make_float4(0.f, 0.f, 0.f, 0.f);
    for (int base = blockIdx.x * 32; base < N; base += gridDim.x * 32) {
        int r0 = base + w * 2, r1 = r0 + 1;
        float* b0 = rb + w * 256; float* b1 = b0 + 128;
        __syncwarp();
        if (r0 < N) { float4 v = *(const float4*)(X + (size_t)r0 * 128 + c); *(float4*)(b0 + c) = inorm4(v); }
        else        { *(float4*)(b0 + c) = z; }
        if (r1 < N) { float4 v = *(const float4*)(X + (size_t)r1 * 128 + c); *(float4*)(b1 + c) = inorm4(v); }
        else        { *(float4*)(b1 + c) = z; }
        __syncwarp();
        float4 a0 = z, a1 = z;
        #pragma unroll 8
        for (int k = 0; k < 128; k += 4) {
            float4 xa = *(const float4*)(b0 + k);
            float4 xb = *(const float4*)(b1 + k);
            const float* wp = Wt + k * WS + c;
            float4 w0 = *(const float4*)(wp);
            float4 w1 = *(const float4*)(wp + WS);
            float4 w2 = *(const float4*)(wp + 2 * WS);
            float4 w3 = *(const float4*)(wp + 3 * WS);
            fma4(a0, w0, xa.x); fma4(a0, w1, xa.y); fma4(a0, w2, xa.z); fma4(a0, w3, xa.w);
            fma4(a1, w0, xb.x); fma4(a1, w1, xb.y); fma4(a1, w2, xb.z); fma4(a1, w3, xb.w);
        }
        float4 bi = *(const float4*)(bias + c);
        a0.x += bi.x; a0.y += bi.y; a0.z += bi.z; a0.w += bi.w;
        a1.x += bi.x; a1.y += bi.y; a1.z += bi.z; a1.w += bi.w;
        if (r0 < N) { float4 o = inorm4(a0); *(float4*)(out + (size_t)r0 * 128 + c) = o; }
        if (r1 < N) { float4 o = inorm4(a1); *(float4*)(out + (size_t)r1 * 128 + c) = o; }
    }
}

// ---------------- out = sigmoid( [EMB, X2] @ W^T + b ), W: 128x256 ----------------
__global__ void __launch_bounds__(512, 1)
k_fus(const float* __restrict__ EMB, const float* __restrict__ X2,
      const float* __restrict__ W, const float* __restrict__ Bv,
      float* __restrict__ out, int N)
{
    extern __shared__ float sm[];
    float* Wt   = sm;               // [256][WS] : Wt[k*WS+j] = W[j*256+k]
    float* bias = Wt + 256 * WS;
    float* rb   = bias + 128;       // 32 rows * 256
    const int tid = threadIdx.x, lane = tid & 31, w = tid >> 5;
    for (int i = tid; i < 128 * 256; i += 512) {
        int j = i >> 8, k = i & 255;
        Wt[k * WS + j] = W[i];
    }
    if (tid < 128) bias[tid] = Bv[tid];
    __syncthreads();
    const int c = lane * 4;
    const float4 z = make_float4(0.f, 0.f, 0.f, 0.f);
    for (int base = blockIdx.x * 32; base < N; base += gridDim.x * 32) {
        int r0 = base + w * 2, r1 = r0 + 1;
        float* b0 = rb + w * 512; float* b1 = b0 + 256;
        __syncwarp();
        if (r0 < N) {
            *(float4*)(b0 + c)       = *(const float4*)(EMB + (size_t)r0 * 128 + c);
            *(float4*)(b0 + 128 + c) = *(const float4*)(X2  + (size_t)r0 * 128 + c);
        } else { *(float4*)(b0 + c) = z; *(float4*)(b0 + 128 + c) = z; }
        if (r1 < N) {
            *(float4*)(b1 + c)       = *(const float4*)(EMB + (size_t)r1 * 128 + c);
            *(float4*)(b1 + 128 + c) = *(const float4*)(X2  + (size_t)r1 * 128 + c);
        } else { *(float4*)(b1 + c) = z; *(float4*)(b1 + 128 + c) = z; }
        __syncwarp();
        float4 a0 = z, a1 = z;
        #pragma unroll 8
        for (int k = 0; k < 256; k += 4) {
            float4 xa = *(const float4*)(b0 + k);
            float4 xb = *(const float4*)(b1 + k);
            const float* wp = Wt + k * WS + c;
            float4 w0 = *(const float4*)(wp);
            float4 w1 = *(const float4*)(wp + WS);
            float4 w2 = *(const float4*)(wp + 2 * WS);
            float4 w3 = *(const float4*)(wp + 3 * WS);
            fma4(a0, w0, xa.x); fma4(a0, w1, xa.y); fma4(a0, w2, xa.z); fma4(a0, w3, xa.w);
            fma4(a1, w0, xb.x); fma4(a1, w1, xb.y); fma4(a1, w2, xb.z); fma4(a1, w3, xb.w);
        }
        float4 bi = *(const float4*)(bias + c);
        if (r0 < N) {
            float4 o = make_float4(sigf(a0.x + bi.x), sigf(a0.y + bi.y), sigf(a0.z + bi.z), sigf(a0.w + bi.w));
            *(float4*)(out + (size_t)r0 * 128 + c) = o;
        }
        if (r1 < N) {
            float4 o = make_float4(sigf(a1.x + bi.x), sigf(a1.y + bi.y), sigf(a1.z + bi.z), sigf(a1.w + bi.w));
            *(float4*)(out + (size_t)r1 * 128 + c) = o;
        }
    }
}

// ------- out = sigmoid(relu( spmm(gg, X) @ W^T + b )) , fused SpMM + matvec -------
__global__ void __launch_bounds__(512, 2)
k_social(const int* __restrict__ rp, const int* __restrict__ cols, const float* __restrict__ vals,
         const float* __restrict__ X, const float* __restrict__ W, const float* __restrict__ Bv,
         float* __restrict__ out, int N)
{
    extern __shared__ float sm[];
    float* Wt   = sm;
    float* bias = Wt + 128 * WS;
    float* ag   = bias + 128;       // 16 warps * 128
    const int tid = threadIdx.x, lane = tid & 31, w = tid >> 5;
    for (int i = tid; i < 128 * 128; i += 512) {
        int j = i >> 7, k = i & 127;
        Wt[k * WS + j] = W[i];
    }
    if (tid < 128) bias[tid] = Bv[tid];
    __syncthreads();
    const int c = lane * 4;
    const float4 z = make_float4(0.f, 0.f, 0.f, 0.f);
    float* arow = ag + w * 128;
    for (int r = blockIdx.x * 16 + w; r < N; r += gridDim.x * 16) {
        float4 acc = z, acc2 = z;
        int s = rp[r], e = rp[r + 1];
        int ed = s;
        for (; ed + 1 < e; ed += 2) {
            int c0 = cols[ed], c1 = cols[ed + 1];
            float v0 = vals[ed], v1 = vals[ed + 1];
            float4 x0 = *(const float4*)(X + (size_t)c0 * 128 + c);
            float4 x1 = *(const float4*)(X + (size_t)c1 * 128 + c);
            fma4(acc, x0, v0); fma4(acc2, x1, v1);
        }
        if (ed < e) {
            int c0 = cols[ed]; float v0 = vals[ed];
            float4 x0 = *(const float4*)(X + (size_t)c0 * 128 + c);
            fma4(acc, x0, v0);
        }
        acc.x += acc2.x; acc.y += acc2.y; acc.z += acc2.z; acc.w += acc2.w;
        __syncwarp();
        *(float4*)(arow + c) = acc;
        __syncwarp();
        float4 a0 = z;
        #pragma unroll 8
        for (int k = 0; k < 128; k += 4) {
            float4 xa = *(const float4*)(arow + k);
            const float* wp = Wt + k * WS + c;
            float4 w0 = *(const float4*)(wp);
            float4 w1 = *(const float4*)(wp + WS);
            float4 w2 = *(const float4*)(wp + 2 * WS);
            float4 w3 = *(const float4*)(wp + 3 * WS);
            fma4(a0, w0, xa.x); fma4(a0, w1, xa.y); fma4(a0, w2, xa.z); fma4(a0, w3, xa.w);
        }
        float4 bi = *(const float4*)(bias + c);
        float4 o = make_float4(sigf(fmaxf(a0.x + bi.x, 0.f)), sigf(fmaxf(a0.y + bi.y, 0.f)),
                               sigf(fmaxf(a0.z + bi.z, 0.f)), sigf(fmaxf(a0.w + bi.w, 0.f)));
        *(float4*)(out + (size_t)r * 128 + c) = o;
    }
}

// ---------------- plain SpMM (optional sigmoid epilogue) ----------------
__global__ void __launch_bounds__(512)
k_spmm(const int* __restrict__ rp, const int* __restrict__ cols, const float* __restrict__ vals,
       const float* __restrict__ X, float* __restrict__ out, int N, int do_sig)
{
    const int lane = threadIdx.x & 31, w = threadIdx.x >> 5;
    const int wpb = blockDim.x >> 5;
    const int c = lane * 4;
    const float4 z = make_float4(0.f, 0.f, 0.f, 0.f);
    for (int r = blockIdx.x * wpb + w; r < N; r += gridDim.x * wpb) {
        float4 acc = z, acc2 = z;
        int s = rp[r], e = rp[r + 1];
        int ed = s;
        for (; ed + 1 < e; ed += 2) {
            int c0 = cols[ed], c1 = cols[ed + 1];
            float v0 = vals[ed], v1 = vals[ed + 1];
            float4 x0 = *(const float4*)(X + (size_t)c0 * 128 + c);
            float4 x1 = *(const float4*)(X + (size_t)c1 * 128 + c);
            fma4(acc, x0, v0); fma4(acc2, x1, v1);
        }
        if (ed < e) {
            int c0 = cols[ed]; float v0 = vals[ed];
            float4 x0 = *(const float4*)(X + (size_t)c0 * 128 + c);
            fma4(acc, x0, v0);
        }
        acc.x += acc2.x; acc.y += acc2.y; acc.z += acc2.z; acc.w += acc2.w;
        if (do_sig) { acc.x = sigf(acc.x); acc.y = sigf(acc.y); acc.z = sigf(acc.z); acc.w = sigf(acc.w); }
        *(float4*)(out + (size_t)r * 128 + c) = acc;
    }
}

// ---------------- final_group = sigmoid((a+b+c)/2) ----------------
__global__ void k_comb(const float* __restrict__ A, const float* __restrict__ Bq,
                       const float* __restrict__ C, float* __restrict__ out, int n)
{
    int i = blockIdx.x * blockDim.x + threadIdx.x;
    if (i < n) out[i] = sigf((A[i] + Bq[i] + C[i]) * 0.5f);
}

// ---------------- scoring: gamma / gamma_2 ----------------
__global__ void __launch_bounds__(256)
k_score(const int* __restrict__ gid, const int* __restrict__ iid,
        const float* __restrict__ FG, const float* __restrict__ FI, const float* __restrict__ AN,
        float* __restrict__ out, int B)
{
    int widx = (blockIdx.x * blockDim.x + threadIdx.x) >> 5;
    int lane = threadIdx.x & 31;
    if (widx >= B) return;
    int g = gid[widx], it = iid[widx];
    const int c = lane * 4;
    float4 ge = *(const float4*)(FG + (size_t)g  * 128 + c);
    float4 ie = *(const float4*)(FI + (size_t)it * 128 + c);
    float4 ne = *(const float4*)(AN + (size_t)g  * 128 + c);
    float d1 = ge.x*ie.x + ge.y*ie.y + ge.z*ie.z + ge.w*ie.w;
    float d2 = ne.x*(ge.x+ie.x) + ne.y*(ge.y+ie.y) + ne.z*(ge.z+ie.z) + ne.w*(ge.w+ie.w);
    d1 = wredsum(d1); d2 = wredsum(d2);
    if (lane == 0) { out[widx] = d1; out[B + widx] = d2; }
}

// ---------------- launch ----------------
extern "C" void kernel_launch(void* const* d_in, const int* in_sizes, int n_in,
                              void* d_out, int out_size)
{
    const int*   group_ids   = (const int*)d_in[0];
    const int*   item_ids    = (const int*)d_in[1];
    const int*   gi_rows     = (const int*)d_in[2];
    const int*   gi_cols     = (const int*)d_in[3];
    const float* gi_vals     = (const float*)d_in[4];
    const int*   gg_rows     = (const int*)d_in[5];
    const int*   gg_cols     = (const int*)d_in[6];
    const float* gg_vals     = (const float*)d_in[7];
    const float* g_feat      = (const float*)d_in[8];
    const float* i_feat      = (const float*)d_in[9];
    const float* emb_group   = (const float*)d_in[10];
    const float* emb_item    = (const float*)d_in[11];
    const float* W_w         = (const float*)d_in[12];
    const float* W_b         = (const float*)d_in[13];
    const float* red_w       = (const float*)d_in[14];
    const float* red_b       = (const float*)d_in[15];
    const float* item_fus_w  = (const float*)d_in[16];
    const float* item_fus_b  = (const float*)d_in[17];
    const float* group_fus_w = (const float*)d_in[18];
    const float* group_fus_b = (const float*)d_in[19];
    float* out = (float*)d_out;

    int B   = in_sizes[0];
    int Egi = in_sizes[2];
    int Egg = in_sizes[5];
    int NG  = in_sizes[8] / 128;  if (NG > NG_CAP) NG = NG_CAP;
    int NI  = in_sizes[9] / 128;  if (NI > NI_CAP) NI = NI_CAP;

    float *p_tmp2, *p_fi, *p_fg, *p_gfi, *p_first, *p_sec, *p_fgrp, *p_an;
    int *p_rp_gi, *p_rp_gg;
    cudaGetSymbolAddress((void**)&p_tmp2,  g_tmp2);
    cudaGetSymbolAddress((void**)&p_fi,    g_fi);
    cudaGetSymbolAddress((void**)&p_fg,    g_fg);
    cudaGetSymbolAddress((void**)&p_gfi,   g_gfi);
    cudaGetSymbolAddress((void**)&p_first, g_first);
    cudaGetSymbolAddress((void**)&p_sec,   g_sec);
    cudaGetSymbolAddress((void**)&p_fgrp,  g_fgrp);
    cudaGetSymbolAddress((void**)&p_an,    g_an);
    cudaGetSymbolAddress((void**)&p_rp_gi, g_rp_gi);
    cudaGetSymbolAddress((void**)&p_rp_gg, g_rp_gg);

    size_t smem1 = (size_t)(128 * WS + 128 + 32 * 128) * sizeof(float);
    size_t smem2 = (size_t)(256 * WS + 128 + 32 * 256) * sizeof(float);
    size_t smem3 = (size_t)(128 * WS + 128 + 16 * 128) * sizeof(float);
    cudaFuncSetAttribute(k_nln,    cudaFuncAttributeMaxDynamicSharedMemorySize, (int)smem1);
    cudaFuncSetAttribute(k_fus,    cudaFuncAttributeMaxDynamicSharedMemorySize, (int)smem2);
    cudaFuncSetAttribute(k_social, cudaFuncAttributeMaxDynamicSharedMemorySize, (int)smem3);

    // row pointers from sorted COO rows
    k_rowptr<<<1024, 256>>>(gi_rows, Egi, NG, p_rp_gi);
    k_rowptr<<<1024, 256>>>(gg_rows, Egg, NG, p_rp_gg);

    // item path: i2 = inorm(inorm(i_feat)@red^T + b); final_item = sig([emb_item,i2]@fus^T + b)
    k_nln<<<296, 512, smem1>>>(i_feat, red_w, red_b, p_tmp2, NI);
    k_fus<<<148, 512, smem2>>>(emb_item, p_tmp2, item_fus_w, item_fus_b, p_fi, NI);

    // group path (reuse tmp buffer)
    k_nln<<<296, 512, smem1>>>(g_feat, red_w, red_b, p_tmp2, NG);
    k_fus<<<148, 512, smem2>>>(emb_group, p_tmp2, group_fus_w, group_fus_b, p_fg, NG);

    // g_from_items = sigmoid(spmm(gi, final_item))
    k_spmm<<<1024, 512>>>(p_rp_gi, gi_cols, gi_vals, p_fi, p_gfi, NG, 1);

    // two social layers (fused spmm + matvec + relu + sigmoid)
    k_social<<<296, 512, smem3>>>(p_rp_gg, gg_cols, gg_vals, p_fg,    W_w, W_b, p_first, NG);
    k_social<<<296, 512, smem3>>>(p_rp_gg, gg_cols, gg_vals, p_first, W_w, W_b, p_sec,   NG);

    // final_group = sigmoid((g_from_items + first + second)/2)
    k_comb<<<(NG * 128 + 255) / 256, 256>>>(p_gfi, p_first, p_sec, p_fgrp, NG * 128);

    // all_neighbors = spmm(gg, final_group)
    k_spmm<<<1024, 512>>>(p_rp_gg, gg_cols, gg_vals, p_fgrp, p_an, NG, 0);

    // scoring
    k_score<<<(B * 32 + 255) / 256, 256>>>(group_ids, item_ids, p_fgrp, p_fi, p_an, out, B);
}

// round 2
// speedup vs baseline: 1.5834x; 1.5834x over previous
#include <cuda_runtime.h>
#include <cuda_bf16.h>
#include <cstdio>

#define FULLMASK 0xffffffffu
#define ASW 132            // smem row stride (words) for A/W tiles: conflict-free frags
#define NG_CAP 50000
#define NI_CAP 100000

// ---------------- scratch (device globals; no allocation allowed) ----------------
__device__ float g_tmp2 [NI_CAP * 128];
__device__ float g_fi   [NI_CAP * 128];
__device__ float g_fg   [NG_CAP * 128];
__device__ float g_gfi  [NG_CAP * 128];
__device__ float g_first[NG_CAP * 128];
__device__ float g_sec  [NG_CAP * 128];
__device__ float g_fgrp [NG_CAP * 128];
__device__ float g_an   [NG_CAP * 128];
__device__ int   g_rp_gi[NG_CAP + 1];
__device__ int   g_rp_gg[NG_CAP + 1];

// ---------------- helpers ----------------
__device__ __forceinline__ float wredsum(float v) {
    #pragma unroll
    for (int o = 16; o; o >>= 1) v += __shfl_xor_sync(FULLMASK, v, o);
    return v;
}
__device__ __forceinline__ float sigf(float x) { return 1.0f / (1.0f + __expf(-x)); }
__device__ __forceinline__ void fma4(float4& a, const float4 w, const float x) {
    a.x = fmaf(w.x, x, a.x); a.y = fmaf(w.y, x, a.y);
    a.z = fmaf(w.z, x, a.z); a.w = fmaf(w.w, x, a.w);
}
__device__ __forceinline__ float4 inorm4(float4 v) {
    float m = wredsum(v.x + v.y + v.z + v.w) * (1.0f / 128.0f);
    float dx = v.x - m, dy = v.y - m, dz = v.z - m, dw = v.w - m;
    float q = wredsum(dx*dx + dy*dy + dz*dz + dw*dw) * (1.0f / 128.0f);
    float inv = rsqrtf(q + 1e-5f);
    return make_float4(dx*inv, dy*inv, dz*inv, dw*inv);
}
__device__ __forceinline__ unsigned f2tf(float f) {
    unsigned u; asm("cvt.rna.tf32.f32 %0, %1;" : "=r"(u) : "f"(f)); return u;
}
__device__ __forceinline__ uint4 cvt4(float4 v) {
    uint4 s; s.x = f2tf(v.x); s.y = f2tf(v.y); s.z = f2tf(v.z); s.w = f2tf(v.w); return s;
}
__device__ __forceinline__ void mma8(float* d, const unsigned* a, unsigned b0, unsigned b1) {
    asm volatile("mma.sync.aligned.m16n8k8.row.col.f32.tf32.tf32.f32 "
        "{%0,%1,%2,%3}, {%4,%5,%6,%7}, {%8,%9}, {%0,%1,%2,%3};"
        : "+f"(d[0]), "+f"(d[1]), "+f"(d[2]), "+f"(d[3])
        : "r"(a[0]), "r"(a[1]), "r"(a[2]), "r"(a[3]), "r"(b0), "r"(b1));
}
// one k-step (k0..k0+7): warp tile M32 x N64
__device__ __forceinline__ void mma_step(float (*d)[8][4],
                                         const unsigned* __restrict__ Asu,
                                         const unsigned* __restrict__ Wsu,
                                         int mbase, int nbase, int qr, int qc, int k0)
{
    unsigned a[2][4];
    #pragma unroll
    for (int t = 0; t < 2; t++) {
        const unsigned* ap = Asu + (mbase + t*16 + qr) * ASW + k0 + qc;
        a[t][0] = ap[0]; a[t][1] = ap[8*ASW]; a[t][2] = ap[4]; a[t][3] = ap[8*ASW + 4];
    }
    #pragma unroll
    for (int nt = 0; nt < 8; nt++) {
        const unsigned* bp = Wsu + (nbase + nt*8 + qr) * ASW + k0 + qc;
        unsigned b0 = bp[0], b1 = bp[4];
        mma8(d[0][nt], a[0], b0, b1);
        mma8(d[1][nt], a[1], b0, b1);
    }
}

// ---------------- row_ptr from sorted COO rows ----------------
__global__ void k_rowptr(const int* __restrict__ rows, int E, int N, int* __restrict__ rp) {
    for (int e = blockIdx.x * blockDim.x + threadIdx.x; e < E; e += gridDim.x * blockDim.x) {
        int r = rows[e];
        int prev = (e == 0) ? -1 : rows[e - 1];
        for (int rr = prev + 1; rr <= r; rr++) rp[rr] = e;
        if (e == E - 1) for (int rr = r + 1; rr <= N; rr++) rp[rr] = E;
    }
}

// ========= out = inorm( inorm(X) @ W^T + b ), W:128x128, MMA tf32 =========
__global__ void __launch_bounds__(512, 1)
k_nln(const float* __restrict__ X, const float* __restrict__ W,
      const float* __restrict__ Bv, float* __restrict__ out, int N)
{
    extern __shared__ float sm[];
    float*    Asf   = sm;                       // 256*ASW
    float*    Wsf   = sm + 256 * ASW;           // 128*ASW
    float*    biasf = Wsf + 128 * ASW;          // 128
    unsigned* Asu = (unsigned*)Asf;
    unsigned* Wsu = (unsigned*)Wsf;
    const int tid = threadIdx.x, lane = tid & 31, w = tid >> 5;
    const int qr = lane >> 2, qc = lane & 3;
    const int mbase = (w >> 1) * 32, nbase = (w & 1) * 64;

    for (int i = tid; i < 128 * 128; i += 512) Wsu[(i >> 7) * ASW + (i & 127)] = f2tf(W[i]);
    if (tid < 128) biasf[tid] = Bv[tid];

    int ntiles = (N + 255) >> 8;
    for (int tile = blockIdx.x; tile < ntiles; tile += gridDim.x) {
        __syncthreads();
        // prologue: per-warp inorm of 16 rows -> smem (tf32)
        #pragma unroll 4
        for (int i = 0; i < 16; i++) {
            int rl = w * 16 + i;
            int r = tile * 256 + rl;
            float4 v = make_float4(0.f, 0.f, 0.f, 0.f);
            if (r < N) { v = *(const float4*)(X + (size_t)r * 128 + lane * 4); v = inorm4(v); }
            *(uint4*)(Asu + rl * ASW + lane * 4) = cvt4(v);
        }
        __syncthreads();
        float d[2][8][4];
        #pragma unroll
        for (int t = 0; t < 2; t++)
            #pragma unroll
            for (int nt = 0; nt < 8; nt++)
                #pragma unroll
                for (int j = 0; j < 4; j++) d[t][nt][j] = 0.f;
        #pragma unroll
        for (int ks = 0; ks < 16; ks++) mma_step(d, Asu, Wsu, mbase, nbase, qr, qc, ks * 8);
        __syncthreads();
        // stash C in As
        #pragma unroll
        for (int t = 0; t < 2; t++)
            #pragma unroll
            for (int nt = 0; nt < 8; nt++) {
                int rl = mbase + t * 16 + qr, col = nbase + nt * 8 + qc * 2;
                *(float2*)(Asf + rl * ASW + col)       = make_float2(d[t][nt][0], d[t][nt][1]);
                *(float2*)(Asf + (rl + 8) * ASW + col) = make_float2(d[t][nt][2], d[t][nt][3]);
            }
        __syncthreads();
        // epilogue: bias + inorm + store
        #pragma unroll 4
        for (int i = 0; i < 16; i++) {
            int rl = w * 16 + i;
            int r = tile * 256 + rl;
            if (r < N) {
                float4 v = *(float4*)(Asf + rl * ASW + lane * 4);
                float4 bi = *(float4*)(biasf + lane * 4);
                v.x += bi.x; v.y += bi.y; v.z += bi.z; v.w += bi.w;
                float4 o = inorm4(v);
                *(float4*)(out + (size_t)r * 128 + lane * 4) = o;
            }
        }
    }
}

// ====== out = sigmoid( [EMB, X2] @ W^T + b ), W:128x256, MMA tf32, K-phased ======
__global__ void __launch_bounds__(512, 1)
k_fus(const float* __restrict__ EMB, const float* __restrict__ X2,
      const float* __restrict__ W, const float* __restrict__ Bv,
      float* __restrict__ out, int N)
{
    extern __shared__ float sm[];
    float*    Asf   = sm;
    float*    Wsf   = sm + 256 * ASW;
    float*    biasf = Wsf + 128 * ASW;
    unsigned* Asu = (unsigned*)Asf;
    unsigned* Wsu = (unsigned*)Wsf;
    const int tid = threadIdx.x, lane = tid & 31, w = tid >> 5;
    const int qr = lane >> 2, qc = lane & 3;
    const int mbase = (w >> 1) * 32, nbase = (w & 1) * 64;

    if (tid < 128) biasf[tid] = Bv[tid];

    int ntiles = (N + 255) >> 8;
    for (int tile = blockIdx.x; tile < ntiles; tile += gridDim.x) {
        float d[2][8][4];
        #pragma unroll
        for (int t = 0; t < 2; t++)
            #pragma unroll
            for (int nt = 0; nt < 8; nt++)
                #pragma unroll
                for (int j = 0; j < 4; j++) d[t][nt][j] = 0.f;
        #pragma unroll
        for (int h = 0; h < 2; h++) {
            __syncthreads();
            const float* src = h ? X2 : EMB;
            for (int i = tid; i < 128 * 128; i += 512)
                Wsu[(i >> 7) * ASW + (i & 127)] = f2tf(W[(size_t)(i >> 7) * 256 + h * 128 + (i & 127)]);
            #pragma unroll 4
            for (int i = 0; i < 16; i++) {
                int rl = w * 16 + i;
                int r = tile * 256 + rl;
                float4 v = make_float4(0.f, 0.f, 0.f, 0.f);
                if (r < N) v = *(const float4*)(src + (size_t)r * 128 + lane * 4);
                *(uint4*)(Asu + rl * ASW + lane * 4) = cvt4(v);
            }
            __syncthreads();
            #pragma unroll
            for (int ks = 0; ks < 16; ks++) mma_step(d, Asu, Wsu, mbase, nbase, qr, qc, ks * 8);
        }
        // epilogue direct from regs
        #pragma unroll
        for (int t = 0; t < 2; t++)
            #pragma unroll
            for (int nt = 0; nt < 8; nt++) {
                int rl = mbase + t * 16 + qr, col = nbase + nt * 8 + qc * 2;
                int r = tile * 256 + rl;
                float b0 = biasf[col], b1 = biasf[col + 1];
                if (r < N)
                    *(float2*)(out + (size_t)r * 128 + col) =
                        make_float2(sigf(d[t][nt][0] + b0), sigf(d[t][nt][1] + b1));
                if (r + 8 < N)
                    *(float2*)(out + (size_t)(r + 8) * 128 + col) =
                        make_float2(sigf(d[t][nt][2] + b0), sigf(d[t][nt][3] + b1));
            }
    }
}

// ==== out = sigmoid(relu( spmm(gg,X) @ W^T + b )): fused SpMM prologue + MMA ====
__global__ void __launch_bounds__(512, 1)
k_social(const int* __restrict__ rp, const int* __restrict__ cols, const float* __restrict__ vals,
         const float* __restrict__ X, const float* __restrict__ W, const float* __restrict__ Bv,
         float* __restrict__ out, int N)
{
    extern __shared__ float sm[];
    float*    Asf   = sm;
    float*    Wsf   = sm + 256 * ASW;
    float*    biasf = Wsf + 128 * ASW;
    unsigned* Asu = (unsigned*)Asf;
    unsigned* Wsu = (unsigned*)Wsf;
    const int tid = threadIdx.x, lane = tid & 31, w = tid >> 5;
    const int qr = lane >> 2, qc = lane & 3;
    const int mbase = (w >> 1) * 32, nbase = (w & 1) * 64;
    const int c = lane * 4;

    for (int i = tid; i < 128 * 128; i += 512) Wsu[(i >> 7) * ASW + (i & 127)] = f2tf(W[i]);
    if (tid < 128) biasf[tid] = Bv[tid];

    int ntiles = (N + 255) >> 8;
    for (int tile = blockIdx.x; tile < ntiles; tile += gridDim.x) {
        __syncthreads();
        // prologue: SpMM rows -> smem (tf32)
        for (int i = 0; i < 16; i++) {
            int rl = w * 16 + i;
            int r = tile * 256 + rl;
            float4 a0 = make_float4(0.f,0.f,0.f,0.f), a1 = a0, a2 = a0, a3 = a0;
            if (r < N) {
                int s = rp[r], e = rp[r + 1];
                int ed = s;
                for (; ed + 3 < e; ed += 4) {
                    int c0 = cols[ed], c1 = cols[ed+1], c2 = cols[ed+2], c3 = cols[ed+3];
                    float v0 = vals[ed], v1 = vals[ed+1], v2 = vals[ed+2], v3 = vals[ed+3];
                    fma4(a0, *(const float4*)(X + (size_t)c0 * 128 + c), v0);
                    fma4(a1, *(const float4*)(X + (size_t)c1 * 128 + c), v1);
                    fma4(a2, *(const float4*)(X + (size_t)c2 * 128 + c), v2);
                    fma4(a3, *(const float4*)(X + (size_t)c3 * 128 + c), v3);
                }
                for (; ed < e; ed++) {
                    int c0 = cols[ed]; float v0 = vals[ed];
                    fma4(a0, *(const float4*)(X + (size_t)c0 * 128 + c), v0);
                }
                a0.x += a1.x + a2.x + a3.x; a0.y += a1.y + a2.y + a3.y;
                a0.z += a1.z + a2.z + a3.z; a0.w += a1.w + a2.w + a3.w;
            }
            *(uint4*)(Asu + rl * ASW + c) = cvt4(a0);
        }
        __syncthreads();
        float d[2][8][4];
        #pragma unroll
        for (int t = 0; t < 2; t++)
            #pragma unroll
            for (int nt = 0; nt < 8; nt++)
                #pragma unroll
                for (int j = 0; j < 4; j++) d[t][nt][j] = 0.f;
        #pragma unroll
        for (int ks = 0; ks < 16; ks++) mma_step(d, Asu, Wsu, mbase, nbase, qr, qc, ks * 8);
        // epilogue: relu + sigmoid, direct store
        #pragma unroll
        for (int t = 0; t < 2; t++)
            #pragma unroll
            for (int nt = 0; nt < 8; nt++) {
                int rl = mbase + t * 16 + qr, col = nbase + nt * 8 + qc * 2;
                int r = tile * 256 + rl;
                float b0 = biasf[col], b1 = biasf[col + 1];
                if (r < N)
                    *(float2*)(out + (size_t)r * 128 + col) =
                        make_float2(sigf(fmaxf(d[t][nt][0] + b0, 0.f)), sigf(fmaxf(d[t][nt][1] + b1, 0.f)));
                if (r + 8 < N)
                    *(float2*)(out + (size_t)(r + 8) * 128 + col) =
                        make_float2(sigf(fmaxf(d[t][nt][2] + b0, 0.f)), sigf(fmaxf(d[t][nt][3] + b1, 0.f)));
            }
    }
}

// ---------------- plain SpMM (optional sigmoid epilogue), 4-deep ILP ----------------
__global__ void __launch_bounds__(512)
k_spmm(const int* __restrict__ rp, const int* __restrict__ cols, const float* __restrict__ vals,
       const float* __restrict__ X, float* __restrict__ out, int N, int do_sig)
{
    const int lane = threadIdx.x & 31, w = threadIdx.x >> 5;
    const int wpb = blockDim.x >> 5;
    const int c = lane * 4;
    for (int r = blockIdx.x * wpb + w; r < N; r += gridDim.x * wpb) {
        float4 a0 = make_float4(0.f,0.f,0.f,0.f), a1 = a0, a2 = a0, a3 = a0;
        int s = rp[r], e = rp[r + 1];
        int ed = s;
        for (; ed + 3 < e; ed += 4) {
            int c0 = cols[ed], c1 = cols[ed+1], c2 = cols[ed+2], c3 = cols[ed+3];
            float v0 = vals[ed], v1 = vals[ed+1], v2 = vals[ed+2], v3 = vals[ed+3];
            fma4(a0, *(const float4*)(X + (size_t)c0 * 128 + c), v0);
            fma4(a1, *(const float4*)(X + (size_t)c1 * 128 + c), v1);
            fma4(a2, *(const float4*)(X + (size_t)c2 * 128 + c), v2);
            fma4(a3, *(const float4*)(X + (size_t)c3 * 128 + c), v3);
        }
        for (; ed < e; ed++) {
            int c0 = cols[ed]; float v0 = vals[ed];
            fma4(a0, *(const float4*)(X + (size_t)c0 * 128 + c), v0);
        }
        a0.x += a1.x + a2.x + a3.x; a0.y += a1.y + a2.y + a3.y;
        a0.z += a1.z + a2.z + a3.z; a0.w += a1.w + a2.w + a3.w;
        if (do_sig) { a0.x = sigf(a0.x); a0.y = sigf(a0.y); a0.z = sigf(a0.z); a0.w = sigf(a0.w); }
        *(float4*)(out + (size_t)r * 128 + c) = a0;
    }
}

// ---------------- final_group = sigmoid((a+b+c)/2) ----------------
__global__ void k_comb(const float* __restrict__ A, const float* __restrict__ Bq,
                       const float* __restrict__ C, float* __restrict__ out, int n)
{
    int i = blockIdx.x * blockDim.x + threadIdx.x;
    if (i < n) out[i] = sigf((A[i] + Bq[i] + C[i]) * 0.5f);
}

// ---------------- scoring ----------------
__global__ void __launch_bounds__(256)
k_score(const int* __restrict__ gid, const int* __restrict__ iid,
        const float* __restrict__ FG, const float* __restrict__ FI, const float* __restrict__ AN,
        float* __restrict__ out, int B)
{
    int widx = (blockIdx.x * blockDim.x + threadIdx.x) >> 5;
    int lane = threadIdx.x & 31;
    if (widx >= B) return;
    int g = gid[widx], it = iid[widx];
    const int c = lane * 4;
    float4 ge = *(const float4*)(FG + (size_t)g  * 128 + c);
    float4 ie = *(const float4*)(FI + (size_t)it * 128 + c);
    float4 ne = *(const float4*)(AN + (size_t)g  * 128 + c);
    float d1 = ge.x*ie.x + ge.y*ie.y + ge.z*ie.z + ge.w*ie.w;
    float d2 = ne.x*(ge.x+ie.x) + ne.y*(ge.y+ie.y) + ne.z*(ge.z+ie.z) + ne.w*(ge.w+ie.w);
    d1 = wredsum(d1); d2 = wredsum(d2);
    if (lane == 0) { out[widx] = d1; out[B + widx] = d2; }
}

// ---------------- launch ----------------
extern "C" void kernel_launch(void* const* d_in, const int* in_sizes, int n_in,
                              void* d_out, int out_size)
{
    const int*   group_ids   = (const int*)d_in[0];
    const int*   item_ids    = (const int*)d_in[1];
    const int*   gi_rows     = (const int*)d_in[2];
    const int*   gi_cols     = (const int*)d_in[3];
    const float* gi_vals     = (const float*)d_in[4];
    const int*   gg_rows     = (const int*)d_in[5];
    const int*   gg_cols     = (const int*)d_in[6];
    const float* gg_vals     = (const float*)d_in[7];
    const float* g_feat      = (const float*)d_in[8];
    const float* i_feat      = (const float*)d_in[9];
    const float* emb_group   = (const float*)d_in[10];
    const float* emb_item    = (const float*)d_in[11];
    const float* W_w         = (const float*)d_in[12];
    const float* W_b         = (const float*)d_in[13];
    const float* red_w       = (const float*)d_in[14];
    const float* red_b       = (const float*)d_in[15];
    const float* item_fus_w  = (const float*)d_in[16];
    const float* item_fus_b  = (const float*)d_in[17];
    const float* group_fus_w = (const float*)d_in[18];
    const float* group_fus_b = (const float*)d_in[19];
    float* out = (float*)d_out;

    int B   = in_sizes[0];
    int Egi = in_sizes[2];
    int Egg = in_sizes[5];
    int NG  = in_sizes[8] / 128;  if (NG > NG_CAP) NG = NG_CAP;
    int NI  = in_sizes[9] / 128;  if (NI > NI_CAP) NI = NI_CAP;

    float *p_tmp2, *p_fi, *p_fg, *p_gfi, *p_first, *p_sec, *p_fgrp, *p_an;
    int *p_rp_gi, *p_rp_gg;
    cudaGetSymbolAddress((void**)&p_tmp2,  g_tmp2);
    cudaGetSymbolAddress((void**)&p_fi,    g_fi);
    cudaGetSymbolAddress((void**)&p_fg,    g_fg);
    cudaGetSymbolAddress((void**)&p_gfi,   g_gfi);
    cudaGetSymbolAddress((void**)&p_first, g_first);
    cudaGetSymbolAddress((void**)&p_sec,   g_sec);
    cudaGetSymbolAddress((void**)&p_fgrp,  g_fgrp);
    cudaGetSymbolAddress((void**)&p_an,    g_an);
    cudaGetSymbolAddress((void**)&p_rp_gi, g_rp_gi);
    cudaGetSymbolAddress((void**)&p_rp_gg, g_rp_gg);

    // smem: A(256*132) + W(128*132) + bias(128) floats
    size_t smem = (size_t)(256 * ASW + 128 * ASW + 128) * sizeof(float);
    cudaFuncSetAttribute(k_nln,    cudaFuncAttributeMaxDynamicSharedMemorySize, (int)smem);
    cudaFuncSetAttribute(k_fus,    cudaFuncAttributeMaxDynamicSharedMemorySize, (int)smem);
    cudaFuncSetAttribute(k_social, cudaFuncAttributeMaxDynamicSharedMemorySize, (int)smem);

    k_rowptr<<<1024, 256>>>(gi_rows, Egi, NG, p_rp_gi);
    k_rowptr<<<1024, 256>>>(gg_rows, Egg, NG, p_rp_gg);

    // item path
    k_nln<<<148, 512, smem>>>(i_feat, red_w, red_b, p_tmp2, NI);
    k_fus<<<148, 512, smem>>>(emb_item, p_tmp2, item_fus_w, item_fus_b, p_fi, NI);

    // group path
    k_nln<<<148, 512, smem>>>(g_feat, red_w, red_b, p_tmp2, NG);
    k_fus<<<148, 512, smem>>>(emb_group, p_tmp2, group_fus_w, group_fus_b, p_fg, NG);

    // g_from_items = sigmoid(spmm(gi, final_item))
    k_spmm<<<1024, 512>>>(p_rp_gi, gi_cols, gi_vals, p_fi, p_gfi, NG, 1);

    // two social layers
    k_social<<<148, 512, smem>>>(p_rp_gg, gg_cols, gg_vals, p_fg,    W_w, W_b, p_first, NG);
    k_social<<<148, 512, smem>>>(p_rp_gg, gg_cols, gg_vals, p_first, W_w, W_b, p_sec,   NG);

    // final_group
    k_comb<<<(NG * 128 + 255) / 256, 256>>>(p_gfi, p_first, p_sec, p_fgrp, NG * 128);

    // all_neighbors = spmm(gg, final_group)
    k_spmm<<<1024, 512>>>(p_rp_gg, gg_cols, gg_vals, p_fgrp, p_an, NG, 0);

    // scoring
    k_score<<<(B * 32 + 255) / 256, 256>>>(group_ids, item_ids, p_fgrp, p_fi, p_an, out, B);
}

// round 4
// speedup vs baseline: 1.8150x; 1.1463x over previous
#include <cuda_runtime.h>
#include <cuda_bf16.h>
#include <cstdio>

#define FULLMASK 0xffffffffu
#define NG_CAP 50000
#define NI_CAP 100000
#define SW128 68    // smem row stride (u32 words) for K=128 tiles
#define SW256 132   // smem row stride for K=256 tiles

// ---------------- scratch (device globals; no allocation allowed) ----------------
__device__ float g_fi   [NI_CAP * 128];   // final_item f32 (scoring)
__device__ float g_gfi  [NG_CAP * 128];
__device__ float g_first[NG_CAP * 128];
__device__ float g_sec  [NG_CAP * 128];
__device__ float g_fgrp [NG_CAP * 128];
__device__ float g_an   [NG_CAP * 128];
__device__ __nv_bfloat16 b_tmp2 [NI_CAP * 128]; // i2 / g2 (GEMM input)
__device__ __nv_bfloat16 b_fi   [NI_CAP * 128]; // final_item (spmm gather)
__device__ __nv_bfloat16 b_fg   [NG_CAP * 128]; // fus_group (spmm gather)
__device__ __nv_bfloat16 b_first[NG_CAP * 128]; // first (spmm gather)
__device__ __nv_bfloat16 b_fgrp [NG_CAP * 128]; // final_group (spmm gather)
__device__ int g_rp_gi[NG_CAP + 1];
__device__ int g_rp_gg[NG_CAP + 1];

// ---------------- helpers ----------------
__device__ __forceinline__ float wredsum(float v) {
    #pragma unroll
    for (int o = 16; o; o >>= 1) v += __shfl_xor_sync(FULLMASK, v, o);
    return v;
}
__device__ __forceinline__ float sigf(float x) { return 1.0f / (1.0f + __expf(-x)); }
__device__ __forceinline__ void fma4(float4& a, const float4 w, const float x) {
    a.x = fmaf(w.x, x, a.x); a.y = fmaf(w.y, x, a.y);
    a.z = fmaf(w.z, x, a.z); a.w = fmaf(w.w, x, a.w);
}
__device__ __forceinline__ float4 inorm4(float4 v) {
    float m = wredsum(v.x + v.y + v.z + v.w) * (1.0f / 128.0f);
    float dx = v.x - m, dy = v.y - m, dz = v.z - m, dw = v.w - m;
    float q = wredsum(dx*dx + dy*dy + dz*dz + dw*dw) * (1.0f / 128.0f);
    float inv = rsqrtf(q + 1e-5f);
    return make_float4(dx*inv, dy*inv, dz*inv, dw*inv);
}
__device__ __forceinline__ unsigned packbf(float lo, float hi) {
    __nv_bfloat162 h = __floats2bfloat162_rn(lo, hi);
    return *reinterpret_cast<unsigned*>(&h);
}
__device__ __forceinline__ float2 unpk(unsigned u) {
    __nv_bfloat162 h = *reinterpret_cast<__nv_bfloat162*>(&u);
    return __bfloat1622float2(h);
}
// gather 4 f32 (elements 4*lane..4*lane+3) from a bf16 row
__device__ __forceinline__ float4 ld4bf(const __nv_bfloat16* p, int lane) {
    uint2 u = ((const uint2*)p)[lane];
    float2 a = unpk(u.x), b = unpk(u.y);
    return make_float4(a.x, a.y, b.x, b.y);
}
// permute word index within each 8-word (k16) group so frag pairs (j, j+4) are adjacent
__device__ __forceinline__ int permw(int j) {
    return (j & ~7) | ((j & 3) << 1) | ((j >> 2) & 1);
}
__device__ __forceinline__ void mma16(float* d, const unsigned* a, unsigned b0, unsigned b1) {
    asm volatile("mma.sync.aligned.m16n8k16.row.col.f32.bf16.bf16.f32 "
        "{%0,%1,%2,%3}, {%4,%5,%6,%7}, {%8,%9}, {%0,%1,%2,%3};"
        : "+f"(d[0]), "+f"(d[1]), "+f"(d[2]), "+f"(d[3])
        : "r"(a[0]), "r"(a[1]), "r"(a[2]), "r"(a[3]), "r"(b0), "r"(b1));
}
// one k16 step, warp tile M32 x N64: 12 LDS.64 + 16 MMA
template<int SW>
__device__ __forceinline__ void mma_step16(float (&d)[2][8][4],
                                           const unsigned* __restrict__ Asu,
                                           const unsigned* __restrict__ Wsu,
                                           int mbase, int nbase, int qr, int qc, int ks)
{
    const int kw = ks * 8 + qc * 2;
    unsigned a[2][4];
    #pragma unroll
    for (int t = 0; t < 2; t++) {
        uint2 lo = *(const uint2*)(Asu + (mbase + t*16 + qr) * SW + kw);
        uint2 hi = *(const uint2*)(Asu + (mbase + t*16 + qr + 8) * SW + kw);
        a[t][0] = lo.x; a[t][1] = hi.x; a[t][2] = lo.y; a[t][3] = hi.y;
    }
    #pragma unroll
    for (int nt = 0; nt < 8; nt++) {
        uint2 b = *(const uint2*)(Wsu + (nbase + nt*8 + qr) * SW + kw);
        mma16(d[0][nt], a[0], b.x, b.y);
        mma16(d[1][nt], a[1], b.x, b.y);
    }
}

// ---------------- row_ptr from sorted COO rows ----------------
__global__ void k_rowptr(const int* __restrict__ rows, int E, int N, int* __restrict__ rp) {
    for (int e = blockIdx.x * blockDim.x + threadIdx.x; e < E; e += gridDim.x * blockDim.x) {
        int r = rows[e];
        int prev = (e == 0) ? -1 : rows[e - 1];
        for (int rr = prev + 1; rr <= r; rr++) rp[rr] = e;
        if (e == E - 1) for (int rr = r + 1; rr <= N; rr++) rp[rr] = E;
    }
}

// ======== out_bf16 = inorm( inorm(X) @ W^T + b ), W:128x128, bf16 MMA ========
__global__ void __launch_bounds__(512, 1)
k_nln(const float* __restrict__ X, const float* __restrict__ W,
      const float* __restrict__ Bv, __nv_bfloat16* __restrict__ outb, int N)
{
    extern __shared__ __align__(16) unsigned smu[];
    unsigned* Asu   = smu;                  // 256*SW128
    unsigned* Wsu   = Asu + 256 * SW128;    // 128*SW128
    float*    biasf = (float*)(Wsu + 128 * SW128);
    const int tid = threadIdx.x, lane = tid & 31, w = tid >> 5;
    const int qr = lane >> 2, qc = lane & 3;
    const int mbase = (w >> 1) * 32, nbase = (w & 1) * 64;

    for (int i = tid; i < 128 * 64; i += 512) {
        int n = i >> 6, j = i & 63;
        float2 wv = ((const float2*)W)[n * 64 + j];
        Wsu[n * SW128 + permw(j)] = packbf(wv.x, wv.y);
    }
    if (tid < 128) biasf[tid] = Bv[tid];

    int ntiles = (N + 255) >> 8;
    for (int tile = blockIdx.x; tile < ntiles; tile += gridDim.x) {
        __syncthreads();
        // prologue: per-warp inorm of 16 rows -> smem bf16 (permuted)
        #pragma unroll 4
        for (int i = 0; i < 16; i++) {
            int rl = w * 16 + i, r = tile * 256 + rl;
            float4 v = make_float4(0.f, 0.f, 0.f, 0.f);
            if (r < N) { v = *(const float4*)(X + (size_t)r * 128 + lane * 4); v = inorm4(v); }
            unsigned* rowp = Asu + rl * SW128;
            int j = lane * 2;
            rowp[permw(j)]     = packbf(v.x, v.y);
            rowp[permw(j + 1)] = packbf(v.z, v.w);
        }
        __syncthreads();
        float d[2][8][4];
        #pragma unroll
        for (int t = 0; t < 2; t++)
            #pragma unroll
            for (int nt = 0; nt < 8; nt++)
                #pragma unroll
                for (int j = 0; j < 4; j++) d[t][nt][j] = 0.f;
        #pragma unroll
        for (int ks = 0; ks < 8; ks++) mma_step16<SW128>(d, Asu, Wsu, mbase, nbase, qr, qc, ks);
        __syncthreads();
        // bias + stash bf16 (unpermuted) into A region
        #pragma unroll
        for (int t = 0; t < 2; t++)
            #pragma unroll
            for (int nt = 0; nt < 8; nt++) {
                int col = nbase + nt * 8 + qc * 2;
                float b0 = biasf[col], b1 = biasf[col + 1];
                int row0 = mbase + t * 16 + qr;
                int wj = (nbase >> 1) + nt * 4 + qc;
                Asu[row0 * SW128 + wj]       = packbf(d[t][nt][0] + b0, d[t][nt][1] + b1);
                Asu[(row0 + 8) * SW128 + wj] = packbf(d[t][nt][2] + b0, d[t][nt][3] + b1);
            }
        __syncthreads();
        // epilogue: re-read row, inorm, store bf16
        #pragma unroll 4
        for (int i = 0; i < 16; i++) {
            int rl = w * 16 + i, r = tile * 256 + rl;
            if (r < N) {
                uint2 u = *(const uint2*)(Asu + rl * SW128 + lane * 2);
                float2 la = unpk(u.x), lb = unpk(u.y);
                float4 o = inorm4(make_float4(la.x, la.y, lb.x, lb.y));
                uint2 st; st.x = packbf(o.x, o.y); st.y = packbf(o.z, o.w);
                *(uint2*)(outb + (size_t)r * 128 + lane * 4) = st;
            }
        }
    }
}

// ==== out = sigmoid([EMB_f32, X2_bf16] @ W^T + b), W:128x256, W fully resident ====
__global__ void __launch_bounds__(512, 1)
k_fus(const float* __restrict__ EMB, const __nv_bfloat16* __restrict__ X2,
      const float* __restrict__ W, const float* __restrict__ Bv,
      float* __restrict__ fout, __nv_bfloat16* __restrict__ bout, int N)
{
    extern __shared__ __align__(16) unsigned smu[];
    unsigned* Asu   = smu;                  // 256*SW256
    unsigned* Wsu   = Asu + 256 * SW256;    // 128*SW256
    float*    biasf = (float*)(Wsu + 128 * SW256);
    const int tid = threadIdx.x, lane = tid & 31, w = tid >> 5;
    const int qr = lane >> 2, qc = lane & 3;
    const int mbase = (w >> 1) * 32, nbase = (w & 1) * 64;

    for (int i = tid; i < 128 * 128; i += 512) {
        int n = i >> 7, j = i & 127;
        float2 wv = ((const float2*)W)[n * 128 + j];
        Wsu[n * SW256 + permw(j)] = packbf(wv.x, wv.y);
    }
    if (tid < 128) biasf[tid] = Bv[tid];

    int ntiles = (N + 255) >> 8;
    for (int tile = blockIdx.x; tile < ntiles; tile += gridDim.x) {
        __syncthreads();
        #pragma unroll 4
        for (int i = 0; i < 16; i++) {
            int rl = w * 16 + i, r = tile * 256 + rl;
            unsigned* rowp = Asu + rl * SW256;
            int j = lane * 2;
            float4 v = make_float4(0.f, 0.f, 0.f, 0.f);
            uint2 u = make_uint2(0u, 0u);
            if (r < N) {
                v = *(const float4*)(EMB + (size_t)r * 128 + lane * 4);
                u = ((const uint2*)(X2 + (size_t)r * 128))[lane];
            }
            rowp[permw(j)]          = packbf(v.x, v.y);
            rowp[permw(j + 1)]      = packbf(v.z, v.w);
            rowp[permw(64 + j)]     = u.x;
            rowp[permw(64 + j + 1)] = u.y;
        }
        __syncthreads();
        float d[2][8][4];
        #pragma unroll
        for (int t = 0; t < 2; t++)
            #pragma unroll
            for (int nt = 0; nt < 8; nt++)
                #pragma unroll
                for (int j = 0; j < 4; j++) d[t][nt][j] = 0.f;
        #pragma unroll
        for (int ks = 0; ks < 16; ks++) mma_step16<SW256>(d, Asu, Wsu, mbase, nbase, qr, qc, ks);
        // epilogue direct from regs
        #pragma unroll
        for (int t = 0; t < 2; t++)
            #pragma unroll
            for (int nt = 0; nt < 8; nt++) {
                int col = nbase + nt * 8 + qc * 2;
                float b0 = biasf[col], b1 = biasf[col + 1];
                int r = tile * 256 + mbase + t * 16 + qr;
                if (r < N) {
                    float s0 = sigf(d[t][nt][0] + b0), s1 = sigf(d[t][nt][1] + b1);
                    if (fout) *(float2*)(fout + (size_t)r * 128 + col) = make_float2(s0, s1);
                    *(unsigned*)(bout + (size_t)r * 128 + col) = packbf(s0, s1);
                }
                if (r + 8 < N) {
                    float s0 = sigf(d[t][nt][2] + b0), s1 = sigf(d[t][nt][3] + b1);
                    if (fout) *(float2*)(fout + (size_t)(r + 8) * 128 + col) = make_float2(s0, s1);
                    *(unsigned*)(bout + (size_t)(r + 8) * 128 + col) = packbf(s0, s1);
                }
            }
    }
}

// ==== out = sigmoid(relu( spmm(gg, Xb) @ W^T + b )): fused bf16 SpMM + bf16 MMA ====
__global__ void __launch_bounds__(512, 1)
k_social(const int* __restrict__ rp, const int* __restrict__ cols, const float* __restrict__ vals,
         const __nv_bfloat16* __restrict__ Xb, const float* __restrict__ W, const float* __restrict__ Bv,
         float* __restrict__ fout, __nv_bfloat16* __restrict__ bout, int N)
{
    extern __shared__ __align__(16) unsigned smu[];
    unsigned* Asu   = smu;
    unsigned* Wsu   = Asu + 256 * SW128;
    float*    biasf = (float*)(Wsu + 128 * SW128);
    const int tid = threadIdx.x, lane = tid & 31, w = tid >> 5;
    const int qr = lane >> 2, qc = lane & 3;
    const int mbase = (w >> 1) * 32, nbase = (w & 1) * 64;

    for (int i = tid; i < 128 * 64; i += 512) {
        int n = i >> 6, j = i & 63;
        float2 wv = ((const float2*)W)[n * 64 + j];
        Wsu[n * SW128 + permw(j)] = packbf(wv.x, wv.y);
    }
    if (tid < 128) biasf[tid] = Bv[tid];

    int ntiles = (N + 255) >> 8;
    for (int tile = blockIdx.x; tile < ntiles; tile += gridDim.x) {
        __syncthreads();
        for (int i = 0; i < 16; i++) {
            int rl = w * 16 + i, r = tile * 256 + rl;
            float4 a0 = make_float4(0.f,0.f,0.f,0.f), a1 = a0, a2 = a0, a3 = a0;
            if (r < N) {
                int s = rp[r], e = rp[r + 1], ed = s;
                for (; ed + 3 < e; ed += 4) {
                    int c0 = cols[ed], c1 = cols[ed+1], c2 = cols[ed+2], c3 = cols[ed+3];
                    float v0 = vals[ed], v1 = vals[ed+1], v2 = vals[ed+2], v3 = vals[ed+3];
                    fma4(a0, ld4bf(Xb + (size_t)c0 * 128, lane), v0);
                    fma4(a1, ld4bf(Xb + (size_t)c1 * 128, lane), v1);
                    fma4(a2, ld4bf(Xb + (size_t)c2 * 128, lane), v2);
                    fma4(a3, ld4bf(Xb + (size_t)c3 * 128, lane), v3);
                }
                for (; ed < e; ed++)
                    fma4(a0, ld4bf(Xb + (size_t)cols[ed] * 128, lane), vals[ed]);
                a0.x += a1.x + a2.x + a3.x; a0.y += a1.y + a2.y + a3.y;
                a0.z += a1.z + a2.z + a3.z; a0.w += a1.w + a2.w + a3.w;
            }
            unsigned* rowp = Asu + rl * SW128;
            int j = lane * 2;
            rowp[permw(j)]     = packbf(a0.x, a0.y);
            rowp[permw(j + 1)] = packbf(a0.z, a0.w);
        }
        __syncthreads();
        float d[2][8][4];
        #pragma unroll
        for (int t = 0; t < 2; t++)
            #pragma unroll
            for (int nt = 0; nt < 8; nt++)
                #pragma unroll
                for (int j = 0; j < 4; j++) d[t][nt][j] = 0.f;
        #pragma unroll
        for (int ks = 0; ks < 8; ks++) mma_step16<SW128>(d, Asu, Wsu, mbase, nbase, qr, qc, ks);
        #pragma unroll
        for (int t = 0; t < 2; t++)
            #pragma unroll
            for (int nt = 0; nt < 8; nt++) {
                int col = nbase + nt * 8 + qc * 2;
                float b0 = biasf[col], b1 = biasf[col + 1];
                int r = tile * 256 + mbase + t * 16 + qr;
                if (r < N) {
                    float s0 = sigf(fmaxf(d[t][nt][0] + b0, 0.f));
                    float s1 = sigf(fmaxf(d[t][nt][1] + b1, 0.f));
                    *(float2*)(fout + (size_t)r * 128 + col) = make_float2(s0, s1);
                    if (bout) *(unsigned*)(bout + (size_t)r * 128 + col) = packbf(s0, s1);
                }
                if (r + 8 < N) {
                    float s0 = sigf(fmaxf(d[t][nt][2] + b0, 0.f));
                    float s1 = sigf(fmaxf(d[t][nt][3] + b1, 0.f));
                    *(float2*)(fout + (size_t)(r + 8) * 128 + col) = make_float2(s0, s1);
                    if (bout) *(unsigned*)(bout + (size_t)(r + 8) * 128 + col) = packbf(s0, s1);
                }
            }
    }
}

// ---------------- plain SpMM over bf16 X (optional sigmoid), f32 out ----------------
__global__ void __launch_bounds__(512)
k_spmm(const int* __restrict__ rp, const int* __restrict__ cols, const float* __restrict__ vals,
       const __nv_bfloat16* __restrict__ Xb, float* __restrict__ out, int N, int do_sig)
{
    const int lane = threadIdx.x & 31, w = threadIdx.x >> 5;
    int r = blockIdx.x * 16 + w;
    if (r >= N) return;
    float4 a0 = make_float4(0.f,0.f,0.f,0.f), a1 = a0, a2 = a0, a3 = a0;
    int s = rp[r], e = rp[r + 1], ed = s;
    for (; ed + 3 < e; ed += 4) {
        int c0 = cols[ed], c1 = cols[ed+1], c2 = cols[ed+2], c3 = cols[ed+3];
        float v0 = vals[ed], v1 = vals[ed+1], v2 = vals[ed+2], v3 = vals[ed+3];
        fma4(a0, ld4bf(Xb + (size_t)c0 * 128, lane), v0);
        fma4(a1, ld4bf(Xb + (size_t)c1 * 128, lane), v1);
        fma4(a2, ld4bf(Xb + (size_t)c2 * 128, lane), v2);
        fma4(a3, ld4bf(Xb + (size_t)c3 * 128, lane), v3);
    }
    for (; ed < e; ed++)
        fma4(a0, ld4bf(Xb + (size_t)cols[ed] * 128, lane), vals[ed]);
    a0.x += a1.x + a2.x + a3.x; a0.y += a1.y + a2.y + a3.y;
    a0.z += a1.z + a2.z + a3.z; a0.w += a1.w + a2.w + a3.w;
    if (do_sig) { a0.x = sigf(a0.x); a0.y = sigf(a0.y); a0.z = sigf(a0.z); a0.w = sigf(a0.w); }
    *(float4*)(out + (size_t)r * 128 + lane * 4) = a0;
}

// ---------------- final_group = sigmoid((a+b+c)/2), dual f32+bf16 ----------------
__global__ void k_comb(const float* __restrict__ A, const float* __restrict__ Bq,
                       const float* __restrict__ C, float* __restrict__ outf,
                       __nv_bfloat16* __restrict__ outb, int n4)
{
    int i = blockIdx.x * blockDim.x + threadIdx.x;
    if (i >= n4) return;
    float4 a = ((const float4*)A)[i], b = ((const float4*)Bq)[i], c = ((const float4*)C)[i];
    float4 o;
    o.x = sigf((a.x + b.x + c.x) * 0.5f);
    o.y = sigf((a.y + b.y + c.y) * 0.5f);
    o.z = sigf((a.z + b.z + c.z) * 0.5f);
    o.w = sigf((a.w + b.w + c.w) * 0.5f);
    ((float4*)outf)[i] = o;
    uint2 st; st.x = packbf(o.x, o.y); st.y = packbf(o.z, o.w);
    ((uint2*)outb)[i] = st;
}

// ---------------- scoring ----------------
__global__ void __launch_bounds__(256)
k_score(const int* __restrict__ gid, const int* __restrict__ iid,
        const float* __restrict__ FG, const float* __restrict__ FI, const float* __restrict__ AN,
        float* __restrict__ out, int B)
{
    int widx = (blockIdx.x * blockDim.x + threadIdx.x) >> 5;
    int lane = threadIdx.x & 31;
    if (widx >= B) return;
    int g = gid[widx], it = iid[widx];
    const int c = lane * 4;
    float4 ge = *(const float4*)(FG + (size_t)g  * 128 + c);
    float4 ie = *(const float4*)(FI + (size_t)it * 128 + c);
    float4 ne = *(const float4*)(AN + (size_t)g  * 128 + c);
    float d1 = ge.x*ie.x + ge.y*ie.y + ge.z*ie.z + ge.w*ie.w;
    float d2 = ne.x*(ge.x+ie.x) + ne.y*(ge.y+ie.y) + ne.z*(ge.z+ie.z) + ne.w*(ge.w+ie.w);
    d1 = wredsum(d1); d2 = wredsum(d2);
    if (lane == 0) { out[widx] = d1; out[B + widx] = d2; }
}

// ---------------- launch ----------------
extern "C" void kernel_launch(void* const* d_in, const int* in_sizes, int n_in,
                              void* d_out, int out_size)
{
    const int*   group_ids   = (const int*)d_in[0];
    const int*   item_ids    = (const int*)d_in[1];
    const int*   gi_rows     = (const int*)d_in[2];
    const int*   gi_cols     = (const int*)d_in[3];
    const float* gi_vals     = (const float*)d_in[4];
    const int*   gg_rows     = (const int*)d_in[5];
    const int*   gg_cols     = (const int*)d_in[6];
    const float* gg_vals     = (const float*)d_in[7];
    const float* g_feat      = (const float*)d_in[8];
    const float* i_feat      = (const float*)d_in[9];
    const float* emb_group   = (const float*)d_in[10];
    const float* emb_item    = (const float*)d_in[11];
    const float* W_w         = (const float*)d_in[12];
    const float* W_b         = (const float*)d_in[13];
    const float* red_w       = (const float*)d_in[14];
    const float* red_b       = (const float*)d_in[15];
    const float* item_fus_w  = (const float*)d_in[16];
    const float* item_fus_b  = (const float*)d_in[17];
    const float* group_fus_w = (const float*)d_in[18];
    const float* group_fus_b = (const float*)d_in[19];
    float* out = (float*)d_out;

    int B   = in_sizes[0];
    int Egi = in_sizes[2];
    int Egg = in_sizes[5];
    int NG  = in_sizes[8] / 128;  if (NG > NG_CAP) NG = NG_CAP;
    int NI  = in_sizes[9] / 128;  if (NI > NI_CAP) NI = NI_CAP;

    float *p_fi, *p_gfi, *p_first, *p_sec, *p_fgrp, *p_an;
    __nv_bfloat16 *pb_tmp2, *pb_fi, *pb_fg, *pb_first, *pb_fgrp;
    int *p_rp_gi, *p_rp_gg;
    cudaGetSymbolAddress((void**)&p_fi,     g_fi);
    cudaGetSymbolAddress((void**)&p_gfi,    g_gfi);
    cudaGetSymbolAddress((void**)&p_first,  g_first);
    cudaGetSymbolAddress((void**)&p_sec,    g_sec);
    cudaGetSymbolAddress((void**)&p_fgrp,   g_fgrp);
    cudaGetSymbolAddress((void**)&p_an,     g_an);
    cudaGetSymbolAddress((void**)&pb_tmp2,  b_tmp2);
    cudaGetSymbolAddress((void**)&pb_fi,    b_fi);
    cudaGetSymbolAddress((void**)&pb_fg,    b_fg);
    cudaGetSymbolAddress((void**)&pb_first, b_first);
    cudaGetSymbolAddress((void**)&pb_fgrp,  b_fgrp);
    cudaGetSymbolAddress((void**)&p_rp_gi,  g_rp_gi);
    cudaGetSymbolAddress((void**)&p_rp_gg,  g_rp_gg);

    size_t smemN = (size_t)(256 * SW128 + 128 * SW128) * 4 + 512;
    size_t smemF = (size_t)(256 * SW256 + 128 * SW256) * 4 + 512;
    cudaFuncSetAttribute(k_nln,    cudaFuncAttributeMaxDynamicSharedMemorySize, (int)smemN);
    cudaFuncSetAttribute(k_fus,    cudaFuncAttributeMaxDynamicSharedMemorySize, (int)smemF);
    cudaFuncSetAttribute(k_social, cudaFuncAttributeMaxDynamicSharedMemorySize, (int)smemN);

    int tI = (NI + 255) >> 8, tG = (NG + 255) >> 8;

    k_rowptr<<<1024, 256>>>(gi_rows, Egi, NG, p_rp_gi);
    k_rowptr<<<1024, 256>>>(gg_rows, Egg, NG, p_rp_gg);

    // item path: i2(bf16) = nln(i_feat); final_item = fus(emb_item, i2)
    k_nln<<<tI, 512, smemN>>>(i_feat, red_w, red_b, pb_tmp2, NI);
    k_fus<<<tI, 512, smemF>>>(emb_item, pb_tmp2, item_fus_w, item_fus_b, p_fi, pb_fi, NI);

    // group path: g2(bf16) = nln(g_feat); fus_group(bf16) = fus(emb_group, g2)
    k_nln<<<tG, 512, smemN>>>(g_feat, red_w, red_b, pb_tmp2, NG);
    k_fus<<<tG, 512, smemF>>>(emb_group, pb_tmp2, group_fus_w, group_fus_b, nullptr, pb_fg, NG);

    // g_from_items = sigmoid(spmm(gi, final_item))
    k_spmm<<<(NG + 15) / 16, 512>>>(p_rp_gi, gi_cols, gi_vals, pb_fi, p_gfi, NG, 1);

    // two social layers
    k_social<<<tG, 512, smemN>>>(p_rp_gg, gg_cols, gg_vals, pb_fg,    W_w, W_b, p_first, pb_first, NG);
    k_social<<<tG, 512, smemN>>>(p_rp_gg, gg_cols, gg_vals, pb_first, W_w, W_b, p_sec,   nullptr,  NG);

    // final_group
    k_comb<<<(NG * 32 + 255) / 256, 256>>>(p_gfi, p_first, p_sec, p_fgrp, pb_fgrp, NG * 32);

    // all_neighbors = spmm(gg, final_group)
    k_spmm<<<(NG + 15) / 16, 512>>>(p_rp_gg, gg_cols, gg_vals, pb_fgrp, p_an, NG, 0);

    // scoring
    k_score<<<(B * 32 + 255) / 256, 256>>>(group_ids, item_ids, p_fgrp, p_fi, p_an, out, B);
}

// round 5
// speedup vs baseline: 1.8909x; 1.0418x over previous
#include <cuda_runtime.h>
#include <cuda_bf16.h>
#include <cstdio>

#define FULLMASK 0xffffffffu
#define NG_CAP 50000
#define NI_CAP 100000
#define RS1 68     // smem row stride (u32 words) K=128 tiles
#define RS2 132    // smem row stride (u32 words) K=256 tiles

// ---------------- scratch (device globals) ----------------
__device__ float g_fi   [NI_CAP * 128];
__device__ float g_gfi  [NG_CAP * 128];
__device__ float g_first[NG_CAP * 128];
__device__ float g_fgrp [NG_CAP * 128];
__device__ float g_an   [NG_CAP * 128];
__device__ __nv_bfloat16 b_tmp2 [NI_CAP * 128];
__device__ __nv_bfloat16 b_fi   [NI_CAP * 128];
__device__ __nv_bfloat16 b_fg   [NG_CAP * 128];
__device__ __nv_bfloat16 b_first[NG_CAP * 128];
__device__ __nv_bfloat16 b_fgrp [NG_CAP * 128];
__device__ __nv_bfloat16 b_embi [NI_CAP * 128];
__device__ __nv_bfloat16 b_embg [NG_CAP * 128];
__device__ int g_rp_gi[NG_CAP + 1];
__device__ int g_rp_gg[NG_CAP + 1];

// ---------------- helpers ----------------
__device__ __forceinline__ float wredsum(float v) {
    #pragma unroll
    for (int o = 16; o; o >>= 1) v += __shfl_xor_sync(FULLMASK, v, o);
    return v;
}
__device__ __forceinline__ float sigf(float x) { return 1.0f / (1.0f + __expf(-x)); }
__device__ __forceinline__ void fma4(float4& a, const float4 w, const float x) {
    a.x = fmaf(w.x, x, a.x); a.y = fmaf(w.y, x, a.y);
    a.z = fmaf(w.z, x, a.z); a.w = fmaf(w.w, x, a.w);
}
// parallel-chain instance norm: Σx and Σx² reduced simultaneously
__device__ __forceinline__ float4 inorm4(float4 v) {
    float s = v.x + v.y + v.z + v.w;
    float q = v.x*v.x + v.y*v.y + v.z*v.z + v.w*v.w;
    #pragma unroll
    for (int o = 16; o; o >>= 1) {
        s += __shfl_xor_sync(FULLMASK, s, o);
        q += __shfl_xor_sync(FULLMASK, q, o);
    }
    float m = s * (1.0f / 128.0f);
    float var = q * (1.0f / 128.0f) - m * m;
    float inv = rsqrtf(var + 1e-5f);
    return make_float4((v.x-m)*inv, (v.y-m)*inv, (v.z-m)*inv, (v.w-m)*inv);
}
__device__ __forceinline__ unsigned packbf(float lo, float hi) {
    __nv_bfloat162 h = __floats2bfloat162_rn(lo, hi);
    return *reinterpret_cast<unsigned*>(&h);
}
__device__ __forceinline__ float2 unpk(unsigned u) {
    __nv_bfloat162 h = *reinterpret_cast<__nv_bfloat162*>(&u);
    return __bfloat1622float2(h);
}
__device__ __forceinline__ float4 ld4bf(const __nv_bfloat16* p, int lane) {
    uint2 u = ((const uint2*)p)[lane];
    float2 a = unpk(u.x), b = unpk(u.y);
    return make_float4(a.x, a.y, b.x, b.y);
}
__device__ __forceinline__ unsigned smaddr(const void* p) {
    unsigned a;
    asm("{ .reg .u64 t; cvta.to.shared.u64 t, %1; cvt.u32.u64 %0, t; }" : "=r"(a) : "l"(p));
    return a;
}
__device__ __forceinline__ void ldsm4(unsigned* r, unsigned addr) {
    asm volatile("ldmatrix.sync.aligned.m8n8.x4.shared.b16 {%0,%1,%2,%3}, [%4];"
        : "=r"(r[0]), "=r"(r[1]), "=r"(r[2]), "=r"(r[3]) : "r"(addr));
}
__device__ __forceinline__ void mma16(float* d, const unsigned* a, unsigned b0, unsigned b1) {
    asm volatile("mma.sync.aligned.m16n8k16.row.col.f32.bf16.bf16.f32 "
        "{%0,%1,%2,%3}, {%4,%5,%6,%7}, {%8,%9}, {%0,%1,%2,%3};"
        : "+f"(d[0]), "+f"(d[1]), "+f"(d[2]), "+f"(d[3])
        : "r"(a[0]), "r"(a[1]), "r"(a[2]), "r"(a[3]), "r"(b0), "r"(b1));
}
// warp tile M32 x N64, one k16 step: 2 A-ldsm + 4 B-ldsm + 16 mma
template<int RS>
__device__ __forceinline__ void mma_m32n64(float (&d)[2][8][4], unsigned aBase, unsigned bBase, int ks) {
    const unsigned kb = ks * 32;
    unsigned a0[4], a1[4];
    ldsm4(a0, aBase + kb);
    ldsm4(a1, aBase + 16*RS*4 + kb);
    #pragma unroll
    for (int q = 0; q < 4; q++) {
        unsigned b[4];
        ldsm4(b, bBase + q*16*RS*4 + kb);
        mma16(d[0][2*q],   a0, b[0], b[1]);
        mma16(d[1][2*q],   a1, b[0], b[1]);
        mma16(d[0][2*q+1], a0, b[2], b[3]);
        mma16(d[1][2*q+1], a1, b[2], b[3]);
    }
}
// warp tile M32 x N32 (k_fus half-N)
template<int RS>
__device__ __forceinline__ void mma_m32n32(float (&d)[2][4][4], unsigned aBase, unsigned bBase, int ks) {
    const unsigned kb = ks * 32;
    unsigned a0[4], a1[4];
    ldsm4(a0, aBase + kb);
    ldsm4(a1, aBase + 16*RS*4 + kb);
    #pragma unroll
    for (int q = 0; q < 2; q++) {
        unsigned b[4];
        ldsm4(b, bBase + q*16*RS*4 + kb);
        mma16(d[0][2*q],   a0, b[0], b[1]);
        mma16(d[1][2*q],   a1, b[0], b[1]);
        mma16(d[0][2*q+1], a0, b[2], b[3]);
        mma16(d[1][2*q+1], a1, b[2], b[3]);
    }
}

// ---------------- row_ptr from sorted COO rows ----------------
__global__ void k_rowptr(const int* __restrict__ rows, int E, int N, int* __restrict__ rp) {
    for (int e = blockIdx.x * blockDim.x + threadIdx.x; e < E; e += gridDim.x * blockDim.x) {
        int r = rows[e];
        int prev = (e == 0) ? -1 : rows[e - 1];
        for (int rr = prev + 1; rr <= r; rr++) rp[rr] = e;
        if (e == E - 1) for (int rr = r + 1; rr <= N; rr++) rp[rr] = E;
    }
}

// ---------------- f32 -> bf16 convert ----------------
__global__ void k_cvt(const float* __restrict__ in, __nv_bfloat16* __restrict__ out, int n2) {
    int i = blockIdx.x * blockDim.x + threadIdx.x;
    if (i < n2) { float2 v = ((const float2*)in)[i]; ((unsigned*)out)[i] = packbf(v.x, v.y); }
}

// ======== outb = inorm( inorm(X) @ W^T + b ), W:128x128 ========
// 256 threads, 2 blocks/SM, tile M128, warp tile M32xN64
__global__ void __launch_bounds__(256, 2)
k_nln(const float* __restrict__ X, const float* __restrict__ W,
      const float* __restrict__ Bv, __nv_bfloat16* __restrict__ outb, int N)
{
    extern __shared__ __align__(16) unsigned smu[];
    unsigned* Asu = smu;                // 128*RS1
    unsigned* Wsu = Asu + 128 * RS1;    // 128*RS1
    float*    biasf = (float*)(Wsu + 128 * RS1);
    const int tid = threadIdx.x, lane = tid & 31, w = tid >> 5;
    const int qr = lane >> 2, qc = lane & 3;
    const int mbase = (w >> 1) * 32, nbase = (w & 1) * 64;

    for (int i = tid; i < 128 * 64; i += 256) {
        float2 wv = ((const float2*)W)[i];
        Wsu[(i >> 6) * RS1 + (i & 63)] = packbf(wv.x, wv.y);
    }
    if (tid < 128) biasf[tid] = Bv[tid];

    const unsigned Au = smaddr(Asu), Wu = smaddr(Wsu);
    const unsigned aBase = Au + (((mbase + (lane & 15)) * RS1 + ((lane >> 4) << 2)) << 2);
    const unsigned bBase = Wu + (((nbase + ((lane >> 4) << 3) + (lane & 7)) * RS1 + (((lane >> 3) & 1) << 2)) << 2);

    int ntiles = (N + 127) >> 7;
    for (int tile = blockIdx.x; tile < ntiles; tile += gridDim.x) {
        __syncthreads();
        #pragma unroll 4
        for (int i = 0; i < 16; i++) {
            int rl = w * 16 + i, r = tile * 128 + rl;
            float4 v = make_float4(0.f, 0.f, 0.f, 0.f);
            if (r < N) { v = *(const float4*)(X + (size_t)r * 128 + lane * 4); v = inorm4(v); }
            uint2 st; st.x = packbf(v.x, v.y); st.y = packbf(v.z, v.w);
            *(uint2*)(Asu + rl * RS1 + lane * 2) = st;
        }
        __syncthreads();
        float d[2][8][4];
        #pragma unroll
        for (int t = 0; t < 2; t++)
            #pragma unroll
            for (int nt = 0; nt < 8; nt++)
                #pragma unroll
                for (int j = 0; j < 4; j++) d[t][nt][j] = 0.f;
        #pragma unroll
        for (int ks = 0; ks < 8; ks++) mma_m32n64<RS1>(d, aBase, bBase, ks);
        __syncthreads();
        // stash C (+bias) bf16 into A region
        #pragma unroll
        for (int t = 0; t < 2; t++)
            #pragma unroll
            for (int nt = 0; nt < 8; nt++) {
                int col = nbase + nt * 8 + qc * 2;
                float b0 = biasf[col], b1 = biasf[col + 1];
                int row0 = mbase + t * 16 + qr;
                int wj = (nbase >> 1) + nt * 4 + qc;
                Asu[row0 * RS1 + wj]       = packbf(d[t][nt][0] + b0, d[t][nt][1] + b1);
                Asu[(row0 + 8) * RS1 + wj] = packbf(d[t][nt][2] + b0, d[t][nt][3] + b1);
            }
        __syncthreads();
        #pragma unroll 4
        for (int i = 0; i < 16; i++) {
            int rl = w * 16 + i, r = tile * 128 + rl;
            if (r < N) {
                uint2 u = *(const uint2*)(Asu + rl * RS1 + lane * 2);
                float2 la = unpk(u.x), lb = unpk(u.y);
                float4 o = inorm4(make_float4(la.x, la.y, lb.x, lb.y));
                uint2 st; st.x = packbf(o.x, o.y); st.y = packbf(o.z, o.w);
                *(uint2*)(outb + (size_t)r * 128 + lane * 4) = st;
            }
        }
    }
}

// ==== out = sigmoid([EMBb, X2] @ W^T + b), K=256; each block does one N64 half ====
__global__ void __launch_bounds__(256, 2)
k_fus(const __nv_bfloat16* __restrict__ EMBb, const __nv_bfloat16* __restrict__ X2,
      const float* __restrict__ W, const float* __restrict__ Bv,
      float* __restrict__ fout, __nv_bfloat16* __restrict__ bout, int N)
{
    extern __shared__ __align__(16) unsigned smu[];
    unsigned* Asu = smu;                // 128*RS2
    unsigned* Wsu = Asu + 128 * RS2;    // 64*RS2
    float*    biasf = (float*)(Wsu + 64 * RS2);
    const int tid = threadIdx.x, lane = tid & 31, w = tid >> 5;
    const int qr = lane >> 2, qc = lane & 3;
    const int half = blockIdx.x & 1;
    const int mbase = (w >> 1) * 32, nloc = (w & 1) * 32;

    for (int i = tid; i < 64 * 128; i += 256) {
        int n = i >> 7, j = i & 127;
        float2 wv = ((const float2*)W)[(size_t)(half * 64 + n) * 128 + j];
        Wsu[n * RS2 + j] = packbf(wv.x, wv.y);
    }
    if (tid < 64) biasf[tid] = Bv[half * 64 + tid];

    const unsigned Au = smaddr(Asu), Wu = smaddr(Wsu);
    const unsigned aBase = Au + (((mbase + (lane & 15)) * RS2 + ((lane >> 4) << 2)) << 2);
    const unsigned bBase = Wu + (((nloc + ((lane >> 4) << 3) + (lane & 7)) * RS2 + (((lane >> 3) & 1) << 2)) << 2);

    int ntiles = (N + 127) >> 7;
    for (int tile = blockIdx.x >> 1; tile < ntiles; tile += gridDim.x >> 1) {
        __syncthreads();
        #pragma unroll 4
        for (int i = 0; i < 16; i++) {
            int rl = w * 16 + i, r = tile * 128 + rl;
            uint2 ue = make_uint2(0u, 0u), ux = make_uint2(0u, 0u);
            if (r < N) {
                ue = ((const uint2*)(EMBb + (size_t)r * 128))[lane];
                ux = ((const uint2*)(X2   + (size_t)r * 128))[lane];
            }
            unsigned* rowp = Asu + rl * RS2;
            *(uint2*)(rowp + lane * 2)      = ue;
            *(uint2*)(rowp + 64 + lane * 2) = ux;
        }
        __syncthreads();
        float d[2][4][4];
        #pragma unroll
        for (int t = 0; t < 2; t++)
            #pragma unroll
            for (int nt = 0; nt < 4; nt++)
                #pragma unroll
                for (int j = 0; j < 4; j++) d[t][nt][j] = 0.f;
        #pragma unroll
        for (int ks = 0; ks < 16; ks++) mma_m32n32<RS2>(d, aBase, bBase, ks);
        #pragma unroll
        for (int t = 0; t < 2; t++)
            #pragma unroll
            for (int nt = 0; nt < 4; nt++) {
                int lcol = nloc + nt * 8 + qc * 2;
                int gcol = half * 64 + lcol;
                float b0 = biasf[lcol], b1 = biasf[lcol + 1];
                int r = tile * 128 + mbase + t * 16 + qr;
                if (r < N) {
                    float s0 = sigf(d[t][nt][0] + b0), s1 = sigf(d[t][nt][1] + b1);
                    if (fout) *(float2*)(fout + (size_t)r * 128 + gcol) = make_float2(s0, s1);
                    *(unsigned*)(bout + (size_t)r * 128 + gcol) = packbf(s0, s1);
                }
                if (r + 8 < N) {
                    float s0 = sigf(d[t][nt][2] + b0), s1 = sigf(d[t][nt][3] + b1);
                    if (fout) *(float2*)(fout + (size_t)(r + 8) * 128 + gcol) = make_float2(s0, s1);
                    *(unsigned*)(bout + (size_t)(r + 8) * 128 + gcol) = packbf(s0, s1);
                }
            }
    }
}

// ==== social layer: s = sigmoid(relu( spmm(gg,Xb) @ W^T + b ))
//      if addA: out = sigmoid((s + addA + addB)/2)  (fused final_group) ====
__global__ void __launch_bounds__(256, 2)
k_social(const int* __restrict__ rp, const int* __restrict__ cols, const float* __restrict__ vals,
         const __nv_bfloat16* __restrict__ Xb, const float* __restrict__ W, const float* __restrict__ Bv,
         float* __restrict__ fout, __nv_bfloat16* __restrict__ bout,
         const float* __restrict__ addA, const float* __restrict__ addB, int N)
{
    extern __shared__ __align__(16) unsigned smu[];
    unsigned* Asu = smu;
    unsigned* Wsu = Asu + 128 * RS1;
    float*    biasf = (float*)(Wsu + 128 * RS1);
    const int tid = threadIdx.x, lane = tid & 31, w = tid >> 5;
    const int qr = lane >> 2, qc = lane & 3;
    const int mbase = (w >> 1) * 32, nbase = (w & 1) * 64;

    for (int i = tid; i < 128 * 64; i += 256) {
        float2 wv = ((const float2*)W)[i];
        Wsu[(i >> 6) * RS1 + (i & 63)] = packbf(wv.x, wv.y);
    }
    if (tid < 128) biasf[tid] = Bv[tid];

    const unsigned Au = smaddr(Asu), Wu = smaddr(Wsu);
    const unsigned aBase = Au + (((mbase + (lane & 15)) * RS1 + ((lane >> 4) << 2)) << 2);
    const unsigned bBase = Wu + (((nbase + ((lane >> 4) << 3) + (lane & 7)) * RS1 + (((lane >> 3) & 1) << 2)) << 2);

    int ntiles = (N + 127) >> 7;
    for (int tile = blockIdx.x; tile < ntiles; tile += gridDim.x) {
        __syncthreads();
        for (int i = 0; i < 16; i++) {
            int rl = w * 16 + i, r = tile * 128 + rl;
            float4 a0 = make_float4(0.f,0.f,0.f,0.f), a1 = a0, a2 = a0, a3 = a0;
            if (r < N) {
                int s = rp[r], e = rp[r + 1], ed = s;
                for (; ed + 3 < e; ed += 4) {
                    int c0 = cols[ed], c1 = cols[ed+1], c2 = cols[ed+2], c3 = cols[ed+3];
                    float v0 = vals[ed], v1 = vals[ed+1], v2 = vals[ed+2], v3 = vals[ed+3];
                    fma4(a0, ld4bf(Xb + (size_t)c0 * 128, lane), v0);
                    fma4(a1, ld4bf(Xb + (size_t)c1 * 128, lane), v1);
                    fma4(a2, ld4bf(Xb + (size_t)c2 * 128, lane), v2);
                    fma4(a3, ld4bf(Xb + (size_t)c3 * 128, lane), v3);
                }
                for (; ed < e; ed++)
                    fma4(a0, ld4bf(Xb + (size_t)cols[ed] * 128, lane), vals[ed]);
                a0.x += a1.x + a2.x + a3.x; a0.y += a1.y + a2.y + a3.y;
                a0.z += a1.z + a2.z + a3.z; a0.w += a1.w + a2.w + a3.w;
            }
            uint2 st; st.x = packbf(a0.x, a0.y); st.y = packbf(a0.z, a0.w);
            *(uint2*)(Asu + rl * RS1 + lane * 2) = st;
        }
        __syncthreads();
        float d[2][8][4];
        #pragma unroll
        for (int t = 0; t < 2; t++)
            #pragma unroll
            for (int nt = 0; nt < 8; nt++)
                #pragma unroll
                for (int j = 0; j < 4; j++) d[t][nt][j] = 0.f;
        #pragma unroll
        for (int ks = 0; ks < 8; ks++) mma_m32n64<RS1>(d, aBase, bBase, ks);
        #pragma unroll
        for (int t = 0; t < 2; t++)
            #pragma unroll
            for (int nt = 0; nt < 8; nt++) {
                int col = nbase + nt * 8 + qc * 2;
                float b0 = biasf[col], b1 = biasf[col + 1];
                #pragma unroll
                for (int h = 0; h < 2; h++) {
                    int r = tile * 128 + mbase + t * 16 + qr + h * 8;
                    if (r < N) {
                        float s0 = sigf(fmaxf(d[t][nt][2*h]   + b0, 0.f));
                        float s1 = sigf(fmaxf(d[t][nt][2*h+1] + b1, 0.f));
                        if (addA) {
                            float2 pa = *(const float2*)(addA + (size_t)r * 128 + col);
                            float2 pb = *(const float2*)(addB + (size_t)r * 128 + col);
                            s0 = sigf((s0 + pa.x + pb.x) * 0.5f);
                            s1 = sigf((s1 + pa.y + pb.y) * 0.5f);
                        }
                        *(float2*)(fout + (size_t)r * 128 + col) = make_float2(s0, s1);
                        if (bout) *(unsigned*)(bout + (size_t)r * 128 + col) = packbf(s0, s1);
                    }
                }
            }
    }
}

// ---------------- plain SpMM over bf16 X (optional sigmoid), f32 out ----------------
__global__ void __launch_bounds__(512)
k_spmm(const int* __restrict__ rp, const int* __restrict__ cols, const float* __restrict__ vals,
       const __nv_bfloat16* __restrict__ Xb, float* __restrict__ out, int N, int do_sig)
{
    const int lane = threadIdx.x & 31, w = threadIdx.x >> 5;
    int r = blockIdx.x * 16 + w;
    if (r >= N) return;
    float4 a0 = make_float4(0.f,0.f,0.f,0.f), a1 = a0, a2 = a0, a3 = a0;
    int s = rp[r], e = rp[r + 1], ed = s;
    for (; ed + 3 < e; ed += 4) {
        int c0 = cols[ed], c1 = cols[ed+1], c2 = cols[ed+2], c3 = cols[ed+3];
        float v0 = vals[ed], v1 = vals[ed+1], v2 = vals[ed+2], v3 = vals[ed+3];
        fma4(a0, ld4bf(Xb + (size_t)c0 * 128, lane), v0);
        fma4(a1, ld4bf(Xb + (size_t)c1 * 128, lane), v1);
        fma4(a2, ld4bf(Xb + (size_t)c2 * 128, lane), v2);
        fma4(a3, ld4bf(Xb + (size_t)c3 * 128, lane), v3);
    }
    for (; ed < e; ed++)
        fma4(a0, ld4bf(Xb + (size_t)cols[ed] * 128, lane), vals[ed]);
    a0.x += a1.x + a2.x + a3.x; a0.y += a1.y + a2.y + a3.y;
    a0.z += a1.z + a2.z + a3.z; a0.w += a1.w + a2.w + a3.w;
    if (do_sig) { a0.x = sigf(a0.x); a0.y = sigf(a0.y); a0.z = sigf(a0.z); a0.w = sigf(a0.w); }
    *(float4*)(out + (size_t)r * 128 + lane * 4) = a0;
}

// ---------------- scoring ----------------
__global__ void __launch_bounds__(256)
k_score(const int* __restrict__ gid, const int* __restrict__ iid,
        const float* __restrict__ FG, const float* __restrict__ FI, const float* __restrict__ AN,
        float* __restrict__ out, int B)
{
    int widx = (blockIdx.x * blockDim.x + threadIdx.x) >> 5;
    int lane = threadIdx.x & 31;
    if (widx >= B) return;
    int g = gid[widx], it = iid[widx];
    const int c = lane * 4;
    float4 ge = *(const float4*)(FG + (size_t)g  * 128 + c);
    float4 ie = *(const float4*)(FI + (size_t)it * 128 + c);
    float4 ne = *(const float4*)(AN + (size_t)g  * 128 + c);
    float d1 = ge.x*ie.x + ge.y*ie.y + ge.z*ie.z + ge.w*ie.w;
    float d2 = ne.x*(ge.x+ie.x) + ne.y*(ge.y+ie.y) + ne.z*(ge.z+ie.z) + ne.w*(ge.w+ie.w);
    d1 = wredsum(d1); d2 = wredsum(d2);
    if (lane == 0) { out[widx] = d1; out[B + widx] = d2; }
}

// ---------------- launch ----------------
extern "C" void kernel_launch(void* const* d_in, const int* in_sizes, int n_in,
                              void* d_out, int out_size)
{
    const int*   group_ids   = (const int*)d_in[0];
    const int*   item_ids    = (const int*)d_in[1];
    const int*   gi_rows     = (const int*)d_in[2];
    const int*   gi_cols     = (const int*)d_in[3];
    const float* gi_vals     = (const float*)d_in[4];
    const int*   gg_rows     = (const int*)d_in[5];
    const int*   gg_cols     = (const int*)d_in[6];
    const float* gg_vals     = (const float*)d_in[7];
    const float* g_feat      = (const float*)d_in[8];
    const float* i_feat      = (const float*)d_in[9];
    const float* emb_group   = (const float*)d_in[10];
    const float* emb_item    = (const float*)d_in[11];
    const float* W_w         = (const float*)d_in[12];
    const float* W_b         = (const float*)d_in[13];
    const float* red_w       = (const float*)d_in[14];
    const float* red_b       = (const float*)d_in[15];
    const float* item_fus_w  = (const float*)d_in[16];
    const float* item_fus_b  = (const float*)d_in[17];
    const float* group_fus_w = (const float*)d_in[18];
    const float* group_fus_b = (const float*)d_in[19];
    float* out = (float*)d_out;

    int B   = in_sizes[0];
    int Egi = in_sizes[2];
    int Egg = in_sizes[5];
    int NG  = in_sizes[8] / 128;  if (NG > NG_CAP) NG = NG_CAP;
    int NI  = in_sizes[9] / 128;  if (NI > NI_CAP) NI = NI_CAP;

    float *p_fi, *p_gfi, *p_first, *p_fgrp, *p_an;
    __nv_bfloat16 *pb_tmp2, *pb_fi, *pb_fg, *pb_first, *pb_fgrp, *pb_embi, *pb_embg;
    int *p_rp_gi, *p_rp_gg;
    cudaGetSymbolAddress((void**)&p_fi,     g_fi);
    cudaGetSymbolAddress((void**)&p_gfi,    g_gfi);
    cudaGetSymbolAddress((void**)&p_first,  g_first);
    cudaGetSymbolAddress((void**)&p_fgrp,   g_fgrp);
    cudaGetSymbolAddress((void**)&p_an,     g_an);
    cudaGetSymbolAddress((void**)&pb_tmp2,  b_tmp2);
    cudaGetSymbolAddress((void**)&pb_fi,    b_fi);
    cudaGetSymbolAddress((void**)&pb_fg,    b_fg);
    cudaGetSymbolAddress((void**)&pb_first, b_first);
    cudaGetSymbolAddress((void**)&pb_fgrp,  b_fgrp);
    cudaGetSymbolAddress((void**)&pb_embi,  b_embi);
    cudaGetSymbolAddress((void**)&pb_embg,  b_embg);
    cudaGetSymbolAddress((void**)&p_rp_gi,  g_rp_gi);
    cudaGetSymbolAddress((void**)&p_rp_gg,  g_rp_gg);

    size_t smemN = (size_t)(128 * RS1 + 128 * RS1) * 4 + 512;          // ~68.5 KB
    size_t smemF = (size_t)(128 * RS2 + 64 * RS2) * 4 + 256;           // ~99.3 KB
    cudaFuncSetAttribute(k_nln,    cudaFuncAttributeMaxDynamicSharedMemorySize, (int)smemN);
    cudaFuncSetAttribute(k_fus,    cudaFuncAttributeMaxDynamicSharedMemorySize, (int)smemF);
    cudaFuncSetAttribute(k_social, cudaFuncAttributeMaxDynamicSharedMemorySize, (int)smemN);

    const int PGRID = 296;  // 2 blocks/SM x 148

    k_rowptr<<<1024, 256>>>(gi_rows, Egi, NG, p_rp_gi);
    k_rowptr<<<1024, 256>>>(gg_rows, Egg, NG, p_rp_gg);

    // pre-convert embeddings to bf16
    k_cvt<<<(NI * 64 + 255) / 256, 256>>>(emb_item,  pb_embi, NI * 64);
    k_cvt<<<(NG * 64 + 255) / 256, 256>>>(emb_group, pb_embg, NG * 64);

    // item path
    k_nln<<<PGRID, 256, smemN>>>(i_feat, red_w, red_b, pb_tmp2, NI);
    k_fus<<<PGRID, 256, smemF>>>(pb_embi, pb_tmp2, item_fus_w, item_fus_b, p_fi, pb_fi, NI);

    // group path
    k_nln<<<PGRID, 256, smemN>>>(g_feat, red_w, red_b, pb_tmp2, NG);
    k_fus<<<PGRID, 256, smemF>>>(pb_embg, pb_tmp2, group_fus_w, group_fus_b, nullptr, pb_fg, NG);

    // g_from_items = sigmoid(spmm(gi, final_item))
    k_spmm<<<(NG + 15) / 16, 512>>>(p_rp_gi, gi_cols, gi_vals, pb_fi, p_gfi, NG, 1);

    // social layer 1: first
    k_social<<<PGRID, 256, smemN>>>(p_rp_gg, gg_cols, gg_vals, pb_fg, W_w, W_b,
                                    p_first, pb_first, nullptr, nullptr, NG);
    // social layer 2 fused with final_group combine
    k_social<<<PGRID, 256, smemN>>>(p_rp_gg, gg_cols, gg_vals, pb_first, W_w, W_b,
                                    p_fgrp, pb_fgrp, p_gfi, p_first, NG);

    // all_neighbors = spmm(gg, final_group)
    k_spmm<<<(NG + 15) / 16, 512>>>(p_rp_gg, gg_cols, gg_vals, pb_fgrp, p_an, NG, 0);

    // scoring
    k_score<<<(B * 32 + 255) / 256, 256>>>(group_ids, item_ids, p_fgrp, p_fi, p_an, out, B);
}

// round 6
// speedup vs baseline: 1.9786x; 1.0464x over previous
#include <cuda_runtime.h>
#include <cuda_bf16.h>
#include <cstdio>

#define FULLMASK 0xffffffffu
#define NG_CAP 50000
#define NI_CAP 100000
#define RS1 68     // smem row stride (u32 words) K=128 tiles
#define RS2 132    // smem row stride (u32 words) K=256 tiles

// ---------------- scratch (device globals) ----------------
__device__ float g_fi   [NI_CAP * 128];   // final_item f32 (scoring)
__device__ float g_gfi  [NG_CAP * 128];
__device__ float g_first[NG_CAP * 128];
__device__ float g_fgrp [NG_CAP * 128];
__device__ __nv_bfloat16 b_t2i  [NI_CAP * 128]; // i2
__device__ __nv_bfloat16 b_t2g  [NG_CAP * 128]; // g2
__device__ __nv_bfloat16 b_fi   [NI_CAP * 128]; // final_item (gather)
__device__ __nv_bfloat16 b_fg   [NG_CAP * 128]; // fus_group (gather)
__device__ __nv_bfloat16 b_first[NG_CAP * 128]; // first (gather)
__device__ __nv_bfloat16 b_fgrp [NG_CAP * 128]; // final_group (gather)
__device__ int g_rp_gi[NG_CAP + 1];
__device__ int g_rp_gg[NG_CAP + 1];

// ---------------- helpers ----------------
__device__ __forceinline__ float wredsum(float v) {
    #pragma unroll
    for (int o = 16; o; o >>= 1) v += __shfl_xor_sync(FULLMASK, v, o);
    return v;
}
__device__ __forceinline__ float sigf(float x) { return 1.0f / (1.0f + __expf(-x)); }
__device__ __forceinline__ void fma4(float4& a, const float4 w, const float x) {
    a.x = fmaf(w.x, x, a.x); a.y = fmaf(w.y, x, a.y);
    a.z = fmaf(w.z, x, a.z); a.w = fmaf(w.w, x, a.w);
}
__device__ __forceinline__ float4 inorm4(float4 v) {
    float s = v.x + v.y + v.z + v.w;
    float q = v.x*v.x + v.y*v.y + v.z*v.z + v.w*v.w;
    #pragma unroll
    for (int o = 16; o; o >>= 1) {
        s += __shfl_xor_sync(FULLMASK, s, o);
        q += __shfl_xor_sync(FULLMASK, q, o);
    }
    float m = s * (1.0f / 128.0f);
    float var = q * (1.0f / 128.0f) - m * m;
    float inv = rsqrtf(var + 1e-5f);
    return make_float4((v.x-m)*inv, (v.y-m)*inv, (v.z-m)*inv, (v.w-m)*inv);
}
__device__ __forceinline__ unsigned packbf(float lo, float hi) {
    __nv_bfloat162 h = __floats2bfloat162_rn(lo, hi);
    return *reinterpret_cast<unsigned*>(&h);
}
__device__ __forceinline__ float2 unpk(unsigned u) {
    __nv_bfloat162 h = *reinterpret_cast<__nv_bfloat162*>(&u);
    return __bfloat1622float2(h);
}
__device__ __forceinline__ float4 ld4bf(const __nv_bfloat16* p, int lane) {
    uint2 u = ((const uint2*)p)[lane];
    float2 a = unpk(u.x), b = unpk(u.y);
    return make_float4(a.x, a.y, b.x, b.y);
}
__device__ __forceinline__ unsigned smaddr(const void* p) {
    unsigned a;
    asm("{ .reg .u64 t; cvta.to.shared.u64 t, %1; cvt.u32.u64 %0, t; }" : "=r"(a) : "l"(p));
    return a;
}
__device__ __forceinline__ void ldsm4(unsigned* r, unsigned addr) {
    asm volatile("ldmatrix.sync.aligned.m8n8.x4.shared.b16 {%0,%1,%2,%3}, [%4];"
        : "=r"(r[0]), "=r"(r[1]), "=r"(r[2]), "=r"(r[3]) : "r"(addr));
}
__device__ __forceinline__ void mma16(float* d, const unsigned* a, unsigned b0, unsigned b1) {
    asm volatile("mma.sync.aligned.m16n8k16.row.col.f32.bf16.bf16.f32 "
        "{%0,%1,%2,%3}, {%4,%5,%6,%7}, {%8,%9}, {%0,%1,%2,%3};"
        : "+f"(d[0]), "+f"(d[1]), "+f"(d[2]), "+f"(d[3])
        : "r"(a[0]), "r"(a[1]), "r"(a[2]), "r"(a[3]), "r"(b0), "r"(b1));
}
template<int RS>
__device__ __forceinline__ void mma_m32n64(float (&d)[2][8][4], unsigned aBase, unsigned bBase, int ks) {
    const unsigned kb = ks * 32;
    unsigned a0[4], a1[4];
    ldsm4(a0, aBase + kb);
    ldsm4(a1, aBase + 16*RS*4 + kb);
    #pragma unroll
    for (int q = 0; q < 4; q++) {
        unsigned b[4];
        ldsm4(b, bBase + q*16*RS*4 + kb);
        mma16(d[0][2*q],   a0, b[0], b[1]);
        mma16(d[1][2*q],   a1, b[0], b[1]);
        mma16(d[0][2*q+1], a0, b[2], b[3]);
        mma16(d[1][2*q+1], a1, b[2], b[3]);
    }
}
template<int RS>
__device__ __forceinline__ void mma_m32n32(float (&d)[2][4][4], unsigned aBase, unsigned bBase, int ks) {
    const unsigned kb = ks * 32;
    unsigned a0[4], a1[4];
    ldsm4(a0, aBase + kb);
    ldsm4(a1, aBase + 16*RS*4 + kb);
    #pragma unroll
    for (int q = 0; q < 2; q++) {
        unsigned b[4];
        ldsm4(b, bBase + q*16*RS*4 + kb);
        mma16(d[0][2*q],   a0, b[0], b[1]);
        mma16(d[1][2*q],   a1, b[0], b[1]);
        mma16(d[0][2*q+1], a0, b[2], b[3]);
        mma16(d[1][2*q+1], a1, b[2], b[3]);
    }
}
// warp-level spmm of one row (bf16 gather, f32 accum)
__device__ __forceinline__ float4 spmm_row(const int* __restrict__ rp, const int* __restrict__ cols,
                                           const float* __restrict__ vals,
                                           const __nv_bfloat16* __restrict__ Xb, int r, int lane)
{
    float4 a0 = make_float4(0.f,0.f,0.f,0.f), a1 = a0, a2 = a0, a3 = a0;
    int s = rp[r], e = rp[r + 1], ed = s;
    for (; ed + 3 < e; ed += 4) {
        int c0 = cols[ed], c1 = cols[ed+1], c2 = cols[ed+2], c3 = cols[ed+3];
        float v0 = vals[ed], v1 = vals[ed+1], v2 = vals[ed+2], v3 = vals[ed+3];
        fma4(a0, ld4bf(Xb + (size_t)c0 * 128, lane), v0);
        fma4(a1, ld4bf(Xb + (size_t)c1 * 128, lane), v1);
        fma4(a2, ld4bf(Xb + (size_t)c2 * 128, lane), v2);
        fma4(a3, ld4bf(Xb + (size_t)c3 * 128, lane), v3);
    }
    for (; ed < e; ed++)
        fma4(a0, ld4bf(Xb + (size_t)cols[ed] * 128, lane), vals[ed]);
    a0.x += a1.x + a2.x + a3.x; a0.y += a1.y + a2.y + a3.y;
    a0.z += a1.z + a2.z + a3.z; a0.w += a1.w + a2.w + a3.w;
    return a0;
}

// ---------------- row_ptr from sorted COO rows ----------------
__global__ void k_rowptr(const int* __restrict__ rows, int E, int N, int* __restrict__ rp) {
    for (int e = blockIdx.x * blockDim.x + threadIdx.x; e < E; e += gridDim.x * blockDim.x) {
        int r = rows[e];
        int prev = (e == 0) ? -1 : rows[e - 1];
        for (int rr = prev + 1; rr <= r; rr++) rp[rr] = e;
        if (e == E - 1) for (int rr = r + 1; rr <= N; rr++) rp[rr] = E;
    }
}

// ======== merged: out = inorm(inorm(X)@W^T+b) for BOTH item and group matrices ========
__global__ void __launch_bounds__(256, 2)
k_nln(const float* __restrict__ X1, int N1, const float* __restrict__ X2, int N2,
      const float* __restrict__ W, const float* __restrict__ Bv,
      __nv_bfloat16* __restrict__ out1, __nv_bfloat16* __restrict__ out2)
{
    extern __shared__ __align__(16) unsigned smu[];
    unsigned* Asu = smu;
    unsigned* Wsu = Asu + 128 * RS1;
    float*    biasf = (float*)(Wsu + 128 * RS1);
    const int tid = threadIdx.x, lane = tid & 31, w = tid >> 5;
    const int qr = lane >> 2, qc = lane & 3;
    const int mbase = (w >> 1) * 32, nbase = (w & 1) * 64;

    for (int i = tid; i < 128 * 64; i += 256) {
        float2 wv = ((const float2*)W)[i];
        Wsu[(i >> 6) * RS1 + (i & 63)] = packbf(wv.x, wv.y);
    }
    if (tid < 128) biasf[tid] = Bv[tid];

    const unsigned aBase = smaddr(Asu) + (((mbase + (lane & 15)) * RS1 + ((lane >> 4) << 2)) << 2);
    const unsigned bBase = smaddr(Wsu) + (((nbase + ((lane >> 4) << 3) + (lane & 7)) * RS1 + (((lane >> 3) & 1) << 2)) << 2);

    const int T1 = (N1 + 127) >> 7, T2 = (N2 + 127) >> 7;
    for (int tt = blockIdx.x; tt < T1 + T2; tt += gridDim.x) {
        const bool seg1 = tt < T1;
        const float* X = seg1 ? X1 : X2;
        __nv_bfloat16* outb = seg1 ? out1 : out2;
        const int N = seg1 ? N1 : N2;
        const int tile = seg1 ? tt : tt - T1;
        __syncthreads();
        #pragma unroll 4
        for (int i = 0; i < 16; i++) {
            int rl = w * 16 + i, r = tile * 128 + rl;
            float4 v = make_float4(0.f, 0.f, 0.f, 0.f);
            if (r < N) { v = *(const float4*)(X + (size_t)r * 128 + lane * 4); v = inorm4(v); }
            uint2 st; st.x = packbf(v.x, v.y); st.y = packbf(v.z, v.w);
            *(uint2*)(Asu + rl * RS1 + lane * 2) = st;
        }
        __syncthreads();
        float d[2][8][4];
        #pragma unroll
        for (int t = 0; t < 2; t++)
            #pragma unroll
            for (int nt = 0; nt < 8; nt++)
                #pragma unroll
                for (int j = 0; j < 4; j++) d[t][nt][j] = 0.f;
        #pragma unroll
        for (int ks = 0; ks < 8; ks++) mma_m32n64<RS1>(d, aBase, bBase, ks);
        __syncthreads();
        #pragma unroll
        for (int t = 0; t < 2; t++)
            #pragma unroll
            for (int nt = 0; nt < 8; nt++) {
                int col = nbase + nt * 8 + qc * 2;
                float b0 = biasf[col], b1 = biasf[col + 1];
                int row0 = mbase + t * 16 + qr;
                int wj = (nbase >> 1) + nt * 4 + qc;
                Asu[row0 * RS1 + wj]       = packbf(d[t][nt][0] + b0, d[t][nt][1] + b1);
                Asu[(row0 + 8) * RS1 + wj] = packbf(d[t][nt][2] + b0, d[t][nt][3] + b1);
            }
        __syncthreads();
        #pragma unroll 4
        for (int i = 0; i < 16; i++) {
            int rl = w * 16 + i, r = tile * 128 + rl;
            if (r < N) {
                uint2 u = *(const uint2*)(Asu + rl * RS1 + lane * 2);
                float2 la = unpk(u.x), lb = unpk(u.y);
                float4 o = inorm4(make_float4(la.x, la.y, lb.x, lb.y));
                uint2 st; st.x = packbf(o.x, o.y); st.y = packbf(o.z, o.w);
                *(uint2*)(outb + (size_t)r * 128 + lane * 4) = st;
            }
        }
    }
}

// ==== merged fus (item + group segments): out = sigmoid([EMB_f32, X2_bf16] @ W^T + b) ====
// blocks [0,SPLIT): item; [SPLIT,grid): group. Each block owns one N64 half (localBid&1).
__global__ void __launch_bounds__(256, 2)
k_fus(const float* __restrict__ EMB1, const __nv_bfloat16* __restrict__ X21,
      const float* __restrict__ W1, const float* __restrict__ B1,
      float* __restrict__ fout1, __nv_bfloat16* __restrict__ bout1, int N1,
      const float* __restrict__ EMB2, const __nv_bfloat16* __restrict__ X22,
      const float* __restrict__ W2, const float* __restrict__ B2,
      float* __restrict__ fout2, __nv_bfloat16* __restrict__ bout2, int N2,
      int SPLIT)
{
    extern __shared__ __align__(16) unsigned smu[];
    unsigned* Asu = smu;                // 128*RS2
    unsigned* Wsu = Asu + 128 * RS2;    // 64*RS2
    float*    biasf = (float*)(Wsu + 64 * RS2);
    const int tid = threadIdx.x, lane = tid & 31, w = tid >> 5;
    const int qr = lane >> 2, qc = lane & 3;

    const bool seg1 = (int)blockIdx.x < SPLIT;
    const int localBid = seg1 ? blockIdx.x : blockIdx.x - SPLIT;
    const int nb       = seg1 ? SPLIT : gridDim.x - SPLIT;
    const float* EMB = seg1 ? EMB1 : EMB2;
    const __nv_bfloat16* X2 = seg1 ? X21 : X22;
    const float* W  = seg1 ? W1 : W2;
    const float* Bv = seg1 ? B1 : B2;
    float* fout = seg1 ? fout1 : fout2;
    __nv_bfloat16* bout = seg1 ? bout1 : bout2;
    const int N = seg1 ? N1 : N2;

    const int half = localBid & 1;
    const int mbase = (w >> 1) * 32, nloc = (w & 1) * 32;

    for (int i = tid; i < 64 * 128; i += 256) {
        int n = i >> 7, j = i & 127;
        float2 wv = ((const float2*)W)[(size_t)(half * 64 + n) * 128 + j];
        Wsu[n * RS2 + j] = packbf(wv.x, wv.y);
    }
    if (tid < 64) biasf[tid] = Bv[half * 64 + tid];

    const unsigned aBase = smaddr(Asu) + (((mbase + (lane & 15)) * RS2 + ((lane >> 4) << 2)) << 2);
    const unsigned bBase = smaddr(Wsu) + (((nloc + ((lane >> 4) << 3) + (lane & 7)) * RS2 + (((lane >> 3) & 1) << 2)) << 2);

    const int ntiles = (N + 127) >> 7;
    for (int tile = localBid >> 1; tile < ntiles; tile += nb >> 1) {
        __syncthreads();
        #pragma unroll 4
        for (int i = 0; i < 16; i++) {
            int rl = w * 16 + i, r = tile * 128 + rl;
            float4 ve = make_float4(0.f,0.f,0.f,0.f);
            uint2 ux = make_uint2(0u, 0u);
            if (r < N) {
                ve = *(const float4*)(EMB + (size_t)r * 128 + lane * 4);
                ux = ((const uint2*)(X2 + (size_t)r * 128))[lane];
            }
            unsigned* rowp = Asu + rl * RS2;
            uint2 st; st.x = packbf(ve.x, ve.y); st.y = packbf(ve.z, ve.w);
            *(uint2*)(rowp + lane * 2)      = st;
            *(uint2*)(rowp + 64 + lane * 2) = ux;
        }
        __syncthreads();
        float d[2][4][4];
        #pragma unroll
        for (int t = 0; t < 2; t++)
            #pragma unroll
            for (int nt = 0; nt < 4; nt++)
                #pragma unroll
                for (int j = 0; j < 4; j++) d[t][nt][j] = 0.f;
        #pragma unroll
        for (int ks = 0; ks < 16; ks++) mma_m32n32<RS2>(d, aBase, bBase, ks);
        #pragma unroll
        for (int t = 0; t < 2; t++)
            #pragma unroll
            for (int nt = 0; nt < 4; nt++) {
                int lcol = nloc + nt * 8 + qc * 2;
                int gcol = half * 64 + lcol;
                float b0 = biasf[lcol], b1 = biasf[lcol + 1];
                #pragma unroll
                for (int h = 0; h < 2; h++) {
                    int r = tile * 128 + mbase + t * 16 + qr + h * 8;
                    if (r < N) {
                        float s0 = sigf(d[t][nt][2*h]   + b0);
                        float s1 = sigf(d[t][nt][2*h+1] + b1);
                        if (fout) *(float2*)(fout + (size_t)r * 128 + gcol) = make_float2(s0, s1);
                        *(unsigned*)(bout + (size_t)r * 128 + gcol) = packbf(s0, s1);
                    }
                }
            }
    }
}

// ==== social layer (+ optional fused combine) + optional tail spmm_gi work ====
__global__ void __launch_bounds__(256, 2)
k_social(const int* __restrict__ rp, const int* __restrict__ cols, const float* __restrict__ vals,
         const __nv_bfloat16* __restrict__ Xb, const float* __restrict__ W, const float* __restrict__ Bv,
         float* __restrict__ fout, __nv_bfloat16* __restrict__ bout,
         const float* __restrict__ addA, const float* __restrict__ addB, int N,
         const int* __restrict__ t_rp, const int* __restrict__ t_cols, const float* __restrict__ t_vals,
         const __nv_bfloat16* __restrict__ t_X, float* __restrict__ t_out, int t_N)
{
    extern __shared__ __align__(16) unsigned smu[];
    unsigned* Asu = smu;
    unsigned* Wsu = Asu + 128 * RS1;
    float*    biasf = (float*)(Wsu + 128 * RS1);
    const int tid = threadIdx.x, lane = tid & 31, w = tid >> 5;
    const int qr = lane >> 2, qc = lane & 3;
    const int mbase = (w >> 1) * 32, nbase = (w & 1) * 64;

    for (int i = tid; i < 128 * 64; i += 256) {
        float2 wv = ((const float2*)W)[i];
        Wsu[(i >> 6) * RS1 + (i & 63)] = packbf(wv.x, wv.y);
    }
    if (tid < 128) biasf[tid] = Bv[tid];

    const unsigned aBase = smaddr(Asu) + (((mbase + (lane & 15)) * RS1 + ((lane >> 4) << 2)) << 2);
    const unsigned bBase = smaddr(Wsu) + (((nbase + ((lane >> 4) << 3) + (lane & 7)) * RS1 + (((lane >> 3) & 1) << 2)) << 2);

    int ntiles = (N + 127) >> 7;
    for (int tile = blockIdx.x; tile < ntiles; tile += gridDim.x) {
        __syncthreads();
        for (int i = 0; i < 16; i++) {
            int rl = w * 16 + i, r = tile * 128 + rl;
            float4 a0 = make_float4(0.f,0.f,0.f,0.f);
            if (r < N) a0 = spmm_row(rp, cols, vals, Xb, r, lane);
            uint2 st; st.x = packbf(a0.x, a0.y); st.y = packbf(a0.z, a0.w);
            *(uint2*)(Asu + rl * RS1 + lane * 2) = st;
        }
        __syncthreads();
        float d[2][8][4];
        #pragma unroll
        for (int t = 0; t < 2; t++)
            #pragma unroll
            for (int nt = 0; nt < 8; nt++)
                #pragma unroll
                for (int j = 0; j < 4; j++) d[t][nt][j] = 0.f;
        #pragma unroll
        for (int ks = 0; ks < 8; ks++) mma_m32n64<RS1>(d, aBase, bBase, ks);
        #pragma unroll
        for (int t = 0; t < 2; t++)
            #pragma unroll
            for (int nt = 0; nt < 8; nt++) {
                int col = nbase + nt * 8 + qc * 2;
                float b0 = biasf[col], b1 = biasf[col + 1];
                #pragma unroll
                for (int h = 0; h < 2; h++) {
                    int r = tile * 128 + mbase + t * 16 + qr + h * 8;
                    if (r < N) {
                        float s0 = sigf(fmaxf(d[t][nt][2*h]   + b0, 0.f));
                        float s1 = sigf(fmaxf(d[t][nt][2*h+1] + b1, 0.f));
                        if (addA) {
                            float2 pa = *(const float2*)(addA + (size_t)r * 128 + col);
                            float2 pb = *(const float2*)(addB + (size_t)r * 128 + col);
                            s0 = sigf((s0 + pa.x + pb.x) * 0.5f);
                            s1 = sigf((s1 + pa.y + pb.y) * 0.5f);
                        }
                        *(float2*)(fout + (size_t)r * 128 + col) = make_float2(s0, s1);
                        if (bout) *(unsigned*)(bout + (size_t)r * 128 + col) = packbf(s0, s1);
                    }
                }
            }
    }
    // tail: independent spmm (g_from_items), sigmoid epilogue
    if (t_out) {
        for (int r = blockIdx.x * 8 + w; r < t_N; r += gridDim.x * 8) {
            float4 a0 = spmm_row(t_rp, t_cols, t_vals, t_X, r, lane);
            a0.x = sigf(a0.x); a0.y = sigf(a0.y); a0.z = sigf(a0.z); a0.w = sigf(a0.w);
            *(float4*)(t_out + (size_t)r * 128 + lane * 4) = a0;
        }
    }
}

// ---------------- scoring with fused all_neighbors spmm ----------------
__global__ void __launch_bounds__(256)
k_score(const int* __restrict__ gid, const int* __restrict__ iid,
        const float* __restrict__ FG, const float* __restrict__ FI,
        const int* __restrict__ rp, const int* __restrict__ cols, const float* __restrict__ vals,
        const __nv_bfloat16* __restrict__ FGb,
        float* __restrict__ out, int B)
{
    int widx = (blockIdx.x * blockDim.x + threadIdx.x) >> 5;
    int lane = threadIdx.x & 31;
    if (widx >= B) return;
    int g = gid[widx], it = iid[widx];
    const int c = lane * 4;
    float4 ge = *(const float4*)(FG + (size_t)g  * 128 + c);
    float4 ie = *(const float4*)(FI + (size_t)it * 128 + c);
    float4 ne = spmm_row(rp, cols, vals, FGb, g, lane);  // all_neighbors[g]
    float d1 = ge.x*ie.x + ge.y*ie.y + ge.z*ie.z + ge.w*ie.w;
    float d2 = ne.x*(ge.x+ie.x) + ne.y*(ge.y+ie.y) + ne.z*(ge.z+ie.z) + ne.w*(ge.w+ie.w);
    d1 = wredsum(d1); d2 = wredsum(d2);
    if (lane == 0) { out[widx] = d1; out[B + widx] = d2; }
}

// ---------------- launch ----------------
extern "C" void kernel_launch(void* const* d_in, const int* in_sizes, int n_in,
                              void* d_out, int out_size)
{
    const int*   group_ids   = (const int*)d_in[0];
    const int*   item_ids    = (const int*)d_in[1];
    const int*   gi_rows     = (const int*)d_in[2];
    const int*   gi_cols     = (const int*)d_in[3];
    const float* gi_vals     = (const float*)d_in[4];
    const int*   gg_rows     = (const int*)d_in[5];
    const int*   gg_cols     = (const int*)d_in[6];
    const float* gg_vals     = (const float*)d_in[7];
    const float* g_feat      = (const float*)d_in[8];
    const float* i_feat      = (const float*)d_in[9];
    const float* emb_group   = (const float*)d_in[10];
    const float* emb_item    = (const float*)d_in[11];
    const float* W_w         = (const float*)d_in[12];
    const float* W_b         = (const float*)d_in[13];
    const float* red_w       = (const float*)d_in[14];
    const float* red_b       = (const float*)d_in[15];
    const float* item_fus_w  = (const float*)d_in[16];
    const float* item_fus_b  = (const float*)d_in[17];
    const float* group_fus_w = (const float*)d_in[18];
    const float* group_fus_b = (const float*)d_in[19];
    float* out = (float*)d_out;

    int B   = in_sizes[0];
    int Egi = in_sizes[2];
    int Egg = in_sizes[5];
    int NG  = in_sizes[8] / 128;  if (NG > NG_CAP) NG = NG_CAP;
    int NI  = in_sizes[9] / 128;  if (NI > NI_CAP) NI = NI_CAP;

    float *p_fi, *p_gfi, *p_first, *p_fgrp;
    __nv_bfloat16 *pb_t2i, *pb_t2g, *pb_fi, *pb_fg, *pb_first, *pb_fgrp;
    int *p_rp_gi, *p_rp_gg;
    cudaGetSymbolAddress((void**)&p_fi,     g_fi);
    cudaGetSymbolAddress((void**)&p_gfi,    g_gfi);
    cudaGetSymbolAddress((void**)&p_first,  g_first);
    cudaGetSymbolAddress((void**)&p_fgrp,   g_fgrp);
    cudaGetSymbolAddress((void**)&pb_t2i,   b_t2i);
    cudaGetSymbolAddress((void**)&pb_t2g,   b_t2g);
    cudaGetSymbolAddress((void**)&pb_fi,    b_fi);
    cudaGetSymbolAddress((void**)&pb_fg,    b_fg);
    cudaGetSymbolAddress((void**)&pb_first, b_first);
    cudaGetSymbolAddress((void**)&pb_fgrp,  b_fgrp);
    cudaGetSymbolAddress((void**)&p_rp_gi,  g_rp_gi);
    cudaGetSymbolAddress((void**)&p_rp_gg,  g_rp_gg);

    size_t smemN = (size_t)(128 * RS1 + 128 * RS1) * 4 + 512;   // ~68.5 KB
    size_t smemF = (size_t)(128 * RS2 + 64 * RS2) * 4 + 256;    // ~99.3 KB
    cudaFuncSetAttribute(k_nln,    cudaFuncAttributeMaxDynamicSharedMemorySize, (int)smemN);
    cudaFuncSetAttribute(k_fus,    cudaFuncAttributeMaxDynamicSharedMemorySize, (int)smemF);
    cudaFuncSetAttribute(k_social, cudaFuncAttributeMaxDynamicSharedMemorySize, (int)smemN);

    const int PGRID = 296;   // 2 blocks/SM
    const int SPLIT = 200;   // k_fus: item blocks (even), group gets 96 (even)

    k_rowptr<<<1024, 256>>>(gi_rows, Egi, NG, p_rp_gi);
    k_rowptr<<<1024, 256>>>(gg_rows, Egg, NG, p_rp_gg);

    // merged nln: i2 and g2 in one launch (same weights)
    k_nln<<<PGRID, 256, smemN>>>(i_feat, NI, g_feat, NG, red_w, red_b, pb_t2i, pb_t2g);

    // merged fus: final_item (f32+bf16) and fus_group (bf16) in one launch
    k_fus<<<PGRID, 256, smemF>>>(emb_item,  pb_t2i, item_fus_w,  item_fus_b,  p_fi,    pb_fi, NI,
                                 emb_group, pb_t2g, group_fus_w, group_fus_b, nullptr, pb_fg, NG,
                                 SPLIT);

    // social layer 1 + tail spmm_gi (g_from_items)
    k_social<<<PGRID, 256, smemN>>>(p_rp_gg, gg_cols, gg_vals, pb_fg, W_w, W_b,
                                    p_first, pb_first, nullptr, nullptr, NG,
                                    p_rp_gi, gi_cols, gi_vals, pb_fi, p_gfi, NG);

    // social layer 2 fused with final_group combine
    k_social<<<PGRID, 256, smemN>>>(p_rp_gg, gg_cols, gg_vals, pb_first, W_w, W_b,
                                    p_fgrp, pb_fgrp, p_gfi, p_first, NG,
                                    nullptr, nullptr, nullptr, nullptr, nullptr, 0);

    // scoring with fused all_neighbors spmm
    k_score<<<(B + 7) / 8, 256>>>(group_ids, item_ids, p_fgrp, p_fi,
                                  p_rp_gg, gg_cols, gg_vals, pb_fgrp, out, B);
}

// round 7
// speedup vs baseline: 1.9927x; 1.0071x over previous
#include <cuda_runtime.h>
#include <cuda_bf16.h>
#include <cstdio>

#define FULLMASK 0xffffffffu
#define NG_CAP 50000
#define NI_CAP 100000
#define RS1 68     // smem row stride (u32 words) K=128 tiles
#define RS2 132    // smem row stride (u32 words) K=256 tiles

// ---------------- scratch (device globals) ----------------
__device__ float g_fi   [NI_CAP * 128];   // final_item f32 (scoring)
__device__ float g_gfi  [NG_CAP * 128];
__device__ float g_first[NG_CAP * 128];
__device__ float g_fgrp [NG_CAP * 128];
__device__ __nv_bfloat16 b_t2i  [NI_CAP * 128]; // i2
__device__ __nv_bfloat16 b_t2g  [NG_CAP * 128]; // g2
__device__ __nv_bfloat16 b_fi   [NI_CAP * 128]; // final_item (gather)
__device__ __nv_bfloat16 b_fg   [NG_CAP * 128]; // fus_group (gather)
__device__ __nv_bfloat16 b_first[NG_CAP * 128]; // first (gather)
__device__ __nv_bfloat16 b_fgrp [NG_CAP * 128]; // final_group (gather)
__device__ int g_rp_gi[NG_CAP + 1];
__device__ int g_rp_gg[NG_CAP + 1];

// ---------------- helpers ----------------
__device__ __forceinline__ float wredsum(float v) {
    #pragma unroll
    for (int o = 16; o; o >>= 1) v += __shfl_xor_sync(FULLMASK, v, o);
    return v;
}
__device__ __forceinline__ float sigf(float x) { return 1.0f / (1.0f + __expf(-x)); }
__device__ __forceinline__ void fma4(float4& a, const float4 w, const float x) {
    a.x = fmaf(w.x, x, a.x); a.y = fmaf(w.y, x, a.y);
    a.z = fmaf(w.z, x, a.z); a.w = fmaf(w.w, x, a.w);
}
__device__ __forceinline__ float4 inorm4(float4 v) {
    float s = v.x + v.y + v.z + v.w;
    float q = v.x*v.x + v.y*v.y + v.z*v.z + v.w*v.w;
    #pragma unroll
    for (int o = 16; o; o >>= 1) {
        s += __shfl_xor_sync(FULLMASK, s, o);
        q += __shfl_xor_sync(FULLMASK, q, o);
    }
    float m = s * (1.0f / 128.0f);
    float var = q * (1.0f / 128.0f) - m * m;
    float inv = rsqrtf(var + 1e-5f);
    return make_float4((v.x-m)*inv, (v.y-m)*inv, (v.z-m)*inv, (v.w-m)*inv);
}
__device__ __forceinline__ unsigned packbf(float lo, float hi) {
    __nv_bfloat162 h = __floats2bfloat162_rn(lo, hi);
    return *reinterpret_cast<unsigned*>(&h);
}
__device__ __forceinline__ float2 unpk(unsigned u) {
    __nv_bfloat162 h = *reinterpret_cast<__nv_bfloat162*>(&u);
    return __bfloat1622float2(h);
}
__device__ __forceinline__ float4 ld4bf(const __nv_bfloat16* p, int lane) {
    uint2 u = ((const uint2*)p)[lane];
    float2 a = unpk(u.x), b = unpk(u.y);
    return make_float4(a.x, a.y, b.x, b.y);
}
__device__ __forceinline__ unsigned smaddr(const void* p) {
    unsigned a;
    asm("{ .reg .u64 t; cvta.to.shared.u64 t, %1; cvt.u32.u64 %0, t; }" : "=r"(a) : "l"(p));
    return a;
}
__device__ __forceinline__ void ldsm4(unsigned* r, unsigned addr) {
    asm volatile("ldmatrix.sync.aligned.m8n8.x4.shared.b16 {%0,%1,%2,%3}, [%4];"
        : "=r"(r[0]), "=r"(r[1]), "=r"(r[2]), "=r"(r[3]) : "r"(addr));
}
__device__ __forceinline__ void mma16(float* d, const unsigned* a, unsigned b0, unsigned b1) {
    asm volatile("mma.sync.aligned.m16n8k16.row.col.f32.bf16.bf16.f32 "
        "{%0,%1,%2,%3}, {%4,%5,%6,%7}, {%8,%9}, {%0,%1,%2,%3};"
        : "+f"(d[0]), "+f"(d[1]), "+f"(d[2]), "+f"(d[3])
        : "r"(a[0]), "r"(a[1]), "r"(a[2]), "r"(a[3]), "r"(b0), "r"(b1));
}
template<int RS>
__device__ __forceinline__ void mma_m32n64(float (&d)[2][8][4], unsigned aBase, unsigned bBase, int ks) {
    const unsigned kb = ks * 32;
    unsigned a0[4], a1[4];
    ldsm4(a0, aBase + kb);
    ldsm4(a1, aBase + 16*RS*4 + kb);
    #pragma unroll
    for (int q = 0; q < 4; q++) {
        unsigned b[4];
        ldsm4(b, bBase + q*16*RS*4 + kb);
        mma16(d[0][2*q],   a0, b[0], b[1]);
        mma16(d[1][2*q],   a1, b[0], b[1]);
        mma16(d[0][2*q+1], a0, b[2], b[3]);
        mma16(d[1][2*q+1], a1, b[2], b[3]);
    }
}
template<int RS>
__device__ __forceinline__ void mma_m32n32(float (&d)[2][4][4], unsigned aBase, unsigned bBase, int ks) {
    const unsigned kb = ks * 32;
    unsigned a0[4], a1[4];
    ldsm4(a0, aBase + kb);
    ldsm4(a1, aBase + 16*RS*4 + kb);
    #pragma unroll
    for (int q = 0; q < 2; q++) {
        unsigned b[4];
        ldsm4(b, bBase + q*16*RS*4 + kb);
        mma16(d[0][2*q],   a0, b[0], b[1]);
        mma16(d[1][2*q],   a1, b[0], b[1]);
        mma16(d[0][2*q+1], a0, b[2], b[3]);
        mma16(d[1][2*q+1], a1, b[2], b[3]);
    }
}
// warp-level spmm of one row (bf16 gather, f32 accum)
__device__ __forceinline__ float4 spmm_row(const int* __restrict__ rp, const int* __restrict__ cols,
                                           const float* __restrict__ vals,
                                           const __nv_bfloat16* __restrict__ Xb, int r, int lane)
{
    float4 a0 = make_float4(0.f,0.f,0.f,0.f), a1 = a0, a2 = a0, a3 = a0;
    int s = rp[r], e = rp[r + 1], ed = s;
    for (; ed + 3 < e; ed += 4) {
        int c0 = cols[ed], c1 = cols[ed+1], c2 = cols[ed+2], c3 = cols[ed+3];
        float v0 = vals[ed], v1 = vals[ed+1], v2 = vals[ed+2], v3 = vals[ed+3];
        fma4(a0, ld4bf(Xb + (size_t)c0 * 128, lane), v0);
        fma4(a1, ld4bf(Xb + (size_t)c1 * 128, lane), v1);
        fma4(a2, ld4bf(Xb + (size_t)c2 * 128, lane), v2);
        fma4(a3, ld4bf(Xb + (size_t)c3 * 128, lane), v3);
    }
    for (; ed < e; ed++)
        fma4(a0, ld4bf(Xb + (size_t)cols[ed] * 128, lane), vals[ed]);
    a0.x += a1.x + a2.x + a3.x; a0.y += a1.y + a2.y + a3.y;
    a0.z += a1.z + a2.z + a3.z; a0.w += a1.w + a2.w + a3.w;
    return a0;
}

// ---------------- row_ptr from sorted COO rows ----------------
__global__ void k_rowptr(const int* __restrict__ rows, int E, int N, int* __restrict__ rp) {
    for (int e = blockIdx.x * blockDim.x + threadIdx.x; e < E; e += gridDim.x * blockDim.x) {
        int r = rows[e];
        int prev = (e == 0) ? -1 : rows[e - 1];
        for (int rr = prev + 1; rr <= r; rr++) rp[rr] = e;
        if (e == E - 1) for (int rr = r + 1; rr <= N; rr++) rp[rr] = E;
    }
}

// ======== merged: out = inorm(inorm(X)@W^T+b) for BOTH item and group matrices ========
__global__ void __launch_bounds__(256, 2)
k_nln(const float* __restrict__ X1, int N1, const float* __restrict__ X2, int N2,
      const float* __restrict__ W, const float* __restrict__ Bv,
      __nv_bfloat16* __restrict__ out1, __nv_bfloat16* __restrict__ out2)
{
    extern __shared__ __align__(16) unsigned smu[];
    unsigned* Asu = smu;
    unsigned* Wsu = Asu + 128 * RS1;
    float*    biasf = (float*)(Wsu + 128 * RS1);
    const int tid = threadIdx.x, lane = tid & 31, w = tid >> 5;
    const int qr = lane >> 2, qc = lane & 3;
    const int mbase = (w >> 1) * 32, nbase = (w & 1) * 64;

    for (int i = tid; i < 128 * 64; i += 256) {
        float2 wv = ((const float2*)W)[i];
        Wsu[(i >> 6) * RS1 + (i & 63)] = packbf(wv.x, wv.y);
    }
    if (tid < 128) biasf[tid] = Bv[tid];

    const unsigned aBase = smaddr(Asu) + (((mbase + (lane & 15)) * RS1 + ((lane >> 4) << 2)) << 2);
    const unsigned bBase = smaddr(Wsu) + (((nbase + ((lane >> 4) << 3) + (lane & 7)) * RS1 + (((lane >> 3) & 1) << 2)) << 2);

    const int T1 = (N1 + 127) >> 7, T2 = (N2 + 127) >> 7;
    for (int tt = blockIdx.x; tt < T1 + T2; tt += gridDim.x) {
        const bool seg1 = tt < T1;
        const float* X = seg1 ? X1 : X2;
        __nv_bfloat16* outb = seg1 ? out1 : out2;
        const int N = seg1 ? N1 : N2;
        const int tile = seg1 ? tt : tt - T1;
        __syncthreads();
        #pragma unroll 4
        for (int i = 0; i < 16; i++) {
            int rl = w * 16 + i, r = tile * 128 + rl;
            float4 v = make_float4(0.f, 0.f, 0.f, 0.f);
            if (r < N) { v = *(const float4*)(X + (size_t)r * 128 + lane * 4); v = inorm4(v); }
            uint2 st; st.x = packbf(v.x, v.y); st.y = packbf(v.z, v.w);
            *(uint2*)(Asu + rl * RS1 + lane * 2) = st;
        }
        __syncthreads();
        float d[2][8][4];
        #pragma unroll
        for (int t = 0; t < 2; t++)
            #pragma unroll
            for (int nt = 0; nt < 8; nt++)
                #pragma unroll
                for (int j = 0; j < 4; j++) d[t][nt][j] = 0.f;
        #pragma unroll
        for (int ks = 0; ks < 8; ks++) mma_m32n64<RS1>(d, aBase, bBase, ks);
        __syncthreads();
        #pragma unroll
        for (int t = 0; t < 2; t++)
            #pragma unroll
            for (int nt = 0; nt < 8; nt++) {
                int col = nbase + nt * 8 + qc * 2;
                float b0 = biasf[col], b1 = biasf[col + 1];
                int row0 = mbase + t * 16 + qr;
                int wj = (nbase >> 1) + nt * 4 + qc;
                Asu[row0 * RS1 + wj]       = packbf(d[t][nt][0] + b0, d[t][nt][1] + b1);
                Asu[(row0 + 8) * RS1 + wj] = packbf(d[t][nt][2] + b0, d[t][nt][3] + b1);
            }
        __syncthreads();
        #pragma unroll 4
        for (int i = 0; i < 16; i++) {
            int rl = w * 16 + i, r = tile * 128 + rl;
            if (r < N) {
                uint2 u = *(const uint2*)(Asu + rl * RS1 + lane * 2);
                float2 la = unpk(u.x), lb = unpk(u.y);
                float4 o = inorm4(make_float4(la.x, la.y, lb.x, lb.y));
                uint2 st; st.x = packbf(o.x, o.y); st.y = packbf(o.z, o.w);
                *(uint2*)(outb + (size_t)r * 128 + lane * 4) = st;
            }
        }
    }
}

// ==== merged fus (item + group segments): out = sigmoid([EMB_f32, X2_bf16] @ W^T + b) ====
// blocks [0,SPLIT): item; [SPLIT,grid): group. Each block owns one N64 half (localBid&1).
__global__ void __launch_bounds__(256, 2)
k_fus(const float* __restrict__ EMB1, const __nv_bfloat16* __restrict__ X21,
      const float* __restrict__ W1, const float* __restrict__ B1,
      float* __restrict__ fout1, __nv_bfloat16* __restrict__ bout1, int N1,
      const float* __restrict__ EMB2, const __nv_bfloat16* __restrict__ X22,
      const float* __restrict__ W2, const float* __restrict__ B2,
      float* __restrict__ fout2, __nv_bfloat16* __restrict__ bout2, int N2,
      int SPLIT)
{
    extern __shared__ __align__(16) unsigned smu[];
    unsigned* Asu = smu;                // 128*RS2
    unsigned* Wsu = Asu + 128 * RS2;    // 64*RS2
    float*    biasf = (float*)(Wsu + 64 * RS2);
    const int tid = threadIdx.x, lane = tid & 31, w = tid >> 5;
    const int qr = lane >> 2, qc = lane & 3;

    const bool seg1 = (int)blockIdx.x < SPLIT;
    const int localBid = seg1 ? blockIdx.x : blockIdx.x - SPLIT;
    const int nb       = seg1 ? SPLIT : gridDim.x - SPLIT;
    const float* EMB = seg1 ? EMB1 : EMB2;
    const __nv_bfloat16* X2 = seg1 ? X21 : X22;
    const float* W  = seg1 ? W1 : W2;
    const float* Bv = seg1 ? B1 : B2;
    float* fout = seg1 ? fout1 : fout2;
    __nv_bfloat16* bout = seg1 ? bout1 : bout2;
    const int N = seg1 ? N1 : N2;

    const int half = localBid & 1;
    const int mbase = (w >> 1) * 32, nloc = (w & 1) * 32;

    for (int i = tid; i < 64 * 128; i += 256) {
        int n = i >> 7, j = i & 127;
        float2 wv = ((const float2*)W)[(size_t)(half * 64 + n) * 128 + j];
        Wsu[n * RS2 + j] = packbf(wv.x, wv.y);
    }
    if (tid < 64) biasf[tid] = Bv[half * 64 + tid];

    const unsigned aBase = smaddr(Asu) + (((mbase + (lane & 15)) * RS2 + ((lane >> 4) << 2)) << 2);
    const unsigned bBase = smaddr(Wsu) + (((nloc + ((lane >> 4) << 3) + (lane & 7)) * RS2 + (((lane >> 3) & 1) << 2)) << 2);

    const int ntiles = (N + 127) >> 7;
    for (int tile = localBid >> 1; tile < ntiles; tile += nb >> 1) {
        __syncthreads();
        #pragma unroll 4
        for (int i = 0; i < 16; i++) {
            int rl = w * 16 + i, r = tile * 128 + rl;
            float4 ve = make_float4(0.f,0.f,0.f,0.f);
            uint2 ux = make_uint2(0u, 0u);
            if (r < N) {
                ve = *(const float4*)(EMB + (size_t)r * 128 + lane * 4);
                ux = ((const uint2*)(X2 + (size_t)r * 128))[lane];
            }
            unsigned* rowp = Asu + rl * RS2;
            uint2 st; st.x = packbf(ve.x, ve.y); st.y = packbf(ve.z, ve.w);
            *(uint2*)(rowp + lane * 2)      = st;
            *(uint2*)(rowp + 64 + lane * 2) = ux;
        }
        __syncthreads();
        float d[2][4][4];
        #pragma unroll
        for (int t = 0; t < 2; t++)
            #pragma unroll
            for (int nt = 0; nt < 4; nt++)
                #pragma unroll
                for (int j = 0; j < 4; j++) d[t][nt][j] = 0.f;
        #pragma unroll
        for (int ks = 0; ks < 16; ks++) mma_m32n32<RS2>(d, aBase, bBase, ks);
        #pragma unroll
        for (int t = 0; t < 2; t++)
            #pragma unroll
            for (int nt = 0; nt < 4; nt++) {
                int lcol = nloc + nt * 8 + qc * 2;
                int gcol = half * 64 + lcol;
                float b0 = biasf[lcol], b1 = biasf[lcol + 1];
                #pragma unroll
                for (int h = 0; h < 2; h++) {
                    int r = tile * 128 + mbase + t * 16 + qr + h * 8;
                    if (r < N) {
                        float s0 = sigf(d[t][nt][2*h]   + b0);
                        float s1 = sigf(d[t][nt][2*h+1] + b1);
                        if (fout) *(float2*)(fout + (size_t)r * 128 + gcol) = make_float2(s0, s1);
                        *(unsigned*)(bout + (size_t)r * 128 + gcol) = packbf(s0, s1);
                    }
                }
            }
    }
}

// ==== social layer (+ optional fused combine) + optional tail spmm_gi work ====
__global__ void __launch_bounds__(256, 2)
k_social(const int* __restrict__ rp, const int* __restrict__ cols, const float* __restrict__ vals,
         const __nv_bfloat16* __restrict__ Xb, const float* __restrict__ W, const float* __restrict__ Bv,
         float* __restrict__ fout, __nv_bfloat16* __restrict__ bout,
         const float* __restrict__ addA, const float* __restrict__ addB, int N,
         const int* __restrict__ t_rp, const int* __restrict__ t_cols, const float* __restrict__ t_vals,
         const __nv_bfloat16* __restrict__ t_X, float* __restrict__ t_out, int t_N)
{
    extern __shared__ __align__(16) unsigned smu[];
    unsigned* Asu = smu;
    unsigned* Wsu = Asu + 128 * RS1;
    float*    biasf = (float*)(Wsu + 128 * RS1);
    const int tid = threadIdx.x, lane = tid & 31, w = tid >> 5;
    const int qr = lane >> 2, qc = lane & 3;
    const int mbase = (w >> 1) * 32, nbase = (w & 1) * 64;

    for (int i = tid; i < 128 * 64; i += 256) {
        float2 wv = ((const float2*)W)[i];
        Wsu[(i >> 6) * RS1 + (i & 63)] = packbf(wv.x, wv.y);
    }
    if (tid < 128) biasf[tid] = Bv[tid];

    const unsigned aBase = smaddr(Asu) + (((mbase + (lane & 15)) * RS1 + ((lane >> 4) << 2)) << 2);
    const unsigned bBase = smaddr(Wsu) + (((nbase + ((lane >> 4) << 3) + (lane & 7)) * RS1 + (((lane >> 3) & 1) << 2)) << 2);

    int ntiles = (N + 127) >> 7;
    for (int tile = blockIdx.x; tile < ntiles; tile += gridDim.x) {
        __syncthreads();
        for (int i = 0; i < 16; i++) {
            int rl = w * 16 + i, r = tile * 128 + rl;
            float4 a0 = make_float4(0.f,0.f,0.f,0.f);
            if (r < N) a0 = spmm_row(rp, cols, vals, Xb, r, lane);
            uint2 st; st.x = packbf(a0.x, a0.y); st.y = packbf(a0.z, a0.w);
            *(uint2*)(Asu + rl * RS1 + lane * 2) = st;
        }
        __syncthreads();
        float d[2][8][4];
        #pragma unroll
        for (int t = 0; t < 2; t++)
            #pragma unroll
            for (int nt = 0; nt < 8; nt++)
                #pragma unroll
                for (int j = 0; j < 4; j++) d[t][nt][j] = 0.f;
        #pragma unroll
        for (int ks = 0; ks < 8; ks++) mma_m32n64<RS1>(d, aBase, bBase, ks);
        #pragma unroll
        for (int t = 0; t < 2; t++)
            #pragma unroll
            for (int nt = 0; nt < 8; nt++) {
                int col = nbase + nt * 8 + qc * 2;
                float b0 = biasf[col], b1 = biasf[col + 1];
                #pragma unroll
                for (int h = 0; h < 2; h++) {
                    int r = tile * 128 + mbase + t * 16 + qr + h * 8;
                    if (r < N) {
                        float s0 = sigf(fmaxf(d[t][nt][2*h]   + b0, 0.f));
                        float s1 = sigf(fmaxf(d[t][nt][2*h+1] + b1, 0.f));
                        if (addA) {
                            float2 pa = *(const float2*)(addA + (size_t)r * 128 + col);
                            float2 pb = *(const float2*)(addB + (size_t)r * 128 + col);
                            s0 = sigf((s0 + pa.x + pb.x) * 0.5f);
                            s1 = sigf((s1 + pa.y + pb.y) * 0.5f);
                        }
                        *(float2*)(fout + (size_t)r * 128 + col) = make_float2(s0, s1);
                        if (bout) *(unsigned*)(bout + (size_t)r * 128 + col) = packbf(s0, s1);
                    }
                }
            }
    }
    // tail: independent spmm (g_from_items), sigmoid epilogue
    if (t_out) {
        for (int r = blockIdx.x * 8 + w; r < t_N; r += gridDim.x * 8) {
            float4 a0 = spmm_row(t_rp, t_cols, t_vals, t_X, r, lane);
            a0.x = sigf(a0.x); a0.y = sigf(a0.y); a0.z = sigf(a0.z); a0.w = sigf(a0.w);
            *(float4*)(t_out + (size_t)r * 128 + lane * 4) = a0;
        }
    }
}

// ---------------- scoring with fused all_neighbors spmm ----------------
__global__ void __launch_bounds__(256)
k_score(const int* __restrict__ gid, const int* __restrict__ iid,
        const float* __restrict__ FG, const float* __restrict__ FI,
        const int* __restrict__ rp, const int* __restrict__ cols, const float* __restrict__ vals,
        const __nv_bfloat16* __restrict__ FGb,
        float* __restrict__ out, int B)
{
    int widx = (blockIdx.x * blockDim.x + threadIdx.x) >> 5;
    int lane = threadIdx.x & 31;
    if (widx >= B) return;
    int g = gid[widx], it = iid[widx];
    const int c = lane * 4;
    float4 ge = *(const float4*)(FG + (size_t)g  * 128 + c);
    float4 ie = *(const float4*)(FI + (size_t)it * 128 + c);
    float4 ne = spmm_row(rp, cols, vals, FGb, g, lane);  // all_neighbors[g]
    float d1 = ge.x*ie.x + ge.y*ie.y + ge.z*ie.z + ge.w*ie.w;
    float d2 = ne.x*(ge.x+ie.x) + ne.y*(ge.y+ie.y) + ne.z*(ge.z+ie.z) + ne.w*(ge.w+ie.w);
    d1 = wredsum(d1); d2 = wredsum(d2);
    if (lane == 0) { out[widx] = d1; out[B + widx] = d2; }
}

// ---------------- launch ----------------
extern "C" void kernel_launch(void* const* d_in, const int* in_sizes, int n_in,
                              void* d_out, int out_size)
{
    const int*   group_ids   = (const int*)d_in[0];
    const int*   item_ids    = (const int*)d_in[1];
    const int*   gi_rows     = (const int*)d_in[2];
    const int*   gi_cols     = (const int*)d_in[3];
    const float* gi_vals     = (const float*)d_in[4];
    const int*   gg_rows     = (const int*)d_in[5];
    const int*   gg_cols     = (const int*)d_in[6];
    const float* gg_vals     = (const float*)d_in[7];
    const float* g_feat      = (const float*)d_in[8];
    const float* i_feat      = (const float*)d_in[9];
    const float* emb_group   = (const float*)d_in[10];
    const float* emb_item    = (const float*)d_in[11];
    const float* W_w         = (const float*)d_in[12];
    const float* W_b         = (const float*)d_in[13];
    const float* red_w       = (const float*)d_in[14];
    const float* red_b       = (const float*)d_in[15];
    const float* item_fus_w  = (const float*)d_in[16];
    const float* item_fus_b  = (const float*)d_in[17];
    const float* group_fus_w = (const float*)d_in[18];
    const float* group_fus_b = (const float*)d_in[19];
    float* out = (float*)d_out;

    int B   = in_sizes[0];
    int Egi = in_sizes[2];
    int Egg = in_sizes[5];
    int NG  = in_sizes[8] / 128;  if (NG > NG_CAP) NG = NG_CAP;
    int NI  = in_sizes[9] / 128;  if (NI > NI_CAP) NI = NI_CAP;

    float *p_fi, *p_gfi, *p_first, *p_fgrp;
    __nv_bfloat16 *pb_t2i, *pb_t2g, *pb_fi, *pb_fg, *pb_first, *pb_fgrp;
    int *p_rp_gi, *p_rp_gg;
    cudaGetSymbolAddress((void**)&p_fi,     g_fi);
    cudaGetSymbolAddress((void**)&p_gfi,    g_gfi);
    cudaGetSymbolAddress((void**)&p_first,  g_first);
    cudaGetSymbolAddress((void**)&p_fgrp,   g_fgrp);
    cudaGetSymbolAddress((void**)&pb_t2i,   b_t2i);
    cudaGetSymbolAddress((void**)&pb_t2g,   b_t2g);
    cudaGetSymbolAddress((void**)&pb_fi,    b_fi);
    cudaGetSymbolAddress((void**)&pb_fg,    b_fg);
    cudaGetSymbolAddress((void**)&pb_first, b_first);
    cudaGetSymbolAddress((void**)&pb_fgrp,  b_fgrp);
    cudaGetSymbolAddress((void**)&p_rp_gi,  g_rp_gi);
    cudaGetSymbolAddress((void**)&p_rp_gg,  g_rp_gg);

    size_t smemN = (size_t)(128 * RS1 + 128 * RS1) * 4 + 512;   // ~68.5 KB
    size_t smemF = (size_t)(128 * RS2 + 64 * RS2) * 4 + 256;    // ~99.3 KB
    cudaFuncSetAttribute(k_nln,    cudaFuncAttributeMaxDynamicSharedMemorySize, (int)smemN);
    cudaFuncSetAttribute(k_fus,    cudaFuncAttributeMaxDynamicSharedMemorySize, (int)smemF);
    cudaFuncSetAttribute(k_social, cudaFuncAttributeMaxDynamicSharedMemorySize, (int)smemN);

    const int PGRID = 296;   // 2 blocks/SM
    const int SPLIT = 200;   // k_fus: item blocks (even), group gets 96 (even)

    k_rowptr<<<1024, 256>>>(gi_rows, Egi, NG, p_rp_gi);
    k_rowptr<<<1024, 256>>>(gg_rows, Egg, NG, p_rp_gg);

    // merged nln: i2 and g2 in one launch (same weights)
    k_nln<<<PGRID, 256, smemN>>>(i_feat, NI, g_feat, NG, red_w, red_b, pb_t2i, pb_t2g);

    // merged fus: final_item (f32+bf16) and fus_group (bf16) in one launch
    k_fus<<<PGRID, 256, smemF>>>(emb_item,  pb_t2i, item_fus_w,  item_fus_b,  p_fi,    pb_fi, NI,
                                 emb_group, pb_t2g, group_fus_w, group_fus_b, nullptr, pb_fg, NG,
                                 SPLIT);

    // social layer 1 + tail spmm_gi (g_from_items)
    k_social<<<PGRID, 256, smemN>>>(p_rp_gg, gg_cols, gg_vals, pb_fg, W_w, W_b,
                                    p_first, pb_first, nullptr, nullptr, NG,
                                    p_rp_gi, gi_cols, gi_vals, pb_fi, p_gfi, NG);

    // social layer 2 fused with final_group combine
    k_social<<<PGRID, 256, smemN>>>(p_rp_gg, gg_cols, gg_vals, pb_first, W_w, W_b,
                                    p_fgrp, pb_fgrp, p_gfi, p_first, NG,
                                    nullptr, nullptr, nullptr, nullptr, nullptr, 0);

    // scoring with fused all_neighbors spmm
    k_score<<<(B + 7) / 8, 256>>>(group_ids, item_ids, p_fgrp, p_fi,
                                  p_rp_gg, gg_cols, gg_vals, pb_fgrp, out, B);
}

// round 8
// speedup vs baseline: 2.7045x; 1.3573x over previous
#include <cuda_runtime.h>
#include <cuda_bf16.h>
#include <cstdio>

#define FULLMASK 0xffffffffu
#define NG_CAP 50000
#define NI_CAP 100000
#define RS1 68     // smem row stride (u32 words) K=128 tiles
#define RS2 132    // smem row stride (u32 words) K=256 tiles

// ---------------- scratch (device globals) ----------------
__device__ float g_fi   [NI_CAP * 128];
__device__ float g_gfi  [NG_CAP * 128];
__device__ float g_first[NG_CAP * 128];
__device__ float g_fgrp [NG_CAP * 128];
__device__ __nv_bfloat16 b_t2i  [NI_CAP * 128];
__device__ __nv_bfloat16 b_t2g  [NG_CAP * 128];
__device__ __nv_bfloat16 b_fi   [NI_CAP * 128];
__device__ __nv_bfloat16 b_fg   [NG_CAP * 128];
__device__ __nv_bfloat16 b_first[NG_CAP * 128];
__device__ __nv_bfloat16 b_fgrp [NG_CAP * 128];
__device__ int g_rp_gi[NG_CAP + 1];
__device__ int g_rp_gg[NG_CAP + 1];

// ---------------- helpers ----------------
__device__ __forceinline__ float wredsum(float v) {
    #pragma unroll
    for (int o = 16; o; o >>= 1) v += __shfl_xor_sync(FULLMASK, v, o);
    return v;
}
__device__ __forceinline__ float sigf(float x) { return 1.0f / (1.0f + __expf(-x)); }
__device__ __forceinline__ void fma4(float4& a, const float4 w, const float x) {
    a.x = fmaf(w.x, x, a.x); a.y = fmaf(w.y, x, a.y);
    a.z = fmaf(w.z, x, a.z); a.w = fmaf(w.w, x, a.w);
}
__device__ __forceinline__ float4 inorm4(float4 v) {
    float s = v.x + v.y + v.z + v.w;
    float q = v.x*v.x + v.y*v.y + v.z*v.z + v.w*v.w;
    #pragma unroll
    for (int o = 16; o; o >>= 1) {
        s += __shfl_xor_sync(FULLMASK, s, o);
        q += __shfl_xor_sync(FULLMASK, q, o);
    }
    float m = s * (1.0f / 128.0f);
    float var = q * (1.0f / 128.0f) - m * m;
    float inv = rsqrtf(var + 1e-5f);
    return make_float4((v.x-m)*inv, (v.y-m)*inv, (v.z-m)*inv, (v.w-m)*inv);
}
__device__ __forceinline__ unsigned packbf(float lo, float hi) {
    __nv_bfloat162 h = __floats2bfloat162_rn(lo, hi);
    return *reinterpret_cast<unsigned*>(&h);
}
__device__ __forceinline__ float2 unpk(unsigned u) {
    __nv_bfloat162 h = *reinterpret_cast<__nv_bfloat162*>(&u);
    return __bfloat1622float2(h);
}
__device__ __forceinline__ float4 cvt4u(uint2 u) {
    float2 a = unpk(u.x), b = unpk(u.y);
    return make_float4(a.x, a.y, b.x, b.y);
}
__device__ __forceinline__ unsigned smaddr(const void* p) {
    unsigned a;
    asm("{ .reg .u64 t; cvta.to.shared.u64 t, %1; cvt.u32.u64 %0, t; }" : "=r"(a) : "l"(p));
    return a;
}
__device__ __forceinline__ void ldsm4(unsigned* r, unsigned addr) {
    asm volatile("ldmatrix.sync.aligned.m8n8.x4.shared.b16 {%0,%1,%2,%3}, [%4];"
        : "=r"(r[0]), "=r"(r[1]), "=r"(r[2]), "=r"(r[3]) : "r"(addr));
}
__device__ __forceinline__ void mma16(float* d, const unsigned* a, unsigned b0, unsigned b1) {
    asm volatile("mma.sync.aligned.m16n8k16.row.col.f32.bf16.bf16.f32 "
        "{%0,%1,%2,%3}, {%4,%5,%6,%7}, {%8,%9}, {%0,%1,%2,%3};"
        : "+f"(d[0]), "+f"(d[1]), "+f"(d[2]), "+f"(d[3])
        : "r"(a[0]), "r"(a[1]), "r"(a[2]), "r"(a[3]), "r"(b0), "r"(b1));
}
// warp tile M32 x N32, one k16 step: 2 A-ldsm + 2 B-ldsm + 8 mma
template<int RS>
__device__ __forceinline__ void mma_m32n32(float (&d)[2][4][4], unsigned aBase, unsigned bBase, int ks) {
    const unsigned kb = ks * 32;
    unsigned a0[4], a1[4];
    ldsm4(a0, aBase + kb);
    ldsm4(a1, aBase + 16*RS*4 + kb);
    #pragma unroll
    for (int q = 0; q < 2; q++) {
        unsigned b[4];
        ldsm4(b, bBase + q*16*RS*4 + kb);
        mma16(d[0][2*q],   a0, b[0], b[1]);
        mma16(d[1][2*q],   a1, b[0], b[1]);
        mma16(d[0][2*q+1], a0, b[2], b[3]);
        mma16(d[1][2*q+1], a1, b[2], b[3]);
    }
}
// warp spmm of one row, 8-deep MLP
__device__ __forceinline__ float4 spmm_row(const int* __restrict__ rp, const int* __restrict__ cols,
                                           const float* __restrict__ vals,
                                           const __nv_bfloat16* __restrict__ Xb, int r, int lane)
{
    float4 a0 = make_float4(0.f,0.f,0.f,0.f), a1 = a0, a2 = a0, a3 = a0;
    int s = rp[r], e = rp[r + 1], ed = s;
    for (; ed + 7 < e; ed += 8) {
        int c[8]; float v[8]; uint2 u[8];
        #pragma unroll
        for (int j = 0; j < 8; j++) { c[j] = cols[ed+j]; v[j] = vals[ed+j]; }
        #pragma unroll
        for (int j = 0; j < 8; j++) u[j] = ((const uint2*)(Xb + (size_t)c[j] * 128))[lane];
        fma4(a0, cvt4u(u[0]), v[0]); fma4(a1, cvt4u(u[1]), v[1]);
        fma4(a2, cvt4u(u[2]), v[2]); fma4(a3, cvt4u(u[3]), v[3]);
        fma4(a0, cvt4u(u[4]), v[4]); fma4(a1, cvt4u(u[5]), v[5]);
        fma4(a2, cvt4u(u[6]), v[6]); fma4(a3, cvt4u(u[7]), v[7]);
    }
    for (; ed + 3 < e; ed += 4) {
        int c[4]; float v[4]; uint2 u[4];
        #pragma unroll
        for (int j = 0; j < 4; j++) { c[j] = cols[ed+j]; v[j] = vals[ed+j]; }
        #pragma unroll
        for (int j = 0; j < 4; j++) u[j] = ((const uint2*)(Xb + (size_t)c[j] * 128))[lane];
        fma4(a0, cvt4u(u[0]), v[0]); fma4(a1, cvt4u(u[1]), v[1]);
        fma4(a2, cvt4u(u[2]), v[2]); fma4(a3, cvt4u(u[3]), v[3]);
    }
    for (; ed < e; ed++) {
        uint2 u = ((const uint2*)(Xb + (size_t)cols[ed] * 128))[lane];
        fma4(a0, cvt4u(u), vals[ed]);
    }
    a0.x += a1.x + a2.x + a3.x; a0.y += a1.y + a2.y + a3.y;
    a0.z += a1.z + a2.z + a3.z; a0.w += a1.w + a2.w + a3.w;
    return a0;
}

// ---------------- row_ptr from sorted COO rows ----------------
__global__ void k_rowptr(const int* __restrict__ rows, int E, int N, int* __restrict__ rp) {
    for (int e = blockIdx.x * blockDim.x + threadIdx.x; e < E; e += gridDim.x * blockDim.x) {
        int r = rows[e];
        int prev = (e == 0) ? -1 : rows[e - 1];
        for (int rr = prev + 1; rr <= r; rr++) rp[rr] = e;
        if (e == E - 1) for (int rr = r + 1; rr <= N; rr++) rp[rr] = E;
    }
}

// ======== merged nln (item+group): out = inorm(inorm(X)@W^T+b), M64 tile, 3/SM ========
__global__ void __launch_bounds__(256, 3)
k_nln(const float* __restrict__ X1, int N1, const float* __restrict__ X2, int N2,
      const float* __restrict__ W, const float* __restrict__ Bv,
      __nv_bfloat16* __restrict__ out1, __nv_bfloat16* __restrict__ out2)
{
    extern __shared__ __align__(16) unsigned smu[];
    unsigned* Asu = smu;                 // 64*RS1
    unsigned* Wsu = Asu + 64 * RS1;      // 128*RS1
    float*    biasf = (float*)(Wsu + 128 * RS1);
    const int tid = threadIdx.x, lane = tid & 31, w = tid >> 5;
    const int qr = lane >> 2, qc = lane & 3;
    const int mbase = (w >> 2) * 32, nbase = (w & 3) * 32;

    for (int i = tid; i < 128 * 64; i += 256) {
        float2 wv = ((const float2*)W)[i];
        Wsu[(i >> 6) * RS1 + (i & 63)] = packbf(wv.x, wv.y);
    }
    if (tid < 128) biasf[tid] = Bv[tid];

    const unsigned aBase = smaddr(Asu) + (((mbase + (lane & 15)) * RS1 + ((lane >> 4) << 2)) << 2);
    const unsigned bBase = smaddr(Wsu) + (((nbase + ((lane >> 4) << 3) + (lane & 7)) * RS1 + (((lane >> 3) & 1) << 2)) << 2);

    const int T1 = (N1 + 63) >> 6, T2 = (N2 + 63) >> 6;
    for (int tt = blockIdx.x; tt < T1 + T2; tt += gridDim.x) {
        const bool seg1 = tt < T1;
        const float* X = seg1 ? X1 : X2;
        __nv_bfloat16* outb = seg1 ? out1 : out2;
        const int N = seg1 ? N1 : N2;
        const int tile = seg1 ? tt : tt - T1;
        __syncthreads();
        #pragma unroll 4
        for (int i = 0; i < 8; i++) {
            int rl = w * 8 + i, r = tile * 64 + rl;
            float4 v = make_float4(0.f, 0.f, 0.f, 0.f);
            if (r < N) { v = *(const float4*)(X + (size_t)r * 128 + lane * 4); v = inorm4(v); }
            uint2 st; st.x = packbf(v.x, v.y); st.y = packbf(v.z, v.w);
            *(uint2*)(Asu + rl * RS1 + lane * 2) = st;
        }
        __syncthreads();
        float d[2][4][4];
        #pragma unroll
        for (int t = 0; t < 2; t++)
            #pragma unroll
            for (int nt = 0; nt < 4; nt++)
                #pragma unroll
                for (int j = 0; j < 4; j++) d[t][nt][j] = 0.f;
        #pragma unroll
        for (int ks = 0; ks < 8; ks++) mma_m32n32<RS1>(d, aBase, bBase, ks);
        __syncthreads();
        #pragma unroll
        for (int t = 0; t < 2; t++)
            #pragma unroll
            for (int nt = 0; nt < 4; nt++) {
                int col = nbase + nt * 8 + qc * 2;
                float b0 = biasf[col], b1 = biasf[col + 1];
                int row0 = mbase + t * 16 + qr;
                int wj = col >> 1;
                Asu[row0 * RS1 + wj]       = packbf(d[t][nt][0] + b0, d[t][nt][1] + b1);
                Asu[(row0 + 8) * RS1 + wj] = packbf(d[t][nt][2] + b0, d[t][nt][3] + b1);
            }
        __syncthreads();
        #pragma unroll 4
        for (int i = 0; i < 8; i++) {
            int rl = w * 8 + i, r = tile * 64 + rl;
            if (r < N) {
                uint2 u = *(const uint2*)(Asu + rl * RS1 + lane * 2);
                float2 la = unpk(u.x), lb = unpk(u.y);
                float4 o = inorm4(make_float4(la.x, la.y, lb.x, lb.y));
                uint2 st; st.x = packbf(o.x, o.y); st.y = packbf(o.z, o.w);
                *(uint2*)(outb + (size_t)r * 128 + lane * 4) = st;
            }
        }
    }
}

// ==== merged fus: full N=128 resident W, M64 tile, 2/SM; segments split by block range ====
__global__ void __launch_bounds__(256, 2)
k_fus(const float* __restrict__ EMB1, const __nv_bfloat16* __restrict__ X21,
      const float* __restrict__ W1, const float* __restrict__ B1,
      float* __restrict__ fout1, __nv_bfloat16* __restrict__ bout1, int N1,
      const float* __restrict__ EMB2, const __nv_bfloat16* __restrict__ X22,
      const float* __restrict__ W2, const float* __restrict__ B2,
      float* __restrict__ fout2, __nv_bfloat16* __restrict__ bout2, int N2,
      int SPLIT)
{
    extern __shared__ __align__(16) unsigned smu[];
    unsigned* Asu = smu;                 // 64*RS2
    unsigned* Wsu = Asu + 64 * RS2;      // 128*RS2
    float*    biasf = (float*)(Wsu + 128 * RS2);
    const int tid = threadIdx.x, lane = tid & 31, w = tid >> 5;
    const int qr = lane >> 2, qc = lane & 3;
    const int mbase = (w >> 2) * 32, nbase = (w & 3) * 32;

    const bool seg1 = (int)blockIdx.x < SPLIT;
    const int localBid = seg1 ? blockIdx.x : blockIdx.x - SPLIT;
    const int nb       = seg1 ? SPLIT : gridDim.x - SPLIT;
    const float* EMB = seg1 ? EMB1 : EMB2;
    const __nv_bfloat16* X2 = seg1 ? X21 : X22;
    const float* W  = seg1 ? W1 : W2;
    const float* Bv = seg1 ? B1 : B2;
    float* fout = seg1 ? fout1 : fout2;
    __nv_bfloat16* bout = seg1 ? bout1 : bout2;
    const int N = seg1 ? N1 : N2;

    for (int i = tid; i < 128 * 128; i += 256) {
        int n = i >> 7, j = i & 127;
        float2 wv = ((const float2*)W)[(size_t)n * 128 + j];
        Wsu[n * RS2 + j] = packbf(wv.x, wv.y);
    }
    if (tid < 128) biasf[tid] = Bv[tid];

    const unsigned aBase = smaddr(Asu) + (((mbase + (lane & 15)) * RS2 + ((lane >> 4) << 2)) << 2);
    const unsigned bBase = smaddr(Wsu) + (((nbase + ((lane >> 4) << 3) + (lane & 7)) * RS2 + (((lane >> 3) & 1) << 2)) << 2);

    const int ntiles = (N + 63) >> 6;
    for (int tile = localBid; tile < ntiles; tile += nb) {
        __syncthreads();
        #pragma unroll 4
        for (int i = 0; i < 8; i++) {
            int rl = w * 8 + i, r = tile * 64 + rl;
            float4 ve = make_float4(0.f,0.f,0.f,0.f);
            uint2 ux = make_uint2(0u, 0u);
            if (r < N) {
                ve = *(const float4*)(EMB + (size_t)r * 128 + lane * 4);
                ux = ((const uint2*)(X2 + (size_t)r * 128))[lane];
            }
            unsigned* rowp = Asu + rl * RS2;
            uint2 st; st.x = packbf(ve.x, ve.y); st.y = packbf(ve.z, ve.w);
            *(uint2*)(rowp + lane * 2)      = st;
            *(uint2*)(rowp + 64 + lane * 2) = ux;
        }
        __syncthreads();
        float d[2][4][4];
        #pragma unroll
        for (int t = 0; t < 2; t++)
            #pragma unroll
            for (int nt = 0; nt < 4; nt++)
                #pragma unroll
                for (int j = 0; j < 4; j++) d[t][nt][j] = 0.f;
        #pragma unroll
        for (int ks = 0; ks < 16; ks++) mma_m32n32<RS2>(d, aBase, bBase, ks);
        #pragma unroll
        for (int t = 0; t < 2; t++)
            #pragma unroll
            for (int nt = 0; nt < 4; nt++) {
                int col = nbase + nt * 8 + qc * 2;
                float b0 = biasf[col], b1 = biasf[col + 1];
                #pragma unroll
                for (int h = 0; h < 2; h++) {
                    int r = tile * 64 + mbase + t * 16 + qr + h * 8;
                    if (r < N) {
                        float s0 = sigf(d[t][nt][2*h]   + b0);
                        float s1 = sigf(d[t][nt][2*h+1] + b1);
                        if (fout) *(float2*)(fout + (size_t)r * 128 + col) = make_float2(s0, s1);
                        *(unsigned*)(bout + (size_t)r * 128 + col) = packbf(s0, s1);
                    }
                }
            }
    }
}

// ==== social layer (+ optional fused combine) + optional tail spmm, M64 tile, 3/SM ====
__global__ void __launch_bounds__(256, 3)
k_social(const int* __restrict__ rp, const int* __restrict__ cols, const float* __restrict__ vals,
         const __nv_bfloat16* __restrict__ Xb, const float* __restrict__ W, const float* __restrict__ Bv,
         float* __restrict__ fout, __nv_bfloat16* __restrict__ bout,
         const float* __restrict__ addA, const float* __restrict__ addB, int N,
         const int* __restrict__ t_rp, const int* __restrict__ t_cols, const float* __restrict__ t_vals,
         const __nv_bfloat16* __restrict__ t_X, float* __restrict__ t_out, int t_N)
{
    extern __shared__ __align__(16) unsigned smu[];
    unsigned* Asu = smu;                 // 64*RS1
    unsigned* Wsu = Asu + 64 * RS1;      // 128*RS1
    float*    biasf = (float*)(Wsu + 128 * RS1);
    const int tid = threadIdx.x, lane = tid & 31, w = tid >> 5;
    const int qr = lane >> 2, qc = lane & 3;
    const int mbase = (w >> 2) * 32, nbase = (w & 3) * 32;

    for (int i = tid; i < 128 * 64; i += 256) {
        float2 wv = ((const float2*)W)[i];
        Wsu[(i >> 6) * RS1 + (i & 63)] = packbf(wv.x, wv.y);
    }
    if (tid < 128) biasf[tid] = Bv[tid];

    const unsigned aBase = smaddr(Asu) + (((mbase + (lane & 15)) * RS1 + ((lane >> 4) << 2)) << 2);
    const unsigned bBase = smaddr(Wsu) + (((nbase + ((lane >> 4) << 3) + (lane & 7)) * RS1 + (((lane >> 3) & 1) << 2)) << 2);

    int ntiles = (N + 63) >> 6;
    for (int tile = blockIdx.x; tile < ntiles; tile += gridDim.x) {
        __syncthreads();
        for (int i = 0; i < 8; i++) {
            int rl = w * 8 + i, r = tile * 64 + rl;
            float4 a0 = make_float4(0.f,0.f,0.f,0.f);
            if (r < N) a0 = spmm_row(rp, cols, vals, Xb, r, lane);
            uint2 st; st.x = packbf(a0.x, a0.y); st.y = packbf(a0.z, a0.w);
            *(uint2*)(Asu + rl * RS1 + lane * 2) = st;
        }
        __syncthreads();
        float d[2][4][4];
        #pragma unroll
        for (int t = 0; t < 2; t++)
            #pragma unroll
            for (int nt = 0; nt < 4; nt++)
                #pragma unroll
                for (int j = 0; j < 4; j++) d[t][nt][j] = 0.f;
        #pragma unroll
        for (int ks = 0; ks < 8; ks++) mma_m32n32<RS1>(d, aBase, bBase, ks);
        #pragma unroll
        for (int t = 0; t < 2; t++)
            #pragma unroll
            for (int nt = 0; nt < 4; nt++) {
                int col = nbase + nt * 8 + qc * 2;
                float b0 = biasf[col], b1 = biasf[col + 1];
                #pragma unroll
                for (int h = 0; h < 2; h++) {
                    int r = tile * 64 + mbase + t * 16 + qr + h * 8;
                    if (r < N) {
                        float s0 = sigf(fmaxf(d[t][nt][2*h]   + b0, 0.f));
                        float s1 = sigf(fmaxf(d[t][nt][2*h+1] + b1, 0.f));
                        if (addA) {
                            float2 pa = *(const float2*)(addA + (size_t)r * 128 + col);
                            float2 pb = *(const float2*)(addB + (size_t)r * 128 + col);
                            s0 = sigf((s0 + pa.x + pb.x) * 0.5f);
                            s1 = sigf((s1 + pa.y + pb.y) * 0.5f);
                        }
                        *(float2*)(fout + (size_t)r * 128 + col) = make_float2(s0, s1);
                        if (bout) *(unsigned*)(bout + (size_t)r * 128 + col) = packbf(s0, s1);
                    }
                }
            }
    }
    // tail: independent spmm (g_from_items), sigmoid epilogue
    if (t_out) {
        for (int r = blockIdx.x * 8 + w; r < t_N; r += gridDim.x * 8) {
            float4 a0 = spmm_row(t_rp, t_cols, t_vals, t_X, r, lane);
            a0.x = sigf(a0.x); a0.y = sigf(a0.y); a0.z = sigf(a0.z); a0.w = sigf(a0.w);
            *(float4*)(t_out + (size_t)r * 128 + lane * 4) = a0;
        }
    }
}

// ---------------- scoring with fused all_neighbors spmm ----------------
__global__ void __launch_bounds__(256)
k_score(const int* __restrict__ gid, const int* __restrict__ iid,
        const float* __restrict__ FG, const float* __restrict__ FI,
        const int* __restrict__ rp, const int* __restrict__ cols, const float* __restrict__ vals,
        const __nv_bfloat16* __restrict__ FGb,
        float* __restrict__ out, int B)
{
    int widx = (blockIdx.x * blockDim.x + threadIdx.x) >> 5;
    int lane = threadIdx.x & 31;
    if (widx >= B) return;
    int g = gid[widx], it = iid[widx];
    const int c = lane * 4;
    float4 ge = *(const float4*)(FG + (size_t)g  * 128 + c);
    float4 ie = *(const float4*)(FI + (size_t)it * 128 + c);
    float4 ne = spmm_row(rp, cols, vals, FGb, g, lane);
    float d1 = ge.x*ie.x + ge.y*ie.y + ge.z*ie.z + ge.w*ie.w;
    float d2 = ne.x*(ge.x+ie.x) + ne.y*(ge.y+ie.y) + ne.z*(ge.z+ie.z) + ne.w*(ge.w+ie.w);
    d1 = wredsum(d1); d2 = wredsum(d2);
    if (lane == 0) { out[widx] = d1; out[B + widx] = d2; }
}

// ---------------- launch ----------------
extern "C" void kernel_launch(void* const* d_in, const int* in_sizes, int n_in,
                              void* d_out, int out_size)
{
    const int*   group_ids   = (const int*)d_in[0];
    const int*   item_ids    = (const int*)d_in[1];
    const int*   gi_rows     = (const int*)d_in[2];
    const int*   gi_cols     = (const int*)d_in[3];
    const float* gi_vals     = (const float*)d_in[4];
    const int*   gg_rows     = (const int*)d_in[5];
    const int*   gg_cols     = (const int*)d_in[6];
    const float* gg_vals     = (const float*)d_in[7];
    const float* g_feat      = (const float*)d_in[8];
    const float* i_feat      = (const float*)d_in[9];
    const float* emb_group   = (const float*)d_in[10];
    const float* emb_item    = (const float*)d_in[11];
    const float* W_w         = (const float*)d_in[12];
    const float* W_b         = (const float*)d_in[13];
    const float* red_w       = (const float*)d_in[14];
    const float* red_b       = (const float*)d_in[15];
    const float* item_fus_w  = (const float*)d_in[16];
    const float* item_fus_b  = (const float*)d_in[17];
    const float* group_fus_w = (const float*)d_in[18];
    const float* group_fus_b = (const float*)d_in[19];
    float* out = (float*)d_out;

    int B   = in_sizes[0];
    int Egi = in_sizes[2];
    int Egg = in_sizes[5];
    int NG  = in_sizes[8] / 128;  if (NG > NG_CAP) NG = NG_CAP;
    int NI  = in_sizes[9] / 128;  if (NI > NI_CAP) NI = NI_CAP;

    float *p_fi, *p_gfi, *p_first, *p_fgrp;
    __nv_bfloat16 *pb_t2i, *pb_t2g, *pb_fi, *pb_fg, *pb_first, *pb_fgrp;
    int *p_rp_gi, *p_rp_gg;
    cudaGetSymbolAddress((void**)&p_fi,     g_fi);
    cudaGetSymbolAddress((void**)&p_gfi,    g_gfi);
    cudaGetSymbolAddress((void**)&p_first,  g_first);
    cudaGetSymbolAddress((void**)&p_fgrp,   g_fgrp);
    cudaGetSymbolAddress((void**)&pb_t2i,   b_t2i);
    cudaGetSymbolAddress((void**)&pb_t2g,   b_t2g);
    cudaGetSymbolAddress((void**)&pb_fi,    b_fi);
    cudaGetSymbolAddress((void**)&pb_fg,    b_fg);
    cudaGetSymbolAddress((void**)&pb_first, b_first);
    cudaGetSymbolAddress((void**)&pb_fgrp,  b_fgrp);
    cudaGetSymbolAddress((void**)&p_rp_gi,  g_rp_gi);
    cudaGetSymbolAddress((void**)&p_rp_gg,  g_rp_gg);

    size_t smemN = (size_t)(64 * RS1 + 128 * RS1) * 4 + 512;    // ~52.7 KB (3/SM)
    size_t smemF = (size_t)(64 * RS2 + 128 * RS2) * 4 + 512;    // ~101.9 KB (2/SM)
    cudaFuncSetAttribute(k_nln,    cudaFuncAttributeMaxDynamicSharedMemorySize, (int)smemN);
    cudaFuncSetAttribute(k_fus,    cudaFuncAttributeMaxDynamicSharedMemorySize, (int)smemF);
    cudaFuncSetAttribute(k_social, cudaFuncAttributeMaxDynamicSharedMemorySize, (int)smemN);

    const int PGRID2 = 296;   // 2 blocks/SM
    const int PGRID3 = 444;   // 3 blocks/SM
    const int SPLIT  = 197;   // k_fus item blocks (NI:NG ≈ 2:1)

    k_rowptr<<<1024, 256>>>(gi_rows, Egi, NG, p_rp_gi);
    k_rowptr<<<1024, 256>>>(gg_rows, Egg, NG, p_rp_gg);

    // merged nln: i2 and g2 (same weights)
    k_nln<<<PGRID3, 256, smemN>>>(i_feat, NI, g_feat, NG, red_w, red_b, pb_t2i, pb_t2g);

    // merged fus: final_item (f32+bf16) and fus_group (bf16)
    k_fus<<<PGRID2, 256, smemF>>>(emb_item,  pb_t2i, item_fus_w,  item_fus_b,  p_fi,    pb_fi, NI,
                                  emb_group, pb_t2g, group_fus_w, group_fus_b, nullptr, pb_fg, NG,
                                  SPLIT);

    // social layer 1 + tail spmm_gi (g_from_items)
    k_social<<<PGRID3, 256, smemN>>>(p_rp_gg, gg_cols, gg_vals, pb_fg, W_w, W_b,
                                     p_first, pb_first, nullptr, nullptr, NG,
                                     p_rp_gi, gi_cols, gi_vals, pb_fi, p_gfi, NG);

    // social layer 2 fused with final_group combine
    k_social<<<PGRID3, 256, smemN>>>(p_rp_gg, gg_cols, gg_vals, pb_first, W_w, W_b,
                                     p_fgrp, pb_fgrp, p_gfi, p_first, NG,
                                     nullptr, nullptr, nullptr, nullptr, nullptr, 0);

    // scoring with fused all_neighbors spmm
    k_score<<<(B + 7) / 8, 256>>>(group_ids, item_ids, p_fgrp, p_fi,
                                  p_rp_gg, gg_cols, gg_vals, pb_fgrp, out, B);
}

// round 10
// speedup vs baseline: 2.7779x; 1.0271x over previous
#include <cuda_runtime.h>
#include <cuda_bf16.h>
#include <cstdio>

#define FULLMASK 0xffffffffu
#define NG_CAP 50000
#define NI_CAP 100000
#define RS1 68     // smem row stride (u32 words) K=128 tiles
#define RS2 132    // smem row stride (u32 words) K=256 tiles

// ---------------- scratch (device globals) ----------------
__device__ float g_fi   [NI_CAP * 128];
__device__ float g_gfi  [NG_CAP * 128];
__device__ float g_first[NG_CAP * 128];
__device__ float g_fgrp [NG_CAP * 128];
__device__ __nv_bfloat16 b_t2i  [NI_CAP * 128];
__device__ __nv_bfloat16 b_t2g  [NG_CAP * 128];
__device__ __nv_bfloat16 b_fi   [NI_CAP * 128];
__device__ __nv_bfloat16 b_fg   [NG_CAP * 128];
__device__ __nv_bfloat16 b_first[NG_CAP * 128];
__device__ __nv_bfloat16 b_fgrp [NG_CAP * 128];
__device__ int g_rp_gi[NG_CAP + 1];
__device__ int g_rp_gg[NG_CAP + 1];

// ---------------- helpers ----------------
__device__ __forceinline__ float wredsum(float v) {
    #pragma unroll
    for (int o = 16; o; o >>= 1) v += __shfl_xor_sync(FULLMASK, v, o);
    return v;
}
__device__ __forceinline__ float sigf(float x) { return 1.0f / (1.0f + __expf(-x)); }
__device__ __forceinline__ void fma4(float4& a, const float4 w, const float x) {
    a.x = fmaf(w.x, x, a.x); a.y = fmaf(w.y, x, a.y);
    a.z = fmaf(w.z, x, a.z); a.w = fmaf(w.w, x, a.w);
}
__device__ __forceinline__ float4 inorm4(float4 v) {
    float s = v.x + v.y + v.z + v.w;
    float q = v.x*v.x + v.y*v.y + v.z*v.z + v.w*v.w;
    #pragma unroll
    for (int o = 16; o; o >>= 1) {
        s += __shfl_xor_sync(FULLMASK, s, o);
        q += __shfl_xor_sync(FULLMASK, q, o);
    }
    float m = s * (1.0f / 128.0f);
    float var = q * (1.0f / 128.0f) - m * m;
    float inv = rsqrtf(var + 1e-5f);
    return make_float4((v.x-m)*inv, (v.y-m)*inv, (v.z-m)*inv, (v.w-m)*inv);
}
__device__ __forceinline__ unsigned packbf(float lo, float hi) {
    __nv_bfloat162 h = __floats2bfloat162_rn(lo, hi);
    return *reinterpret_cast<unsigned*>(&h);
}
__device__ __forceinline__ float2 unpk(unsigned u) {
    __nv_bfloat162 h = *reinterpret_cast<__nv_bfloat162*>(&u);
    return __bfloat1622float2(h);
}
__device__ __forceinline__ float4 cvt4u(uint2 u) {
    float2 a = unpk(u.x), b = unpk(u.y);
    return make_float4(a.x, a.y, b.x, b.y);
}
__device__ __forceinline__ unsigned smaddr(const void* p) {
    unsigned a;
    asm("{ .reg .u64 t; cvta.to.shared.u64 t, %1; cvt.u32.u64 %0, t; }" : "=r"(a) : "l"(p));
    return a;
}
__device__ __forceinline__ void ldsm4(unsigned* r, unsigned addr) {
    asm volatile("ldmatrix.sync.aligned.m8n8.x4.shared.b16 {%0,%1,%2,%3}, [%4];"
        : "=r"(r[0]), "=r"(r[1]), "=r"(r[2]), "=r"(r[3]) : "r"(addr));
}
__device__ __forceinline__ void mma16(float* d, const unsigned* a, unsigned b0, unsigned b1) {
    asm volatile("mma.sync.aligned.m16n8k16.row.col.f32.bf16.bf16.f32 "
        "{%0,%1,%2,%3}, {%4,%5,%6,%7}, {%8,%9}, {%0,%1,%2,%3};"
        : "+f"(d[0]), "+f"(d[1]), "+f"(d[2]), "+f"(d[3])
        : "r"(a[0]), "r"(a[1]), "r"(a[2]), "r"(a[3]), "r"(b0), "r"(b1));
}
__device__ __forceinline__ void cpasync8(unsigned dst, const void* src) {
    asm volatile("cp.async.ca.shared.global [%0], [%1], 8;" :: "r"(dst), "l"(src) : "memory");
}
#define CP_COMMIT() asm volatile("cp.async.commit_group;" ::: "memory")
#define CP_WAIT0()  asm volatile("cp.async.wait_group 0;" ::: "memory")

// warp tile M32 x N32 (nln / social path)
template<int RS>
__device__ __forceinline__ void mma_m32n32(float (&d)[2][4][4], unsigned aBase, unsigned bBase, int ks) {
    const unsigned kb = ks * 32;
    unsigned a0[4], a1[4];
    ldsm4(a0, aBase + kb);
    ldsm4(a1, aBase + 16*RS*4 + kb);
    #pragma unroll
    for (int q = 0; q < 2; q++) {
        unsigned b[4];
        ldsm4(b, bBase + q*16*RS*4 + kb);
        mma16(d[0][2*q],   a0, b[0], b[1]);
        mma16(d[1][2*q],   a1, b[0], b[1]);
        mma16(d[0][2*q+1], a0, b[2], b[3]);
        mma16(d[1][2*q+1], a1, b[2], b[3]);
    }
}

// warp spmm of one row, 8-deep MLP (k_score)
__device__ __forceinline__ float4 spmm_row(const int* __restrict__ rp, const int* __restrict__ cols,
                                           const float* __restrict__ vals,
                                           const __nv_bfloat16* __restrict__ Xb, int r, int lane)
{
    float4 a0 = make_float4(0.f,0.f,0.f,0.f), a1 = a0, a2 = a0, a3 = a0;
    int s = rp[r], e = rp[r + 1], ed = s;
    for (; ed + 7 < e; ed += 8) {
        int c[8]; float v[8]; uint2 u[8];
        #pragma unroll
        for (int j = 0; j < 8; j++) { c[j] = cols[ed+j]; v[j] = vals[ed+j]; }
        #pragma unroll
        for (int j = 0; j < 8; j++) u[j] = ((const uint2*)(Xb + (size_t)c[j] * 128))[lane];
        fma4(a0, cvt4u(u[0]), v[0]); fma4(a1, cvt4u(u[1]), v[1]);
        fma4(a2, cvt4u(u[2]), v[2]); fma4(a3, cvt4u(u[3]), v[3]);
        fma4(a0, cvt4u(u[4]), v[4]); fma4(a1, cvt4u(u[5]), v[5]);
        fma4(a2, cvt4u(u[6]), v[6]); fma4(a3, cvt4u(u[7]), v[7]);
    }
    for (; ed + 3 < e; ed += 4) {
        int c[4]; float v[4]; uint2 u[4];
        #pragma unroll
        for (int j = 0; j < 4; j++) { c[j] = cols[ed+j]; v[j] = vals[ed+j]; }
        #pragma unroll
        for (int j = 0; j < 4; j++) u[j] = ((const uint2*)(Xb + (size_t)c[j] * 128))[lane];
        fma4(a0, cvt4u(u[0]), v[0]); fma4(a1, cvt4u(u[1]), v[1]);
        fma4(a2, cvt4u(u[2]), v[2]); fma4(a3, cvt4u(u[3]), v[3]);
    }
    for (; ed < e; ed++) {
        uint2 u = ((const uint2*)(Xb + (size_t)cols[ed] * 128))[lane];
        fma4(a0, cvt4u(u), vals[ed]);
    }
    a0.x += a1.x + a2.x + a3.x; a0.y += a1.y + a2.y + a3.y;
    a0.z += a1.z + a2.z + a3.z; a0.w += a1.w + a2.w + a3.w;
    return a0;
}

// paired-row spmm: two rows gathered with interleaved batches (doubles effective MLP)
__device__ __forceinline__ void spmm_pair(const int* __restrict__ rp, const int* __restrict__ cols,
                                          const float* __restrict__ vals,
                                          const __nv_bfloat16* __restrict__ Xb,
                                          int r0, int r1, int N, int lane,
                                          float4& out0, float4& out1)
{
    float4 p0 = make_float4(0.f,0.f,0.f,0.f), p1 = p0, q0 = p0, q1 = p0;
    int e0 = 0, e1 = 0, ed0 = 0, ed1 = 0;
    if (r0 < N) { ed0 = rp[r0]; e0 = rp[r0 + 1]; }
    if (r1 < N) { ed1 = rp[r1]; e1 = rp[r1 + 1]; }
    while (ed0 + 3 < e0 && ed1 + 3 < e1) {
        int c0[4], c1[4]; float v0[4], v1[4]; uint2 u0[4], u1[4];
        #pragma unroll
        for (int j = 0; j < 4; j++) { c0[j] = cols[ed0+j]; v0[j] = vals[ed0+j]; }
        #pragma unroll
        for (int j = 0; j < 4; j++) { c1[j] = cols[ed1+j]; v1[j] = vals[ed1+j]; }
        #pragma unroll
        for (int j = 0; j < 4; j++) u0[j] = ((const uint2*)(Xb + (size_t)c0[j] * 128))[lane];
        #pragma unroll
        for (int j = 0; j < 4; j++) u1[j] = ((const uint2*)(Xb + (size_t)c1[j] * 128))[lane];
        fma4(p0, cvt4u(u0[0]), v0[0]); fma4(p1, cvt4u(u0[1]), v0[1]);
        fma4(p0, cvt4u(u0[2]), v0[2]); fma4(p1, cvt4u(u0[3]), v0[3]);
        fma4(q0, cvt4u(u1[0]), v1[0]); fma4(q1, cvt4u(u1[1]), v1[1]);
        fma4(q0, cvt4u(u1[2]), v1[2]); fma4(q1, cvt4u(u1[3]), v1[3]);
        ed0 += 4; ed1 += 4;
    }
    for (; ed0 + 3 < e0; ed0 += 4) {
        int c[4]; float v[4]; uint2 u[4];
        #pragma unroll
        for (int j = 0; j < 4; j++) { c[j] = cols[ed0+j]; v[j] = vals[ed0+j]; }
        #pragma unroll
        for (int j = 0; j < 4; j++) u[j] = ((const uint2*)(Xb + (size_t)c[j] * 128))[lane];
        fma4(p0, cvt4u(u[0]), v[0]); fma4(p1, cvt4u(u[1]), v[1]);
        fma4(p0, cvt4u(u[2]), v[2]); fma4(p1, cvt4u(u[3]), v[3]);
    }
    for (; ed0 < e0; ed0++) {
        uint2 u = ((const uint2*)(Xb + (size_t)cols[ed0] * 128))[lane];
        fma4(p0, cvt4u(u), vals[ed0]);
    }
    for (; ed1 + 3 < e1; ed1 += 4) {
        int c[4]; float v[4]; uint2 u[4];
        #pragma unroll
        for (int j = 0; j < 4; j++) { c[j] = cols[ed1+j]; v[j] = vals[ed1+j]; }
        #pragma unroll
        for (int j = 0; j < 4; j++) u[j] = ((const uint2*)(Xb + (size_t)c[j] * 128))[lane];
        fma4(q0, cvt4u(u[0]), v[0]); fma4(q1, cvt4u(u[1]), v[1]);
        fma4(q0, cvt4u(u[2]), v[2]); fma4(q1, cvt4u(u[3]), v[3]);
    }
    for (; ed1 < e1; ed1++) {
        uint2 u = ((const uint2*)(Xb + (size_t)cols[ed1] * 128))[lane];
        fma4(q0, cvt4u(u), vals[ed1]);
    }
    out0 = make_float4(p0.x+p1.x, p0.y+p1.y, p0.z+p1.z, p0.w+p1.w);
    out1 = make_float4(q0.x+q1.x, q0.y+q1.y, q0.z+q1.z, q0.w+q1.w);
}

// ---------------- row_ptr from sorted COO rows ----------------
__global__ void k_rowptr(const int* __restrict__ rows, int E, int N, int* __restrict__ rp) {
    for (int e = blockIdx.x * blockDim.x + threadIdx.x; e < E; e += gridDim.x * blockDim.x) {
        int r = rows[e];
        int prev = (e == 0) ? -1 : rows[e - 1];
        for (int rr = prev + 1; rr <= r; rr++) rp[rr] = e;
        if (e == E - 1) for (int rr = r + 1; rr <= N; rr++) rp[rr] = E;
    }
}

// ======== merged nln (item+group): out = inorm(inorm(X)@W^T+b), M64 tile, 3/SM ========
__global__ void __launch_bounds__(256, 3)
k_nln(const float* __restrict__ X1, int N1, const float* __restrict__ X2, int N2,
      const float* __restrict__ W, const float* __restrict__ Bv,
      __nv_bfloat16* __restrict__ out1, __nv_bfloat16* __restrict__ out2)
{
    extern __shared__ __align__(16) unsigned smu[];
    unsigned* Asu = smu;                 // 64*RS1
    unsigned* Wsu = Asu + 64 * RS1;      // 128*RS1
    float*    biasf = (float*)(Wsu + 128 * RS1);
    const int tid = threadIdx.x, lane = tid & 31, w = tid >> 5;
    const int qr = lane >> 2, qc = lane & 3;
    const int mbase = (w >> 2) * 32, nbase = (w & 3) * 32;

    for (int i = tid; i < 128 * 64; i += 256) {
        float2 wv = ((const float2*)W)[i];
        Wsu[(i >> 6) * RS1 + (i & 63)] = packbf(wv.x, wv.y);
    }
    if (tid < 128) biasf[tid] = Bv[tid];

    const unsigned aBase = smaddr(Asu) + (((mbase + (lane & 15)) * RS1 + ((lane >> 4) << 2)) << 2);
    const unsigned bBase = smaddr(Wsu) + (((nbase + ((lane >> 4) << 3) + (lane & 7)) * RS1 + (((lane >> 3) & 1) << 2)) << 2);

    const int T1 = (N1 + 63) >> 6, T2 = (N2 + 63) >> 6;
    for (int tt = blockIdx.x; tt < T1 + T2; tt += gridDim.x) {
        const bool seg1 = tt < T1;
        const float* X = seg1 ? X1 : X2;
        __nv_bfloat16* outb = seg1 ? out1 : out2;
        const int N = seg1 ? N1 : N2;
        const int tile = seg1 ? tt : tt - T1;
        __syncthreads();
        #pragma unroll 4
        for (int i = 0; i < 8; i++) {
            int rl = w * 8 + i, r = tile * 64 + rl;
            float4 v = make_float4(0.f, 0.f, 0.f, 0.f);
            if (r < N) { v = *(const float4*)(X + (size_t)r * 128 + lane * 4); v = inorm4(v); }
            uint2 st; st.x = packbf(v.x, v.y); st.y = packbf(v.z, v.w);
            *(uint2*)(Asu + rl * RS1 + lane * 2) = st;
        }
        __syncthreads();
        float d[2][4][4];
        #pragma unroll
        for (int t = 0; t < 2; t++)
            #pragma unroll
            for (int nt = 0; nt < 4; nt++)
                #pragma unroll
                for (int j = 0; j < 4; j++) d[t][nt][j] = 0.f;
        #pragma unroll
        for (int ks = 0; ks < 8; ks++) mma_m32n32<RS1>(d, aBase, bBase, ks);
        __syncthreads();
        #pragma unroll
        for (int t = 0; t < 2; t++)
            #pragma unroll
            for (int nt = 0; nt < 4; nt++) {
                int col = nbase + nt * 8 + qc * 2;
                float b0 = biasf[col], b1 = biasf[col + 1];
                int row0 = mbase + t * 16 + qr;
                int wj = col >> 1;
                Asu[row0 * RS1 + wj]       = packbf(d[t][nt][0] + b0, d[t][nt][1] + b1);
                Asu[(row0 + 8) * RS1 + wj] = packbf(d[t][nt][2] + b0, d[t][nt][3] + b1);
            }
        __syncthreads();
        #pragma unroll 4
        for (int i = 0; i < 8; i++) {
            int rl = w * 8 + i, r = tile * 64 + rl;
            if (r < N) {
                uint2 u = *(const uint2*)(Asu + rl * RS1 + lane * 2);
                float2 la = unpk(u.x), lb = unpk(u.y);
                float4 o = inorm4(make_float4(la.x, la.y, lb.x, lb.y));
                uint2 st; st.x = packbf(o.x, o.y); st.y = packbf(o.z, o.w);
                *(uint2*)(outb + (size_t)r * 128 + lane * 4) = st;
            }
        }
    }
}

// ==== merged fus, software-pipelined M32 half-tiles with cp.async + reg prefetch ====
// A ping-pong buffers (2 x 32 rows), W fully resident (K=256, N=128). Warp tile M32xN16.
__global__ void __launch_bounds__(256, 2)
k_fus(const float* __restrict__ EMB1, const __nv_bfloat16* __restrict__ X21,
      const float* __restrict__ W1, const float* __restrict__ B1,
      float* __restrict__ fout1, __nv_bfloat16* __restrict__ bout1, int N1,
      const float* __restrict__ EMB2, const __nv_bfloat16* __restrict__ X22,
      const float* __restrict__ W2, const float* __restrict__ B2,
      float* __restrict__ fout2, __nv_bfloat16* __restrict__ bout2, int N2,
      int SPLIT)
{
    extern __shared__ __align__(16) unsigned smu[];
    // [0, 32*RS2): A buf0 ; [32*RS2, 64*RS2): A buf1 ; then W (128*RS2) ; then bias
    unsigned* Wsu = smu + 64 * RS2;
    float*    biasf = (float*)(Wsu + 128 * RS2);
    const int tid = threadIdx.x, lane = tid & 31, w = tid >> 5;
    const int qr = lane >> 2, qc = lane & 3;
    const int nbase = w * 16;    // 8 warps x N16 = N128

    const bool seg1 = (int)blockIdx.x < SPLIT;
    const int localBid = seg1 ? blockIdx.x : blockIdx.x - SPLIT;
    const int nb       = seg1 ? SPLIT : gridDim.x - SPLIT;
    const float* EMB = seg1 ? EMB1 : EMB2;
    const __nv_bfloat16* X2 = seg1 ? X21 : X22;
    const float* W  = seg1 ? W1 : W2;
    const float* Bv = seg1 ? B1 : B2;
    float* fout = seg1 ? fout1 : fout2;
    __nv_bfloat16* bout = seg1 ? bout1 : bout2;
    const int N = seg1 ? N1 : N2;

    for (int i = tid; i < 128 * 128; i += 256) {
        int n = i >> 7, j = i & 127;
        float2 wv = ((const float2*)W)[(size_t)n * 128 + j];
        Wsu[n * RS2 + j] = packbf(wv.x, wv.y);
    }
    if (tid < 128) biasf[tid] = Bv[tid];

    const unsigned smA = smaddr(smu);
    const unsigned bufStride = 32 * RS2 * 4;
    const unsigned aBase0 = smA + (((lane & 15) * RS2 + ((lane >> 4) << 2)) << 2);
    const unsigned bBase = smaddr(Wsu) + (((nbase + ((lane >> 4) << 3) + (lane & 7)) * RS2 + (((lane >> 3) & 1) << 2)) << 2);

    const int ntiles = (N + 63) >> 6;
    const int nass = (localBid < ntiles) ? ((ntiles - 1 - localBid) / nb + 1) : 0;
    const int nh = 2 * nass;

    float4 e[4];
    // ---- prologue for half 0 into buffer 0 ----
    if (nh > 0) {
        int rbase = localBid * 64;
        #pragma unroll
        for (int i = 0; i < 4; i++) {
            int r = rbase + w * 4 + i;
            e[i] = make_float4(0.f,0.f,0.f,0.f);
            if (r < N) {
                e[i] = *(const float4*)(EMB + (size_t)r * 128 + lane * 4);
                cpasync8(smA + (((w*4+i) * RS2 + 64 + lane * 2) << 2),
                         (const void*)(((const uint2*)(X2 + (size_t)r * 128)) + lane));
            }
        }
        CP_COMMIT();
        #pragma unroll
        for (int i = 0; i < 4; i++) {
            uint2 st; st.x = packbf(e[i].x, e[i].y); st.y = packbf(e[i].z, e[i].w);
            *(uint2*)(smu + (w*4+i) * RS2 + lane * 2) = st;
        }
    }

    for (int hh = 0; hh < nh; hh++) {
        const int b = hh & 1;
        CP_WAIT0();
        __syncthreads();
        const bool hasNext = (hh + 1) < nh;
        if (hasNext) {
            int tile = localBid + ((hh+1) >> 1) * nb;
            int rbase = tile * 64 + ((hh+1) & 1) * 32;
            #pragma unroll
            for (int i = 0; i < 4; i++) {
                int r = rbase + w * 4 + i;
                e[i] = make_float4(0.f,0.f,0.f,0.f);
                if (r < N) {
                    e[i] = *(const float4*)(EMB + (size_t)r * 128 + lane * 4);
                    cpasync8(smA + (b ^ 1) * bufStride + (((w*4+i) * RS2 + 64 + lane * 2) << 2),
                             (const void*)(((const uint2*)(X2 + (size_t)r * 128)) + lane));
                }
            }
            CP_COMMIT();
        }
        // ---- MMA on buffer b (M32 x N16 per warp, K=256) ----
        float d[2][2][4];
        #pragma unroll
        for (int t = 0; t < 2; t++)
            #pragma unroll
            for (int nt = 0; nt < 2; nt++)
                #pragma unroll
                for (int j = 0; j < 4; j++) d[t][nt][j] = 0.f;
        const unsigned aB = aBase0 + b * bufStride;
        #pragma unroll
        for (int ks = 0; ks < 16; ks++) {
            const unsigned kb = ks * 32;
            unsigned a0[4], a1[4], bb[4];
            ldsm4(a0, aB + kb);
            ldsm4(a1, aB + 16*RS2*4 + kb);
            ldsm4(bb, bBase + kb);
            mma16(d[0][0], a0, bb[0], bb[1]);
            mma16(d[1][0], a1, bb[0], bb[1]);
            mma16(d[0][1], a0, bb[2], bb[3]);
            mma16(d[1][1], a1, bb[2], bb[3]);
        }
        if (hasNext) {
            #pragma unroll
            for (int i = 0; i < 4; i++) {
                uint2 st; st.x = packbf(e[i].x, e[i].y); st.y = packbf(e[i].z, e[i].w);
                *(uint2*)(smu + (b ^ 1) * 32 * RS2 + (w*4+i) * RS2 + lane * 2) = st;
            }
        }
        // ---- epilogue for half hh ----
        {
            int tile = localBid + (hh >> 1) * nb;
            int rbase = tile * 64 + (hh & 1) * 32;
            #pragma unroll
            for (int t = 0; t < 2; t++)
                #pragma unroll
                for (int nt = 0; nt < 2; nt++) {
                    int col = nbase + nt * 8 + qc * 2;
                    float b0 = biasf[col], b1 = biasf[col + 1];
                    #pragma unroll
                    for (int h8 = 0; h8 < 2; h8++) {
                        int r = rbase + t * 16 + qr + h8 * 8;
                        if (r < N) {
                            float s0 = sigf(d[t][nt][2*h8]   + b0);
                            float s1 = sigf(d[t][nt][2*h8+1] + b1);
                            if (fout) *(float2*)(fout + (size_t)r * 128 + col) = make_float2(s0, s1);
                            *(unsigned*)(bout + (size_t)r * 128 + col) = packbf(s0, s1);
                        }
                    }
                }
        }
    }
}

// ==== social layer (+ optional fused combine) + optional tail spmm, M64 tile, 3/SM ====
__global__ void __launch_bounds__(256, 3)
k_social(const int* __restrict__ rp, const int* __restrict__ cols, const float* __restrict__ vals,
         const __nv_bfloat16* __restrict__ Xb, const float* __restrict__ W, const float* __restrict__ Bv,
         float* __restrict__ fout, __nv_bfloat16* __restrict__ bout,
         const float* __restrict__ addA, const float* __restrict__ addB, int N,
         const int* __restrict__ t_rp, const int* __restrict__ t_cols, const float* __restrict__ t_vals,
         const __nv_bfloat16* __restrict__ t_X, float* __restrict__ t_out, int t_N)
{
    extern __shared__ __align__(16) unsigned smu[];
    unsigned* Asu = smu;                 // 64*RS1
    unsigned* Wsu = Asu + 64 * RS1;      // 128*RS1
    float*    biasf = (float*)(Wsu + 128 * RS1);
    const int tid = threadIdx.x, lane = tid & 31, w = tid >> 5;
    const int qr = lane >> 2, qc = lane & 3;
    const int mbase = (w >> 2) * 32, nbase = (w & 3) * 32;

    for (int i = tid; i < 128 * 64; i += 256) {
        float2 wv = ((const float2*)W)[i];
        Wsu[(i >> 6) * RS1 + (i & 63)] = packbf(wv.x, wv.y);
    }
    if (tid < 128) biasf[tid] = Bv[tid];

    const unsigned aBase = smaddr(Asu) + (((mbase + (lane & 15)) * RS1 + ((lane >> 4) << 2)) << 2);
    const unsigned bBase = smaddr(Wsu) + (((nbase + ((lane >> 4) << 3) + (lane & 7)) * RS1 + (((lane >> 3) & 1) << 2)) << 2);

    int ntiles = (N + 63) >> 6;
    for (int tile = blockIdx.x; tile < ntiles; tile += gridDim.x) {
        __syncthreads();
        for (int i = 0; i < 8; i += 2) {
            int rl = w * 8 + i;
            int r0 = tile * 64 + rl, r1 = r0 + 1;
            float4 o0, o1;
            spmm_pair(rp, cols, vals, Xb, r0, r1, N, lane, o0, o1);
            uint2 st0; st0.x = packbf(o0.x, o0.y); st0.y = packbf(o0.z, o0.w);
            uint2 st1; st1.x = packbf(o1.x, o1.y); st1.y = packbf(o1.z, o1.w);
            *(uint2*)(Asu + rl * RS1 + lane * 2)       = st0;
            *(uint2*)(Asu + (rl + 1) * RS1 + lane * 2) = st1;
        }
        __syncthreads();
        float d[2][4][4];
        #pragma unroll
        for (int t = 0; t < 2; t++)
            #pragma unroll
            for (int nt = 0; nt < 4; nt++)
                #pragma unroll
                for (int j = 0; j < 4; j++) d[t][nt][j] = 0.f;
        #pragma unroll
        for (int ks = 0; ks < 8; ks++) mma_m32n32<RS1>(d, aBase, bBase, ks);
        #pragma unroll
        for (int t = 0; t < 2; t++)
            #pragma unroll
            for (int nt = 0; nt < 4; nt++) {
                int col = nbase + nt * 8 + qc * 2;
                float b0 = biasf[col], b1 = biasf[col + 1];
                #pragma unroll
                for (int h = 0; h < 2; h++) {
                    int r = tile * 64 + mbase + t * 16 + qr + h * 8;
                    if (r < N) {
                        float s0 = sigf(fmaxf(d[t][nt][2*h]   + b0, 0.f));
                        float s1 = sigf(fmaxf(d[t][nt][2*h+1] + b1, 0.f));
                        if (addA) {
                            float2 pa = *(const float2*)(addA + (size_t)r * 128 + col);
                            float2 pb = *(const float2*)(addB + (size_t)r * 128 + col);
                            s0 = sigf((s0 + pa.x + pb.x) * 0.5f);
                            s1 = sigf((s1 + pa.y + pb.y) * 0.5f);
                        }
                        *(float2*)(fout + (size_t)r * 128 + col) = make_float2(s0, s1);
                        if (bout) *(unsigned*)(bout + (size_t)r * 128 + col) = packbf(s0, s1);
                    }
                }
            }
    }
    // tail: independent spmm (g_from_items), paired rows, sigmoid epilogue
    if (t_out) {
        for (int base = blockIdx.x * 16 + w * 2; base < t_N; base += gridDim.x * 16) {
            int r0 = base, r1 = base + 1;
            float4 o0, o1;
            spmm_pair(t_rp, t_cols, t_vals, t_X, r0, r1, t_N, lane, o0, o1);
            o0.x = sigf(o0.x); o0.y = sigf(o0.y); o0.z = sigf(o0.z); o0.w = sigf(o0.w);
            *(float4*)(t_out + (size_t)r0 * 128 + lane * 4) = o0;
            if (r1 < t_N) {
                o1.x = sigf(o1.x); o1.y = sigf(o1.y); o1.z = sigf(o1.z); o1.w = sigf(o1.w);
                *(float4*)(t_out + (size_t)r1 * 128 + lane * 4) = o1;
            }
        }
    }
}

// ---------------- scoring with fused all_neighbors spmm ----------------
__global__ void __launch_bounds__(256)
k_score(const int* __restrict__ gid, const int* __restrict__ iid,
        const float* __restrict__ FG, const float* __restrict__ FI,
        const int* __restrict__ rp, const int* __restrict__ cols, const float* __restrict__ vals,
        const __nv_bfloat16* __restrict__ FGb,
        float* __restrict__ out, int B)
{
    int widx = (blockIdx.x * blockDim.x + threadIdx.x) >> 5;
    int lane = threadIdx.x & 31;
    if (widx >= B) return;
    int g = gid[widx], it = iid[widx];
    const int c = lane * 4;
    float4 ge = *(const float4*)(FG + (size_t)g  * 128 + c);
    float4 ie = *(const float4*)(FI + (size_t)it * 128 + c);
    float4 ne = spmm_row(rp, cols, vals, FGb, g, lane);
    float d1 = ge.x*ie.x + ge.y*ie.y + ge.z*ie.z + ge.w*ie.w;
    float d2 = ne.x*(ge.x+ie.x) + ne.y*(ge.y+ie.y) + ne.z*(ge.z+ie.z) + ne.w*(ge.w+ie.w);
    d1 = wredsum(d1); d2 = wredsum(d2);
    if (lane == 0) { out[widx] = d1; out[B + widx] = d2; }
}

// ---------------- launch ----------------
extern "C" void kernel_launch(void* const* d_in, const int* in_sizes, int n_in,
                              void* d_out, int out_size)
{
    const int*   group_ids   = (const int*)d_in[0];
    const int*   item_ids    = (const int*)d_in[1];
    const int*   gi_rows     = (const int*)d_in[2];
    const int*   gi_cols     = (const int*)d_in[3];
    const float* gi_vals     = (const float*)d_in[4];
    const int*   gg_rows     = (const int*)d_in[5];
    const int*   gg_cols     = (const int*)d_in[6];
    const float* gg_vals     = (const float*)d_in[7];
    const float* g_feat      = (const float*)d_in[8];
    const float* i_feat      = (const float*)d_in[9];
    const float* emb_group   = (const float*)d_in[10];
    const float* emb_item    = (const float*)d_in[11];
    const float* W_w         = (const float*)d_in[12];
    const float* W_b         = (const float*)d_in[13];
    const float* red_w       = (const float*)d_in[14];
    const float* red_b       = (const float*)d_in[15];
    const float* item_fus_w  = (const float*)d_in[16];
    const float* item_fus_b  = (const float*)d_in[17];
    const float* group_fus_w = (const float*)d_in[18];
    const float* group_fus_b = (const float*)d_in[19];
    float* out = (float*)d_out;

    int B   = in_sizes[0];
    int Egi = in_sizes[2];
    int Egg = in_sizes[5];
    int NG  = in_sizes[8] / 128;  if (NG > NG_CAP) NG = NG_CAP;
    int NI  = in_sizes[9] / 128;  if (NI > NI_CAP) NI = NI_CAP;

    float *p_fi, *p_gfi, *p_first, *p_fgrp;
    __nv_bfloat16 *pb_t2i, *pb_t2g, *pb_fi, *pb_fg, *pb_first, *pb_fgrp;
    int *p_rp_gi, *p_rp_gg;
    cudaGetSymbolAddress((void**)&p_fi,     g_fi);
    cudaGetSymbolAddress((void**)&p_gfi,    g_gfi);
    cudaGetSymbolAddress((void**)&p_first,  g_first);
    cudaGetSymbolAddress((void**)&p_fgrp,   g_fgrp);
    cudaGetSymbolAddress((void**)&pb_t2i,   b_t2i);
    cudaGetSymbolAddress((void**)&pb_t2g,   b_t2g);
    cudaGetSymbolAddress((void**)&pb_fi,    b_fi);
    cudaGetSymbolAddress((void**)&pb_fg,    b_fg);
    cudaGetSymbolAddress((void**)&pb_first, b_first);
    cudaGetSymbolAddress((void**)&pb_fgrp,  b_fgrp);
    cudaGetSymbolAddress((void**)&p_rp_gi,  g_rp_gi);
    cudaGetSymbolAddress((void**)&p_rp_gg,  g_rp_gg);

    size_t smemN = (size_t)(64 * RS1 + 128 * RS1) * 4 + 512;    // ~52.7 KB (3/SM)
    size_t smemF = (size_t)(64 * RS2 + 128 * RS2) * 4 + 512;    // ~101.9 KB (2/SM)
    cudaFuncSetAttribute(k_nln,    cudaFuncAttributeMaxDynamicSharedMemorySize, (int)smemN);
    cudaFuncSetAttribute(k_fus,    cudaFuncAttributeMaxDynamicSharedMemorySize, (int)smemF);
    cudaFuncSetAttribute(k_social, cudaFuncAttributeMaxDynamicSharedMemorySize, (int)smemN);

    const int PGRID2 = 296;   // 2 blocks/SM
    const int PGRID3 = 444;   // 3 blocks/SM
    const int SPLIT  = 197;   // k_fus item blocks (NI:NG ≈ 2:1)

    k_rowptr<<<1024, 256>>>(gi_rows, Egi, NG, p_rp_gi);
    k_rowptr<<<1024, 256>>>(gg_rows, Egg, NG, p_rp_gg);

    // merged nln: i2 and g2 (same weights)
    k_nln<<<PGRID3, 256, smemN>>>(i_feat, NI, g_feat, NG, red_w, red_b, pb_t2i, pb_t2g);

    // merged fus (pipelined): final_item (f32+bf16) and fus_group (bf16)
    k_fus<<<PGRID2, 256, smemF>>>(emb_item,  pb_t2i, item_fus_w,  item_fus_b,  p_fi,    pb_fi, NI,
                                  emb_group, pb_t2g, group_fus_w, group_fus_b, nullptr, pb_fg, NG,
                                  SPLIT);

    // social layer 1 + tail spmm_gi (g_from_items)
    k_social<<<PGRID3, 256, smemN>>>(p_rp_gg, gg_cols, gg_vals, pb_fg, W_w, W_b,
                                     p_first, pb_first, nullptr, nullptr, NG,
                                     p_rp_gi, gi_cols, gi_vals, pb_fi, p_gfi, NG);

    // social layer 2 fused with final_group combine
    k_social<<<PGRID3, 256, smemN>>>(p_rp_gg, gg_cols, gg_vals, pb_first, W_w, W_b,
                                     p_fgrp, pb_fgrp, p_gfi, p_first, NG,
                                     nullptr, nullptr, nullptr, nullptr, nullptr, 0);

    // scoring with fused all_neighbors spmm
    k_score<<<(B + 7) / 8, 256>>>(group_ids, item_ids, p_fgrp, p_fi,
                                  p_rp_gg, gg_cols, gg_vals, pb_fgrp, out, B);
}

// round 11
// speedup vs baseline: 2.9551x; 1.0638x over previous
#include <cuda_runtime.h>
#include <cuda_bf16.h>
#include <cstdio>

#define FULLMASK 0xffffffffu
#define NG_CAP 50000
#define NI_CAP 100000
#define RS1 68     // smem row stride (u32 words) K=128 tiles
#define RS2 132    // smem row stride (u32 words) K=256 tiles

// ---------------- scratch (device globals) ----------------
__device__ __nv_bfloat16 b_t2i  [NI_CAP * 128]; // i2
__device__ __nv_bfloat16 b_t2g  [NG_CAP * 128]; // g2
__device__ __nv_bfloat16 b_fi   [NI_CAP * 128]; // final_item
__device__ __nv_bfloat16 b_fg   [NG_CAP * 128]; // fus_group
__device__ __nv_bfloat16 b_gfi  [NG_CAP * 128]; // sigmoid(spmm(gi, fi))
__device__ __nv_bfloat16 b_first[NG_CAP * 128]; // first
__device__ __nv_bfloat16 b_fgrp [NG_CAP * 128]; // final_group
__device__ int g_rp_gi[NG_CAP + 1];
__device__ int g_rp_gg[NG_CAP + 1];

// ---------------- helpers ----------------
__device__ __forceinline__ float wredsum(float v) {
    #pragma unroll
    for (int o = 16; o; o >>= 1) v += __shfl_xor_sync(FULLMASK, v, o);
    return v;
}
__device__ __forceinline__ float sigf(float x) { return 1.0f / (1.0f + __expf(-x)); }
__device__ __forceinline__ void fma4(float4& a, const float4 w, const float x) {
    a.x = fmaf(w.x, x, a.x); a.y = fmaf(w.y, x, a.y);
    a.z = fmaf(w.z, x, a.z); a.w = fmaf(w.w, x, a.w);
}
__device__ __forceinline__ float4 inorm4(float4 v) {
    float s = v.x + v.y + v.z + v.w;
    float q = v.x*v.x + v.y*v.y + v.z*v.z + v.w*v.w;
    #pragma unroll
    for (int o = 16; o; o >>= 1) {
        s += __shfl_xor_sync(FULLMASK, s, o);
        q += __shfl_xor_sync(FULLMASK, q, o);
    }
    float m = s * (1.0f / 128.0f);
    float var = q * (1.0f / 128.0f) - m * m;
    float inv = rsqrtf(var + 1e-5f);
    return make_float4((v.x-m)*inv, (v.y-m)*inv, (v.z-m)*inv, (v.w-m)*inv);
}
__device__ __forceinline__ unsigned packbf(float lo, float hi) {
    __nv_bfloat162 h = __floats2bfloat162_rn(lo, hi);
    return *reinterpret_cast<unsigned*>(&h);
}
__device__ __forceinline__ float2 unpk(unsigned u) {
    __nv_bfloat162 h = *reinterpret_cast<__nv_bfloat162*>(&u);
    return __bfloat1622float2(h);
}
__device__ __forceinline__ float4 cvt4u(uint2 u) {
    float2 a = unpk(u.x), b = unpk(u.y);
    return make_float4(a.x, a.y, b.x, b.y);
}
__device__ __forceinline__ unsigned smaddr(const void* p) {
    unsigned a;
    asm("{ .reg .u64 t; cvta.to.shared.u64 t, %1; cvt.u32.u64 %0, t; }" : "=r"(a) : "l"(p));
    return a;
}
__device__ __forceinline__ void ldsm4(unsigned* r, unsigned addr) {
    asm volatile("ldmatrix.sync.aligned.m8n8.x4.shared.b16 {%0,%1,%2,%3}, [%4];"
        : "=r"(r[0]), "=r"(r[1]), "=r"(r[2]), "=r"(r[3]) : "r"(addr));
}
__device__ __forceinline__ void mma16(float* d, const unsigned* a, unsigned b0, unsigned b1) {
    asm volatile("mma.sync.aligned.m16n8k16.row.col.f32.bf16.bf16.f32 "
        "{%0,%1,%2,%3}, {%4,%5,%6,%7}, {%8,%9}, {%0,%1,%2,%3};"
        : "+f"(d[0]), "+f"(d[1]), "+f"(d[2]), "+f"(d[3])
        : "r"(a[0]), "r"(a[1]), "r"(a[2]), "r"(a[3]), "r"(b0), "r"(b1));
}
// warp tile M32 x N32, one k16 step: 2 A-ldsm + 2 B-ldsm + 8 mma
template<int RS>
__device__ __forceinline__ void mma_m32n32(float (&d)[2][4][4], unsigned aBase, unsigned bBase, int ks) {
    const unsigned kb = ks * 32;
    unsigned a0[4], a1[4];
    ldsm4(a0, aBase + kb);
    ldsm4(a1, aBase + 16*RS*4 + kb);
    #pragma unroll
    for (int q = 0; q < 2; q++) {
        unsigned b[4];
        ldsm4(b, bBase + q*16*RS*4 + kb);
        mma16(d[0][2*q],   a0, b[0], b[1]);
        mma16(d[1][2*q],   a1, b[0], b[1]);
        mma16(d[0][2*q+1], a0, b[2], b[3]);
        mma16(d[1][2*q+1], a1, b[2], b[3]);
    }
}

// warp spmm of one row, 8-deep MLP (k_score)
__device__ __forceinline__ float4 spmm_row(const int* __restrict__ rp, const int* __restrict__ cols,
                                           const float* __restrict__ vals,
                                           const __nv_bfloat16* __restrict__ Xb, int r, int lane)
{
    float4 a0 = make_float4(0.f,0.f,0.f,0.f), a1 = a0, a2 = a0, a3 = a0;
    int s = rp[r], e = rp[r + 1], ed = s;
    for (; ed + 7 < e; ed += 8) {
        int c[8]; float v[8]; uint2 u[8];
        #pragma unroll
        for (int j = 0; j < 8; j++) { c[j] = cols[ed+j]; v[j] = vals[ed+j]; }
        #pragma unroll
        for (int j = 0; j < 8; j++) u[j] = ((const uint2*)(Xb + (size_t)c[j] * 128))[lane];
        fma4(a0, cvt4u(u[0]), v[0]); fma4(a1, cvt4u(u[1]), v[1]);
        fma4(a2, cvt4u(u[2]), v[2]); fma4(a3, cvt4u(u[3]), v[3]);
        fma4(a0, cvt4u(u[4]), v[4]); fma4(a1, cvt4u(u[5]), v[5]);
        fma4(a2, cvt4u(u[6]), v[6]); fma4(a3, cvt4u(u[7]), v[7]);
    }
    for (; ed + 3 < e; ed += 4) {
        int c[4]; float v[4]; uint2 u[4];
        #pragma unroll
        for (int j = 0; j < 4; j++) { c[j] = cols[ed+j]; v[j] = vals[ed+j]; }
        #pragma unroll
        for (int j = 0; j < 4; j++) u[j] = ((const uint2*)(Xb + (size_t)c[j] * 128))[lane];
        fma4(a0, cvt4u(u[0]), v[0]); fma4(a1, cvt4u(u[1]), v[1]);
        fma4(a2, cvt4u(u[2]), v[2]); fma4(a3, cvt4u(u[3]), v[3]);
    }
    for (; ed < e; ed++) {
        uint2 u = ((const uint2*)(Xb + (size_t)cols[ed] * 128))[lane];
        fma4(a0, cvt4u(u), vals[ed]);
    }
    a0.x += a1.x + a2.x + a3.x; a0.y += a1.y + a2.y + a3.y;
    a0.z += a1.z + a2.z + a3.z; a0.w += a1.w + a2.w + a3.w;
    return a0;
}

// paired-row spmm: two rows gathered with interleaved batches
__device__ __forceinline__ void spmm_pair(const int* __restrict__ rp, const int* __restrict__ cols,
                                          const float* __restrict__ vals,
                                          const __nv_bfloat16* __restrict__ Xb,
                                          int r0, int r1, int N, int lane,
                                          float4& out0, float4& out1)
{
    float4 p0 = make_float4(0.f,0.f,0.f,0.f), p1 = p0, q0 = p0, q1 = p0;
    int e0 = 0, e1 = 0, ed0 = 0, ed1 = 0;
    if (r0 < N) { ed0 = rp[r0]; e0 = rp[r0 + 1]; }
    if (r1 < N) { ed1 = rp[r1]; e1 = rp[r1 + 1]; }
    while (ed0 + 3 < e0 && ed1 + 3 < e1) {
        int c0[4], c1[4]; float v0[4], v1[4]; uint2 u0[4], u1[4];
        #pragma unroll
        for (int j = 0; j < 4; j++) { c0[j] = cols[ed0+j]; v0[j] = vals[ed0+j]; }
        #pragma unroll
        for (int j = 0; j < 4; j++) { c1[j] = cols[ed1+j]; v1[j] = vals[ed1+j]; }
        #pragma unroll
        for (int j = 0; j < 4; j++) u0[j] = ((const uint2*)(Xb + (size_t)c0[j] * 128))[lane];
        #pragma unroll
        for (int j = 0; j < 4; j++) u1[j] = ((const uint2*)(Xb + (size_t)c1[j] * 128))[lane];
        fma4(p0, cvt4u(u0[0]), v0[0]); fma4(p1, cvt4u(u0[1]), v0[1]);
        fma4(p0, cvt4u(u0[2]), v0[2]); fma4(p1, cvt4u(u0[3]), v0[3]);
        fma4(q0, cvt4u(u1[0]), v1[0]); fma4(q1, cvt4u(u1[1]), v1[1]);
        fma4(q0, cvt4u(u1[2]), v1[2]); fma4(q1, cvt4u(u1[3]), v1[3]);
        ed0 += 4; ed1 += 4;
    }
    for (; ed0 + 3 < e0; ed0 += 4) {
        int c[4]; float v[4]; uint2 u[4];
        #pragma unroll
        for (int j = 0; j < 4; j++) { c[j] = cols[ed0+j]; v[j] = vals[ed0+j]; }
        #pragma unroll
        for (int j = 0; j < 4; j++) u[j] = ((const uint2*)(Xb + (size_t)c[j] * 128))[lane];
        fma4(p0, cvt4u(u[0]), v[0]); fma4(p1, cvt4u(u[1]), v[1]);
        fma4(p0, cvt4u(u[2]), v[2]); fma4(p1, cvt4u(u[3]), v[3]);
    }
    for (; ed0 < e0; ed0++) {
        uint2 u = ((const uint2*)(Xb + (size_t)cols[ed0] * 128))[lane];
        fma4(p0, cvt4u(u), vals[ed0]);
    }
    for (; ed1 + 3 < e1; ed1 += 4) {
        int c[4]; float v[4]; uint2 u[4];
        #pragma unroll
        for (int j = 0; j < 4; j++) { c[j] = cols[ed1+j]; v[j] = vals[ed1+j]; }
        #pragma unroll
        for (int j = 0; j < 4; j++) u[j] = ((const uint2*)(Xb + (size_t)c[j] * 128))[lane];
        fma4(q0, cvt4u(u[0]), v[0]); fma4(q1, cvt4u(u[1]), v[1]);
        fma4(q0, cvt4u(u[2]), v[2]); fma4(q1, cvt4u(u[3]), v[3]);
    }
    for (; ed1 < e1; ed1++) {
        uint2 u = ((const uint2*)(Xb + (size_t)cols[ed1] * 128))[lane];
        fma4(q0, cvt4u(u), vals[ed1]);
    }
    out0 = make_float4(p0.x+p1.x, p0.y+p1.y, p0.z+p1.z, p0.w+p1.w);
    out1 = make_float4(q0.x+q1.x, q0.y+q1.y, q0.z+q1.z, q0.w+q1.w);
}

// ---------------- row_ptr from sorted COO rows ----------------
__global__ void k_rowptr(const int* __restrict__ rows, int E, int N, int* __restrict__ rp) {
    for (int e = blockIdx.x * blockDim.x + threadIdx.x; e < E; e += gridDim.x * blockDim.x) {
        int r = rows[e];
        int prev = (e == 0) ? -1 : rows[e - 1];
        for (int rr = prev + 1; rr <= r; rr++) rp[rr] = e;
        if (e == E - 1) for (int rr = r + 1; rr <= N; rr++) rp[rr] = E;
    }
}

// ======== merged nln (item+group): out = inorm(inorm(X)@W^T+b), M64 tile, 3/SM ========
__global__ void __launch_bounds__(256, 3)
k_nln(const float* __restrict__ X1, int N1, const float* __restrict__ X2, int N2,
      const float* __restrict__ W, const float* __restrict__ Bv,
      __nv_bfloat16* __restrict__ out1, __nv_bfloat16* __restrict__ out2)
{
    extern __shared__ __align__(16) unsigned smu[];
    unsigned* Asu = smu;                 // 64*RS1
    unsigned* Wsu = Asu + 64 * RS1;      // 128*RS1
    float*    biasf = (float*)(Wsu + 128 * RS1);
    const int tid = threadIdx.x, lane = tid & 31, w = tid >> 5;
    const int qr = lane >> 2, qc = lane & 3;
    const int mbase = (w >> 2) * 32, nbase = (w & 3) * 32;

    for (int i = tid; i < 128 * 64; i += 256) {
        float2 wv = ((const float2*)W)[i];
        Wsu[(i >> 6) * RS1 + (i & 63)] = packbf(wv.x, wv.y);
    }
    if (tid < 128) biasf[tid] = Bv[tid];

    const unsigned aBase = smaddr(Asu) + (((mbase + (lane & 15)) * RS1 + ((lane >> 4) << 2)) << 2);
    const unsigned bBase = smaddr(Wsu) + (((nbase + ((lane >> 4) << 3) + (lane & 7)) * RS1 + (((lane >> 3) & 1) << 2)) << 2);

    const int T1 = (N1 + 63) >> 6, T2 = (N2 + 63) >> 6;
    for (int tt = blockIdx.x; tt < T1 + T2; tt += gridDim.x) {
        const bool seg1 = tt < T1;
        const float* X = seg1 ? X1 : X2;
        __nv_bfloat16* outb = seg1 ? out1 : out2;
        const int N = seg1 ? N1 : N2;
        const int tile = seg1 ? tt : tt - T1;
        __syncthreads();
        #pragma unroll 4
        for (int i = 0; i < 8; i++) {
            int rl = w * 8 + i, r = tile * 64 + rl;
            float4 v = make_float4(0.f, 0.f, 0.f, 0.f);
            if (r < N) { v = *(const float4*)(X + (size_t)r * 128 + lane * 4); v = inorm4(v); }
            uint2 st; st.x = packbf(v.x, v.y); st.y = packbf(v.z, v.w);
            *(uint2*)(Asu + rl * RS1 + lane * 2) = st;
        }
        __syncthreads();
        float d[2][4][4];
        #pragma unroll
        for (int t = 0; t < 2; t++)
            #pragma unroll
            for (int nt = 0; nt < 4; nt++)
                #pragma unroll
                for (int j = 0; j < 4; j++) d[t][nt][j] = 0.f;
        #pragma unroll
        for (int ks = 0; ks < 8; ks++) mma_m32n32<RS1>(d, aBase, bBase, ks);
        __syncthreads();
        #pragma unroll
        for (int t = 0; t < 2; t++)
            #pragma unroll
            for (int nt = 0; nt < 4; nt++) {
                int col = nbase + nt * 8 + qc * 2;
                float b0 = biasf[col], b1 = biasf[col + 1];
                int row0 = mbase + t * 16 + qr;
                int wj = col >> 1;
                Asu[row0 * RS1 + wj]       = packbf(d[t][nt][0] + b0, d[t][nt][1] + b1);
                Asu[(row0 + 8) * RS1 + wj] = packbf(d[t][nt][2] + b0, d[t][nt][3] + b1);
            }
        __syncthreads();
        #pragma unroll 4
        for (int i = 0; i < 8; i++) {
            int rl = w * 8 + i, r = tile * 64 + rl;
            if (r < N) {
                uint2 u = *(const uint2*)(Asu + rl * RS1 + lane * 2);
                float2 la = unpk(u.x), lb = unpk(u.y);
                float4 o = inorm4(make_float4(la.x, la.y, lb.x, lb.y));
                uint2 st; st.x = packbf(o.x, o.y); st.y = packbf(o.z, o.w);
                *(uint2*)(outb + (size_t)r * 128 + lane * 4) = st;
            }
        }
    }
}

// ==== merged fus: full-resident W (K=256, N=128), M64 tile, warp M32xN32, bf16 out only ====
__global__ void __launch_bounds__(256, 2)
k_fus(const float* __restrict__ EMB1, const __nv_bfloat16* __restrict__ X21,
      const float* __restrict__ W1, const float* __restrict__ B1,
      __nv_bfloat16* __restrict__ bout1, int N1,
      const float* __restrict__ EMB2, const __nv_bfloat16* __restrict__ X22,
      const float* __restrict__ W2, const float* __restrict__ B2,
      __nv_bfloat16* __restrict__ bout2, int N2,
      int SPLIT)
{
    extern __shared__ __align__(16) unsigned smu[];
    unsigned* Asu = smu;                 // 64*RS2
    unsigned* Wsu = Asu + 64 * RS2;      // 128*RS2
    float*    biasf = (float*)(Wsu + 128 * RS2);
    const int tid = threadIdx.x, lane = tid & 31, w = tid >> 5;
    const int qr = lane >> 2, qc = lane & 3;
    const int mbase = (w >> 2) * 32, nbase = (w & 3) * 32;

    const bool seg1 = (int)blockIdx.x < SPLIT;
    const int localBid = seg1 ? blockIdx.x : blockIdx.x - SPLIT;
    const int nb       = seg1 ? SPLIT : gridDim.x - SPLIT;
    const float* EMB = seg1 ? EMB1 : EMB2;
    const __nv_bfloat16* X2 = seg1 ? X21 : X22;
    const float* W  = seg1 ? W1 : W2;
    const float* Bv = seg1 ? B1 : B2;
    __nv_bfloat16* bout = seg1 ? bout1 : bout2;
    const int N = seg1 ? N1 : N2;

    for (int i = tid; i < 128 * 128; i += 256) {
        int n = i >> 7, j = i & 127;
        float2 wv = ((const float2*)W)[(size_t)n * 128 + j];
        Wsu[n * RS2 + j] = packbf(wv.x, wv.y);
    }
    if (tid < 128) biasf[tid] = Bv[tid];

    const unsigned aBase = smaddr(Asu) + (((mbase + (lane & 15)) * RS2 + ((lane >> 4) << 2)) << 2);
    const unsigned bBase = smaddr(Wsu) + (((nbase + ((lane >> 4) << 3) + (lane & 7)) * RS2 + (((lane >> 3) & 1) << 2)) << 2);

    const int ntiles = (N + 63) >> 6;
    for (int tile = localBid; tile < ntiles; tile += nb) {
        __syncthreads();
        #pragma unroll 4
        for (int i = 0; i < 8; i++) {
            int rl = w * 8 + i, r = tile * 64 + rl;
            float4 ve = make_float4(0.f,0.f,0.f,0.f);
            uint2 ux = make_uint2(0u, 0u);
            if (r < N) {
                ve = *(const float4*)(EMB + (size_t)r * 128 + lane * 4);
                ux = ((const uint2*)(X2 + (size_t)r * 128))[lane];
            }
            unsigned* rowp = Asu + rl * RS2;
            uint2 st; st.x = packbf(ve.x, ve.y); st.y = packbf(ve.z, ve.w);
            *(uint2*)(rowp + lane * 2)      = st;
            *(uint2*)(rowp + 64 + lane * 2) = ux;
        }
        __syncthreads();
        float d[2][4][4];
        #pragma unroll
        for (int t = 0; t < 2; t++)
            #pragma unroll
            for (int nt = 0; nt < 4; nt++)
                #pragma unroll
                for (int j = 0; j < 4; j++) d[t][nt][j] = 0.f;
        #pragma unroll
        for (int ks = 0; ks < 16; ks++) mma_m32n32<RS2>(d, aBase, bBase, ks);
        #pragma unroll
        for (int t = 0; t < 2; t++)
            #pragma unroll
            for (int nt = 0; nt < 4; nt++) {
                int col = nbase + nt * 8 + qc * 2;
                float b0 = biasf[col], b1 = biasf[col + 1];
                #pragma unroll
                for (int h = 0; h < 2; h++) {
                    int r = tile * 64 + mbase + t * 16 + qr + h * 8;
                    if (r < N) {
                        float s0 = sigf(d[t][nt][2*h]   + b0);
                        float s1 = sigf(d[t][nt][2*h+1] + b1);
                        *(unsigned*)(bout + (size_t)r * 128 + col) = packbf(s0, s1);
                    }
                }
            }
    }
}

// ==== social layer (+ optional fused combine, all bf16) + optional tail spmm ====
__global__ void __launch_bounds__(256, 3)
k_social(const int* __restrict__ rp, const int* __restrict__ cols, const float* __restrict__ vals,
         const __nv_bfloat16* __restrict__ Xb, const float* __restrict__ W, const float* __restrict__ Bv,
         __nv_bfloat16* __restrict__ bout,
         const __nv_bfloat16* __restrict__ addA, const __nv_bfloat16* __restrict__ addB, int N,
         const int* __restrict__ t_rp, const int* __restrict__ t_cols, const float* __restrict__ t_vals,
         const __nv_bfloat16* __restrict__ t_X, __nv_bfloat16* __restrict__ t_out, int t_N)
{
    extern __shared__ __align__(16) unsigned smu[];
    unsigned* Asu = smu;                 // 64*RS1
    unsigned* Wsu = Asu + 64 * RS1;      // 128*RS1
    float*    biasf = (float*)(Wsu + 128 * RS1);
    const int tid = threadIdx.x, lane = tid & 31, w = tid >> 5;
    const int qr = lane >> 2, qc = lane & 3;
    const int mbase = (w >> 2) * 32, nbase = (w & 3) * 32;

    for (int i = tid; i < 128 * 64; i += 256) {
        float2 wv = ((const float2*)W)[i];
        Wsu[(i >> 6) * RS1 + (i & 63)] = packbf(wv.x, wv.y);
    }
    if (tid < 128) biasf[tid] = Bv[tid];

    const unsigned aBase = smaddr(Asu) + (((mbase + (lane & 15)) * RS1 + ((lane >> 4) << 2)) << 2);
    const unsigned bBase = smaddr(Wsu) + (((nbase + ((lane >> 4) << 3) + (lane & 7)) * RS1 + (((lane >> 3) & 1) << 2)) << 2);

    int ntiles = (N + 63) >> 6;
    for (int tile = blockIdx.x; tile < ntiles; tile += gridDim.x) {
        __syncthreads();
        for (int i = 0; i < 8; i += 2) {
            int rl = w * 8 + i;
            int r0 = tile * 64 + rl, r1 = r0 + 1;
            float4 o0, o1;
            spmm_pair(rp, cols, vals, Xb, r0, r1, N, lane, o0, o1);
            uint2 st0; st0.x = packbf(o0.x, o0.y); st0.y = packbf(o0.z, o0.w);
            uint2 st1; st1.x = packbf(o1.x, o1.y); st1.y = packbf(o1.z, o1.w);
            *(uint2*)(Asu + rl * RS1 + lane * 2)       = st0;
            *(uint2*)(Asu + (rl + 1) * RS1 + lane * 2) = st1;
        }
        __syncthreads();
        float d[2][4][4];
        #pragma unroll
        for (int t = 0; t < 2; t++)
            #pragma unroll
            for (int nt = 0; nt < 4; nt++)
                #pragma unroll
                for (int j = 0; j < 4; j++) d[t][nt][j] = 0.f;
        #pragma unroll
        for (int ks = 0; ks < 8; ks++) mma_m32n32<RS1>(d, aBase, bBase, ks);
        #pragma unroll
        for (int t = 0; t < 2; t++)
            #pragma unroll
            for (int nt = 0; nt < 4; nt++) {
                int col = nbase + nt * 8 + qc * 2;
                float b0 = biasf[col], b1 = biasf[col + 1];
                #pragma unroll
                for (int h = 0; h < 2; h++) {
                    int r = tile * 64 + mbase + t * 16 + qr + h * 8;
                    if (r < N) {
                        float s0 = sigf(fmaxf(d[t][nt][2*h]   + b0, 0.f));
                        float s1 = sigf(fmaxf(d[t][nt][2*h+1] + b1, 0.f));
                        if (addA) {
                            float2 pa = unpk(*(const unsigned*)(addA + (size_t)r * 128 + col));
                            float2 pb = unpk(*(const unsigned*)(addB + (size_t)r * 128 + col));
                            s0 = sigf((s0 + pa.x + pb.x) * 0.5f);
                            s1 = sigf((s1 + pa.y + pb.y) * 0.5f);
                        }
                        *(unsigned*)(bout + (size_t)r * 128 + col) = packbf(s0, s1);
                    }
                }
            }
    }
    // tail: independent spmm (g_from_items), paired rows, sigmoid epilogue, bf16 out
    if (t_out) {
        for (int base = blockIdx.x * 16 + w * 2; base < t_N; base += gridDim.x * 16) {
            int r0 = base, r1 = base + 1;
            float4 o0, o1;
            spmm_pair(t_rp, t_cols, t_vals, t_X, r0, r1, t_N, lane, o0, o1);
            uint2 st0; st0.x = packbf(sigf(o0.x), sigf(o0.y)); st0.y = packbf(sigf(o0.z), sigf(o0.w));
            *(uint2*)(t_out + (size_t)r0 * 128 + lane * 4) = st0;
            if (r1 < t_N) {
                uint2 st1; st1.x = packbf(sigf(o1.x), sigf(o1.y)); st1.y = packbf(sigf(o1.z), sigf(o1.w));
                *(uint2*)(t_out + (size_t)r1 * 128 + lane * 4) = st1;
            }
        }
    }
}

// ---------------- scoring with fused all_neighbors spmm (bf16 inputs) ----------------
__global__ void __launch_bounds__(256)
k_score(const int* __restrict__ gid, const int* __restrict__ iid,
        const __nv_bfloat16* __restrict__ FG, const __nv_bfloat16* __restrict__ FI,
        const int* __restrict__ rp, const int* __restrict__ cols, const float* __restrict__ vals,
        float* __restrict__ out, int B)
{
    int widx = (blockIdx.x * blockDim.x + threadIdx.x) >> 5;
    int lane = threadIdx.x & 31;
    if (widx >= B) return;
    int g = gid[widx], it = iid[widx];
    float4 ge = cvt4u(((const uint2*)(FG + (size_t)g  * 128))[lane]);
    float4 ie = cvt4u(((const uint2*)(FI + (size_t)it * 128))[lane]);
    float4 ne = spmm_row(rp, cols, vals, FG, g, lane);
    float d1 = ge.x*ie.x + ge.y*ie.y + ge.z*ie.z + ge.w*ie.w;
    float d2 = ne.x*(ge.x+ie.x) + ne.y*(ge.y+ie.y) + ne.z*(ge.z+ie.z) + ne.w*(ge.w+ie.w);
    d1 = wredsum(d1); d2 = wredsum(d2);
    if (lane == 0) { out[widx] = d1; out[B + widx] = d2; }
}

// ---------------- launch ----------------
extern "C" void kernel_launch(void* const* d_in, const int* in_sizes, int n_in,
                              void* d_out, int out_size)
{
    const int*   group_ids   = (const int*)d_in[0];
    const int*   item_ids    = (const int*)d_in[1];
    const int*   gi_rows     = (const int*)d_in[2];
    const int*   gi_cols     = (const int*)d_in[3];
    const float* gi_vals     = (const float*)d_in[4];
    const int*   gg_rows     = (const int*)d_in[5];
    const int*   gg_cols     = (const int*)d_in[6];
    const float* gg_vals     = (const float*)d_in[7];
    const float* g_feat      = (const float*)d_in[8];
    const float* i_feat      = (const float*)d_in[9];
    const float* emb_group   = (const float*)d_in[10];
    const float* emb_item    = (const float*)d_in[11];
    const float* W_w         = (const float*)d_in[12];
    const float* W_b         = (const float*)d_in[13];
    const float* red_w       = (const float*)d_in[14];
    const float* red_b       = (const float*)d_in[15];
    const float* item_fus_w  = (const float*)d_in[16];
    const float* item_fus_b  = (const float*)d_in[17];
    const float* group_fus_w = (const float*)d_in[18];
    const float* group_fus_b = (const float*)d_in[19];
    float* out = (float*)d_out;

    int B   = in_sizes[0];
    int Egi = in_sizes[2];
    int Egg = in_sizes[5];
    int NG  = in_sizes[8] / 128;  if (NG > NG_CAP) NG = NG_CAP;
    int NI  = in_sizes[9] / 128;  if (NI > NI_CAP) NI = NI_CAP;

    __nv_bfloat16 *pb_t2i, *pb_t2g, *pb_fi, *pb_fg, *pb_gfi, *pb_first, *pb_fgrp;
    int *p_rp_gi, *p_rp_gg;
    cudaGetSymbolAddress((void**)&pb_t2i,   b_t2i);
    cudaGetSymbolAddress((void**)&pb_t2g,   b_t2g);
    cudaGetSymbolAddress((void**)&pb_fi,    b_fi);
    cudaGetSymbolAddress((void**)&pb_fg,    b_fg);
    cudaGetSymbolAddress((void**)&pb_gfi,   b_gfi);
    cudaGetSymbolAddress((void**)&pb_first, b_first);
    cudaGetSymbolAddress((void**)&pb_fgrp,  b_fgrp);
    cudaGetSymbolAddress((void**)&p_rp_gi,  g_rp_gi);
    cudaGetSymbolAddress((void**)&p_rp_gg,  g_rp_gg);

    size_t smemN = (size_t)(64 * RS1 + 128 * RS1) * 4 + 512;    // ~52.7 KB (3/SM)
    size_t smemF = (size_t)(64 * RS2 + 128 * RS2) * 4 + 512;    // ~101.9 KB (2/SM)
    cudaFuncSetAttribute(k_nln,    cudaFuncAttributeMaxDynamicSharedMemorySize, (int)smemN);
    cudaFuncSetAttribute(k_fus,    cudaFuncAttributeMaxDynamicSharedMemorySize, (int)smemF);
    cudaFuncSetAttribute(k_social, cudaFuncAttributeMaxDynamicSharedMemorySize, (int)smemN);

    const int PGRID2 = 296;   // 2 blocks/SM
    const int PGRID3 = 444;   // 3 blocks/SM
    const int SPLIT  = 197;   // k_fus item blocks (NI:NG ≈ 2:1)

    k_rowptr<<<1024, 256>>>(gi_rows, Egi, NG, p_rp_gi);
    k_rowptr<<<1024, 256>>>(gg_rows, Egg, NG, p_rp_gg);

    // merged nln: i2 and g2 (same weights)
    k_nln<<<PGRID3, 256, smemN>>>(i_feat, NI, g_feat, NG, red_w, red_b, pb_t2i, pb_t2g);

    // merged fus: final_item and fus_group (bf16 outputs only)
    k_fus<<<PGRID2, 256, smemF>>>(emb_item,  pb_t2i, item_fus_w,  item_fus_b,  pb_fi, NI,
                                  emb_group, pb_t2g, group_fus_w, group_fus_b, pb_fg, NG,
                                  SPLIT);

    // social layer 1 + tail spmm_gi (g_from_items)
    k_social<<<PGRID3, 256, smemN>>>(p_rp_gg, gg_cols, gg_vals, pb_fg, W_w, W_b,
                                     pb_first, nullptr, nullptr, NG,
                                     p_rp_gi, gi_cols, gi_vals, pb_fi, pb_gfi, NG);

    // social layer 2 fused with final_group combine
    k_social<<<PGRID3, 256, smemN>>>(p_rp_gg, gg_cols, gg_vals, pb_first, W_w, W_b,
                                     pb_fgrp, pb_gfi, pb_first, NG,
                                     nullptr, nullptr, nullptr, nullptr, nullptr, 0);

    // scoring with fused all_neighbors spmm
    k_score<<<(B + 7) / 8, 256>>>(group_ids, item_ids, pb_fgrp, pb_fi,
                                  p_rp_gg, gg_cols, gg_vals, out, B);
}

// round 12
// speedup vs baseline: 3.1804x; 1.0762x over previous
#include <cuda_runtime.h>
#include <cuda_bf16.h>
#include <cstdio>

#define FULLMASK 0xffffffffu
#define NG_CAP 50000
#define NI_CAP 100000
#define RS1 68     // smem row stride (u32 words) K=128 tiles
#define RS2 132    // smem row stride (u32 words) K=256 tiles

// ---------------- scratch (device globals) ----------------
__device__ __nv_bfloat16 b_fi   [NI_CAP * 128]; // final_item
__device__ __nv_bfloat16 b_fg   [NG_CAP * 128]; // fus_group
__device__ __nv_bfloat16 b_gfi  [NG_CAP * 128]; // sigmoid(spmm(gi, fi))
__device__ __nv_bfloat16 b_first[NG_CAP * 128]; // first
__device__ __nv_bfloat16 b_fgrp [NG_CAP * 128]; // final_group
__device__ int g_rp_gi[NG_CAP + 1];
__device__ int g_rp_gg[NG_CAP + 1];

// ---------------- helpers ----------------
__device__ __forceinline__ float wredsum(float v) {
    #pragma unroll
    for (int o = 16; o; o >>= 1) v += __shfl_xor_sync(FULLMASK, v, o);
    return v;
}
__device__ __forceinline__ float sigf(float x) { return 1.0f / (1.0f + __expf(-x)); }
__device__ __forceinline__ void fma4(float4& a, const float4 w, const float x) {
    a.x = fmaf(w.x, x, a.x); a.y = fmaf(w.y, x, a.y);
    a.z = fmaf(w.z, x, a.z); a.w = fmaf(w.w, x, a.w);
}
__device__ __forceinline__ float4 inorm4(float4 v) {
    float s = v.x + v.y + v.z + v.w;
    float q = v.x*v.x + v.y*v.y + v.z*v.z + v.w*v.w;
    #pragma unroll
    for (int o = 16; o; o >>= 1) {
        s += __shfl_xor_sync(FULLMASK, s, o);
        q += __shfl_xor_sync(FULLMASK, q, o);
    }
    float m = s * (1.0f / 128.0f);
    float var = q * (1.0f / 128.0f) - m * m;
    float inv = rsqrtf(var + 1e-5f);
    return make_float4((v.x-m)*inv, (v.y-m)*inv, (v.z-m)*inv, (v.w-m)*inv);
}
__device__ __forceinline__ unsigned packbf(float lo, float hi) {
    __nv_bfloat162 h = __floats2bfloat162_rn(lo, hi);
    return *reinterpret_cast<unsigned*>(&h);
}
__device__ __forceinline__ float2 unpk(unsigned u) {
    __nv_bfloat162 h = *reinterpret_cast<__nv_bfloat162*>(&u);
    return __bfloat1622float2(h);
}
__device__ __forceinline__ float4 cvt4u(uint2 u) {
    float2 a = unpk(u.x), b = unpk(u.y);
    return make_float4(a.x, a.y, b.x, b.y);
}
__device__ __forceinline__ unsigned smaddr(const void* p) {
    unsigned a;
    asm("{ .reg .u64 t; cvta.to.shared.u64 t, %1; cvt.u32.u64 %0, t; }" : "=r"(a) : "l"(p));
    return a;
}
__device__ __forceinline__ void ldsm4(unsigned* r, unsigned addr) {
    asm volatile("ldmatrix.sync.aligned.m8n8.x4.shared.b16 {%0,%1,%2,%3}, [%4];"
        : "=r"(r[0]), "=r"(r[1]), "=r"(r[2]), "=r"(r[3]) : "r"(addr));
}
__device__ __forceinline__ void mma16(float* d, const unsigned* a, unsigned b0, unsigned b1) {
    asm volatile("mma.sync.aligned.m16n8k16.row.col.f32.bf16.bf16.f32 "
        "{%0,%1,%2,%3}, {%4,%5,%6,%7}, {%8,%9}, {%0,%1,%2,%3};"
        : "+f"(d[0]), "+f"(d[1]), "+f"(d[2]), "+f"(d[3])
        : "r"(a[0]), "r"(a[1]), "r"(a[2]), "r"(a[3]), "r"(b0), "r"(b1));
}
// warp tile M32 x N32, one k16 step; separate A/B smem row strides
template<int RSA, int RSB>
__device__ __forceinline__ void mma_g(float (&d)[2][4][4], unsigned aBase, unsigned bBase, int ks) {
    const unsigned kb = ks * 32;
    unsigned a0[4], a1[4];
    ldsm4(a0, aBase + kb);
    ldsm4(a1, aBase + 16*RSA*4 + kb);
    #pragma unroll
    for (int q = 0; q < 2; q++) {
        unsigned b[4];
        ldsm4(b, bBase + q*16*RSB*4 + kb);
        mma16(d[0][2*q],   a0, b[0], b[1]);
        mma16(d[1][2*q],   a1, b[0], b[1]);
        mma16(d[0][2*q+1], a0, b[2], b[3]);
        mma16(d[1][2*q+1], a1, b[2], b[3]);
    }
}

// warp spmm of one row, 8-deep MLP (k_score)
__device__ __forceinline__ float4 spmm_row(const int* __restrict__ rp, const int* __restrict__ cols,
                                           const float* __restrict__ vals,
                                           const __nv_bfloat16* __restrict__ Xb, int r, int lane)
{
    float4 a0 = make_float4(0.f,0.f,0.f,0.f), a1 = a0, a2 = a0, a3 = a0;
    int s = rp[r], e = rp[r + 1], ed = s;
    for (; ed + 7 < e; ed += 8) {
        int c[8]; float v[8]; uint2 u[8];
        #pragma unroll
        for (int j = 0; j < 8; j++) { c[j] = cols[ed+j]; v[j] = vals[ed+j]; }
        #pragma unroll
        for (int j = 0; j < 8; j++) u[j] = ((const uint2*)(Xb + (size_t)c[j] * 128))[lane];
        fma4(a0, cvt4u(u[0]), v[0]); fma4(a1, cvt4u(u[1]), v[1]);
        fma4(a2, cvt4u(u[2]), v[2]); fma4(a3, cvt4u(u[3]), v[3]);
        fma4(a0, cvt4u(u[4]), v[4]); fma4(a1, cvt4u(u[5]), v[5]);
        fma4(a2, cvt4u(u[6]), v[6]); fma4(a3, cvt4u(u[7]), v[7]);
    }
    for (; ed + 3 < e; ed += 4) {
        int c[4]; float v[4]; uint2 u[4];
        #pragma unroll
        for (int j = 0; j < 4; j++) { c[j] = cols[ed+j]; v[j] = vals[ed+j]; }
        #pragma unroll
        for (int j = 0; j < 4; j++) u[j] = ((const uint2*)(Xb + (size_t)c[j] * 128))[lane];
        fma4(a0, cvt4u(u[0]), v[0]); fma4(a1, cvt4u(u[1]), v[1]);
        fma4(a2, cvt4u(u[2]), v[2]); fma4(a3, cvt4u(u[3]), v[3]);
    }
    for (; ed < e; ed++) {
        uint2 u = ((const uint2*)(Xb + (size_t)cols[ed] * 128))[lane];
        fma4(a0, cvt4u(u), vals[ed]);
    }
    a0.x += a1.x + a2.x + a3.x; a0.y += a1.y + a2.y + a3.y;
    a0.z += a1.z + a2.z + a3.z; a0.w += a1.w + a2.w + a3.w;
    return a0;
}

// paired-row spmm
__device__ __forceinline__ void spmm_pair(const int* __restrict__ rp, const int* __restrict__ cols,
                                          const float* __restrict__ vals,
                                          const __nv_bfloat16* __restrict__ Xb,
                                          int r0, int r1, int N, int lane,
                                          float4& out0, float4& out1)
{
    float4 p0 = make_float4(0.f,0.f,0.f,0.f), p1 = p0, q0 = p0, q1 = p0;
    int e0 = 0, e1 = 0, ed0 = 0, ed1 = 0;
    if (r0 < N) { ed0 = rp[r0]; e0 = rp[r0 + 1]; }
    if (r1 < N) { ed1 = rp[r1]; e1 = rp[r1 + 1]; }
    while (ed0 + 3 < e0 && ed1 + 3 < e1) {
        int c0[4], c1[4]; float v0[4], v1[4]; uint2 u0[4], u1[4];
        #pragma unroll
        for (int j = 0; j < 4; j++) { c0[j] = cols[ed0+j]; v0[j] = vals[ed0+j]; }
        #pragma unroll
        for (int j = 0; j < 4; j++) { c1[j] = cols[ed1+j]; v1[j] = vals[ed1+j]; }
        #pragma unroll
        for (int j = 0; j < 4; j++) u0[j] = ((const uint2*)(Xb + (size_t)c0[j] * 128))[lane];
        #pragma unroll
        for (int j = 0; j < 4; j++) u1[j] = ((const uint2*)(Xb + (size_t)c1[j] * 128))[lane];
        fma4(p0, cvt4u(u0[0]), v0[0]); fma4(p1, cvt4u(u0[1]), v0[1]);
        fma4(p0, cvt4u(u0[2]), v0[2]); fma4(p1, cvt4u(u0[3]), v0[3]);
        fma4(q0, cvt4u(u1[0]), v1[0]); fma4(q1, cvt4u(u1[1]), v1[1]);
        fma4(q0, cvt4u(u1[2]), v1[2]); fma4(q1, cvt4u(u1[3]), v1[3]);
        ed0 += 4; ed1 += 4;
    }
    for (; ed0 + 3 < e0; ed0 += 4) {
        int c[4]; float v[4]; uint2 u[4];
        #pragma unroll
        for (int j = 0; j < 4; j++) { c[j] = cols[ed0+j]; v[j] = vals[ed0+j]; }
        #pragma unroll
        for (int j = 0; j < 4; j++) u[j] = ((const uint2*)(Xb + (size_t)c[j] * 128))[lane];
        fma4(p0, cvt4u(u[0]), v[0]); fma4(p1, cvt4u(u[1]), v[1]);
        fma4(p0, cvt4u(u[2]), v[2]); fma4(p1, cvt4u(u[3]), v[3]);
    }
    for (; ed0 < e0; ed0++) {
        uint2 u = ((const uint2*)(Xb + (size_t)cols[ed0] * 128))[lane];
        fma4(p0, cvt4u(u), vals[ed0]);
    }
    for (; ed1 + 3 < e1; ed1 += 4) {
        int c[4]; float v[4]; uint2 u[4];
        #pragma unroll
        for (int j = 0; j < 4; j++) { c[j] = cols[ed1+j]; v[j] = vals[ed1+j]; }
        #pragma unroll
        for (int j = 0; j < 4; j++) u[j] = ((const uint2*)(Xb + (size_t)c[j] * 128))[lane];
        fma4(q0, cvt4u(u[0]), v[0]); fma4(q1, cvt4u(u[1]), v[1]);
        fma4(q0, cvt4u(u[2]), v[2]); fma4(q1, cvt4u(u[3]), v[3]);
    }
    for (; ed1 < e1; ed1++) {
        uint2 u = ((const uint2*)(Xb + (size_t)cols[ed1] * 128))[lane];
        fma4(q0, cvt4u(u), vals[ed1]);
    }
    out0 = make_float4(p0.x+p1.x, p0.y+p1.y, p0.z+p1.z, p0.w+p1.w);
    out1 = make_float4(q0.x+q1.x, q0.y+q1.y, q0.z+q1.z, q0.w+q1.w);
}

// ---------------- row_ptr from sorted COO rows ----------------
__global__ void k_rowptr(const int* __restrict__ rows, int E, int N, int* __restrict__ rp) {
    for (int e = blockIdx.x * blockDim.x + threadIdx.x; e < E; e += gridDim.x * blockDim.x) {
        int r = rows[e];
        int prev = (e == 0) ? -1 : rows[e - 1];
        for (int rr = prev + 1; rr <= r; rr++) rp[rr] = e;
        if (e == E - 1) for (int rr = r + 1; rr <= N; rr++) rp[rr] = E;
    }
}

// ======================================================================
// k_nf: fused  t2 = inorm(inorm(X)@Wr^T+br);  out = sigmoid([EMB,t2]@Wf^T+bf)
// 512 threads, 1 block/SM. M128 tile, 16 warps (4x4 of M32xN32).
// A row layout (RS2): words [0,64) = emb bf16, words [64,128) = t2 slot.
// Segments: blocks [0,SPLIT) items, rest groups (per-segment Wf).
// ======================================================================
__global__ void __launch_bounds__(512, 1)
k_nf(const float* __restrict__ X1, const float* __restrict__ EMB1,
     const float* __restrict__ WF1, const float* __restrict__ BF1,
     __nv_bfloat16* __restrict__ out1, int N1,
     const float* __restrict__ X2, const float* __restrict__ EMB2,
     const float* __restrict__ WF2, const float* __restrict__ BF2,
     __nv_bfloat16* __restrict__ out2, int N2,
     const float* __restrict__ WR, const float* __restrict__ BR, int SPLIT)
{
    extern __shared__ __align__(16) unsigned smu[];
    unsigned* Asu = smu;                   // 128*RS2
    unsigned* W1u = Asu + 128 * RS2;       // 128*RS1 (red)
    unsigned* W2u = W1u + 128 * RS1;       // 128*RS2 (fus)
    float* bias1 = (float*)(W2u + 128 * RS2);
    float* bias2 = bias1 + 128;
    const int tid = threadIdx.x, lane = tid & 31, w = tid >> 5;
    const int qr = lane >> 2, qc = lane & 3;
    const int mbase = (w >> 2) * 32, nbase = (w & 3) * 32;

    const bool seg1 = (int)blockIdx.x < SPLIT;
    const int localBid = seg1 ? blockIdx.x : blockIdx.x - SPLIT;
    const int nb       = seg1 ? SPLIT : gridDim.x - SPLIT;
    const float* X   = seg1 ? X1 : X2;
    const float* EMB = seg1 ? EMB1 : EMB2;
    const float* WF  = seg1 ? WF1 : WF2;
    const float* BF  = seg1 ? BF1 : BF2;
    __nv_bfloat16* bout = seg1 ? out1 : out2;
    const int N = seg1 ? N1 : N2;

    for (int i = tid; i < 128 * 64; i += 512) {
        float2 wv = ((const float2*)WR)[i];
        W1u[(i >> 6) * RS1 + (i & 63)] = packbf(wv.x, wv.y);
    }
    for (int i = tid; i < 128 * 128; i += 512) {
        float2 wv = ((const float2*)WF)[i];
        W2u[(i >> 7) * RS2 + (i & 127)] = packbf(wv.x, wv.y);
    }
    if (tid < 128) bias1[tid] = BR[tid];
    else if (tid < 256) bias2[tid - 128] = BF[tid - 128];

    const unsigned smA = smaddr(Asu);
    const unsigned aBase2 = smA + (((mbase + (lane & 15)) * RS2 + ((lane >> 4) << 2)) << 2);
    const unsigned aBase1 = aBase2 + 64 * 4;  // t2 slot
    const unsigned b1Base = smaddr(W1u) + (((nbase + ((lane >> 4) << 3) + (lane & 7)) * RS1 + (((lane >> 3) & 1) << 2)) << 2);
    const unsigned b2Base = smaddr(W2u) + (((nbase + ((lane >> 4) << 3) + (lane & 7)) * RS2 + (((lane >> 3) & 1) << 2)) << 2);

    const int ntiles = (N + 127) >> 7;
    for (int tile = localBid; tile < ntiles; tile += nb) {
        __syncthreads();
        // P1: load X (inorm) -> t2 slot ; load EMB -> emb slot
        #pragma unroll 2
        for (int i = 0; i < 8; i++) {
            int rl = w * 8 + i, r = tile * 128 + rl;
            float4 xv = make_float4(0.f,0.f,0.f,0.f), ev = xv;
            if (r < N) {
                xv = *(const float4*)(X   + (size_t)r * 128 + lane * 4);
                ev = *(const float4*)(EMB + (size_t)r * 128 + lane * 4);
            }
            xv = inorm4(xv);
            unsigned* rowp = Asu + rl * RS2;
            uint2 se; se.x = packbf(ev.x, ev.y); se.y = packbf(ev.z, ev.w);
            uint2 sx; sx.x = packbf(xv.x, xv.y); sx.y = packbf(xv.z, xv.w);
            *(uint2*)(rowp + lane * 2)      = se;
            *(uint2*)(rowp + 64 + lane * 2) = sx;
        }
        __syncthreads();
        // P2: GEMM1 (t2 slot @ Wr)
        float d[2][4][4];
        #pragma unroll
        for (int t = 0; t < 2; t++)
            #pragma unroll
            for (int nt = 0; nt < 4; nt++)
                #pragma unroll
                for (int j = 0; j < 4; j++) d[t][nt][j] = 0.f;
        #pragma unroll
        for (int ks = 0; ks < 8; ks++) mma_g<RS2, RS1>(d, aBase1, b1Base, ks);
        __syncthreads();
        // P3: stash C1+bias1 (bf16) back into t2 slot
        #pragma unroll
        for (int t = 0; t < 2; t++)
            #pragma unroll
            for (int nt = 0; nt < 4; nt++) {
                int col = nbase + nt * 8 + qc * 2;
                float b0 = bias1[col], b1 = bias1[col + 1];
                int row0 = mbase + t * 16 + qr;
                int wj = 64 + (col >> 1);
                Asu[row0 * RS2 + wj]       = packbf(d[t][nt][0] + b0, d[t][nt][1] + b1);
                Asu[(row0 + 8) * RS2 + wj] = packbf(d[t][nt][2] + b0, d[t][nt][3] + b1);
            }
        __syncthreads();
        // P4: row-wise inorm of t2 slot (in place)
        #pragma unroll 2
        for (int i = 0; i < 8; i++) {
            int rl = w * 8 + i;
            uint2 u = *(const uint2*)(Asu + rl * RS2 + 64 + lane * 2);
            float4 o = inorm4(cvt4u(u));
            uint2 st; st.x = packbf(o.x, o.y); st.y = packbf(o.z, o.w);
            *(uint2*)(Asu + rl * RS2 + 64 + lane * 2) = st;
        }
        __syncthreads();
        // P5: GEMM2 ([emb|t2] @ Wf, K=256) + sigmoid epilogue
        #pragma unroll
        for (int t = 0; t < 2; t++)
            #pragma unroll
            for (int nt = 0; nt < 4; nt++)
                #pragma unroll
                for (int j = 0; j < 4; j++) d[t][nt][j] = 0.f;
        #pragma unroll
        for (int ks = 0; ks < 16; ks++) mma_g<RS2, RS2>(d, aBase2, b2Base, ks);
        #pragma unroll
        for (int t = 0; t < 2; t++)
            #pragma unroll
            for (int nt = 0; nt < 4; nt++) {
                int col = nbase + nt * 8 + qc * 2;
                float b0 = bias2[col], b1 = bias2[col + 1];
                #pragma unroll
                for (int h = 0; h < 2; h++) {
                    int r = tile * 128 + mbase + t * 16 + qr + h * 8;
                    if (r < N) {
                        float s0 = sigf(d[t][nt][2*h]   + b0);
                        float s1 = sigf(d[t][nt][2*h+1] + b1);
                        *(unsigned*)(bout + (size_t)r * 128 + col) = packbf(s0, s1);
                    }
                }
            }
    }
}

// ==== social layer (+ optional fused combine, all bf16) + optional tail spmm ====
__global__ void __launch_bounds__(256, 3)
k_social(const int* __restrict__ rp, const int* __restrict__ cols, const float* __restrict__ vals,
         const __nv_bfloat16* __restrict__ Xb, const float* __restrict__ W, const float* __restrict__ Bv,
         __nv_bfloat16* __restrict__ bout,
         const __nv_bfloat16* __restrict__ addA, const __nv_bfloat16* __restrict__ addB, int N,
         const int* __restrict__ t_rp, const int* __restrict__ t_cols, const float* __restrict__ t_vals,
         const __nv_bfloat16* __restrict__ t_X, __nv_bfloat16* __restrict__ t_out, int t_N)
{
    extern __shared__ __align__(16) unsigned smu[];
    unsigned* Asu = smu;                 // 64*RS1
    unsigned* Wsu = Asu + 64 * RS1;      // 128*RS1
    float*    biasf = (float*)(Wsu + 128 * RS1);
    const int tid = threadIdx.x, lane = tid & 31, w = tid >> 5;
    const int qr = lane >> 2, qc = lane & 3;
    const int mbase = (w >> 2) * 32, nbase = (w & 3) * 32;

    for (int i = tid; i < 128 * 64; i += 256) {
        float2 wv = ((const float2*)W)[i];
        Wsu[(i >> 6) * RS1 + (i & 63)] = packbf(wv.x, wv.y);
    }
    if (tid < 128) biasf[tid] = Bv[tid];

    const unsigned aBase = smaddr(Asu) + (((mbase + (lane & 15)) * RS1 + ((lane >> 4) << 2)) << 2);
    const unsigned bBase = smaddr(Wsu) + (((nbase + ((lane >> 4) << 3) + (lane & 7)) * RS1 + (((lane >> 3) & 1) << 2)) << 2);

    int ntiles = (N + 63) >> 6;
    for (int tile = blockIdx.x; tile < ntiles; tile += gridDim.x) {
        __syncthreads();
        for (int i = 0; i < 8; i += 2) {
            int rl = w * 8 + i;
            int r0 = tile * 64 + rl, r1 = r0 + 1;
            float4 o0, o1;
            spmm_pair(rp, cols, vals, Xb, r0, r1, N, lane, o0, o1);
            uint2 st0; st0.x = packbf(o0.x, o0.y); st0.y = packbf(o0.z, o0.w);
            uint2 st1; st1.x = packbf(o1.x, o1.y); st1.y = packbf(o1.z, o1.w);
            *(uint2*)(Asu + rl * RS1 + lane * 2)       = st0;
            *(uint2*)(Asu + (rl + 1) * RS1 + lane * 2) = st1;
        }
        __syncthreads();
        float d[2][4][4];
        #pragma unroll
        for (int t = 0; t < 2; t++)
            #pragma unroll
            for (int nt = 0; nt < 4; nt++)
                #pragma unroll
                for (int j = 0; j < 4; j++) d[t][nt][j] = 0.f;
        #pragma unroll
        for (int ks = 0; ks < 8; ks++) mma_g<RS1, RS1>(d, aBase, bBase, ks);
        #pragma unroll
        for (int t = 0; t < 2; t++)
            #pragma unroll
            for (int nt = 0; nt < 4; nt++) {
                int col = nbase + nt * 8 + qc * 2;
                float b0 = biasf[col], b1 = biasf[col + 1];
                #pragma unroll
                for (int h = 0; h < 2; h++) {
                    int r = tile * 64 + mbase + t * 16 + qr + h * 8;
                    if (r < N) {
                        float s0 = sigf(fmaxf(d[t][nt][2*h]   + b0, 0.f));
                        float s1 = sigf(fmaxf(d[t][nt][2*h+1] + b1, 0.f));
                        if (addA) {
                            float2 pa = unpk(*(const unsigned*)(addA + (size_t)r * 128 + col));
                            float2 pb = unpk(*(const unsigned*)(addB + (size_t)r * 128 + col));
                            s0 = sigf((s0 + pa.x + pb.x) * 0.5f);
                            s1 = sigf((s1 + pa.y + pb.y) * 0.5f);
                        }
                        *(unsigned*)(bout + (size_t)r * 128 + col) = packbf(s0, s1);
                    }
                }
            }
    }
    // tail: independent spmm (g_from_items), paired rows, sigmoid epilogue, bf16 out
    if (t_out) {
        for (int base = blockIdx.x * 16 + w * 2; base < t_N; base += gridDim.x * 16) {
            int r0 = base, r1 = base + 1;
            float4 o0, o1;
            spmm_pair(t_rp, t_cols, t_vals, t_X, r0, r1, t_N, lane, o0, o1);
            uint2 st0; st0.x = packbf(sigf(o0.x), sigf(o0.y)); st0.y = packbf(sigf(o0.z), sigf(o0.w));
            *(uint2*)(t_out + (size_t)r0 * 128 + lane * 4) = st0;
            if (r1 < t_N) {
                uint2 st1; st1.x = packbf(sigf(o1.x), sigf(o1.y)); st1.y = packbf(sigf(o1.z), sigf(o1.w));
                *(uint2*)(t_out + (size_t)r1 * 128 + lane * 4) = st1;
            }
        }
    }
}

// ---------------- scoring with fused all_neighbors spmm (bf16 inputs) ----------------
__global__ void __launch_bounds__(256)
k_score(const int* __restrict__ gid, const int* __restrict__ iid,
        const __nv_bfloat16* __restrict__ FG, const __nv_bfloat16* __restrict__ FI,
        const int* __restrict__ rp, const int* __restrict__ cols, const float* __restrict__ vals,
        float* __restrict__ out, int B)
{
    int widx = (blockIdx.x * blockDim.x + threadIdx.x) >> 5;
    int lane = threadIdx.x & 31;
    if (widx >= B) return;
    int g = gid[widx], it = iid[widx];
    float4 ge = cvt4u(((const uint2*)(FG + (size_t)g  * 128))[lane]);
    float4 ie = cvt4u(((const uint2*)(FI + (size_t)it * 128))[lane]);
    float4 ne = spmm_row(rp, cols, vals, FG, g, lane);
    float d1 = ge.x*ie.x + ge.y*ie.y + ge.z*ie.z + ge.w*ie.w;
    float d2 = ne.x*(ge.x+ie.x) + ne.y*(ge.y+ie.y) + ne.z*(ge.z+ie.z) + ne.w*(ge.w+ie.w);
    d1 = wredsum(d1); d2 = wredsum(d2);
    if (lane == 0) { out[widx] = d1; out[B + widx] = d2; }
}

// ---------------- launch ----------------
extern "C" void kernel_launch(void* const* d_in, const int* in_sizes, int n_in,
                              void* d_out, int out_size)
{
    const int*   group_ids   = (const int*)d_in[0];
    const int*   item_ids    = (const int*)d_in[1];
    const int*   gi_rows     = (const int*)d_in[2];
    const int*   gi_cols     = (const int*)d_in[3];
    const float* gi_vals     = (const float*)d_in[4];
    const int*   gg_rows     = (const int*)d_in[5];
    const int*   gg_cols     = (const int*)d_in[6];
    const float* gg_vals     = (const float*)d_in[7];
    const float* g_feat      = (const float*)d_in[8];
    const float* i_feat      = (const float*)d_in[9];
    const float* emb_group   = (const float*)d_in[10];
    const float* emb_item    = (const float*)d_in[11];
    const float* W_w         = (const float*)d_in[12];
    const float* W_b         = (const float*)d_in[13];
    const float* red_w       = (const float*)d_in[14];
    const float* red_b       = (const float*)d_in[15];
    const float* item_fus_w  = (const float*)d_in[16];
    const float* item_fus_b  = (const float*)d_in[17];
    const float* group_fus_w = (const float*)d_in[18];
    const float* group_fus_b = (const float*)d_in[19];
    float* out = (float*)d_out;

    int B   = in_sizes[0];
    int Egi = in_sizes[2];
    int Egg = in_sizes[5];
    int NG  = in_sizes[8] / 128;  if (NG > NG_CAP) NG = NG_CAP;
    int NI  = in_sizes[9] / 128;  if (NI > NI_CAP) NI = NI_CAP;

    __nv_bfloat16 *pb_fi, *pb_fg, *pb_gfi, *pb_first, *pb_fgrp;
    int *p_rp_gi, *p_rp_gg;
    cudaGetSymbolAddress((void**)&pb_fi,    b_fi);
    cudaGetSymbolAddress((void**)&pb_fg,    b_fg);
    cudaGetSymbolAddress((void**)&pb_gfi,   b_gfi);
    cudaGetSymbolAddress((void**)&pb_first, b_first);
    cudaGetSymbolAddress((void**)&pb_fgrp,  b_fgrp);
    cudaGetSymbolAddress((void**)&p_rp_gi,  g_rp_gi);
    cudaGetSymbolAddress((void**)&p_rp_gg,  g_rp_gg);

    size_t smemS  = (size_t)(64 * RS1 + 128 * RS1) * 4 + 512;                 // ~52.7 KB (3/SM)
    size_t smemNF = (size_t)(128 * RS2 + 128 * RS1 + 128 * RS2) * 4 + 1024;   // ~167 KB (1/SM)
    cudaFuncSetAttribute(k_nf,     cudaFuncAttributeMaxDynamicSharedMemorySize, (int)smemNF);
    cudaFuncSetAttribute(k_social, cudaFuncAttributeMaxDynamicSharedMemorySize, (int)smemS);

    const int PGRID3 = 444;   // 3 blocks/SM
    // k_nf split: proportional to tile counts (M128 tiles)
    int tI = (NI + 127) >> 7, tG = (NG + 127) >> 7;
    int SPLIT = (int)((long long)148 * tI / (tI + tG));
    if (SPLIT < 1) SPLIT = 1;
    if (SPLIT > 147) SPLIT = 147;

    k_rowptr<<<1024, 256>>>(gi_rows, Egi, NG, p_rp_gi);
    k_rowptr<<<1024, 256>>>(gg_rows, Egg, NG, p_rp_gg);

    // fused nln+fus: final_item and fus_group directly from raw inputs
    k_nf<<<148, 512, smemNF>>>(i_feat, emb_item,  item_fus_w,  item_fus_b,  pb_fi, NI,
                               g_feat, emb_group, group_fus_w, group_fus_b, pb_fg, NG,
                               red_w, red_b, SPLIT);

    // social layer 1 + tail spmm_gi (g_from_items)
    k_social<<<PGRID3, 256, smemS>>>(p_rp_gg, gg_cols, gg_vals, pb_fg, W_w, W_b,
                                     pb_first, nullptr, nullptr, NG,
                                     p_rp_gi, gi_cols, gi_vals, pb_fi, pb_gfi, NG);

    // social layer 2 fused with final_group combine
    k_social<<<PGRID3, 256, smemS>>>(p_rp_gg, gg_cols, gg_vals, pb_first, W_w, W_b,
                                     pb_fgrp, pb_gfi, pb_first, NG,
                                     nullptr, nullptr, nullptr, nullptr, nullptr, 0);

    // scoring with fused all_neighbors spmm
    k_score<<<(B + 7) / 8, 256>>>(group_ids, item_ids, pb_fgrp, pb_fi,
                                  p_rp_gg, gg_cols, gg_vals, out, B);
}